// round 1
// baseline (speedup 1.0000x reference)
#include <cuda_runtime.h>
#include <cuda_fp16.h>
#include <cstdint>
#include <cstddef>

#define BATCH 4096
#define IN_DIM 10000
#define H1 512
#define H2 256
#define NP 32
#define PD 8
#define NL 100
#define CD 16
#define JO (NL*CD)       // 1600
#define PREDROW (NP*JO)  // 51200

// ---------------- scratch (static device globals; no runtime allocation) ----
__device__ float  g_X1[(size_t)BATCH*H1];
__device__ float  g_X2[(size_t)BATCH*H2];
__device__ float  g_P [(size_t)BATCH*H2];
__device__ __half g_preds[(size_t)BATCH*PREDROW];   // 419 MB
__device__ float  g_V [(size_t)BATCH*JO];

// ---------------- generic tiled fp32 GEMM:  C = act(A[M,K] @ B[K,N] + bias) --
// TN fixed at 4 (one float4 of B per thread). M % BM == 0 and K % BK == 0 are
// required; N is guarded.
template<int BM,int BN,int BK,int TM,bool RELU>
__global__ __launch_bounds__((BM/TM)*(BN/4))
void gemm_kernel(const float* __restrict__ A, const float* __restrict__ Bm,
                 const float* __restrict__ bias, float* __restrict__ C,
                 int M, int N, int K)
{
  constexpr int TN = 4;
  constexpr int THREADS = (BM/TM)*(BN/TN);
  __shared__ __align__(16) float As[BK][BM];   // stored k-major (transposed)
  __shared__ __align__(16) float Bs[BK][BN];
  const int t  = threadIdx.x;
  const int bm = blockIdx.y * BM;
  const int bn = blockIdx.x * BN;
  const int tx = t % (BN/TN);
  const int ty = t / (BN/TN);
  const int a_row = t / (BK/4);
  const int a_k   = (t % (BK/4)) * 4;
  const int b_row = t / (BN/4);
  const int b_c   = (t % (BN/4)) * 4;

  float acc[TM][TN];
#pragma unroll
  for (int i=0;i<TM;i++)
#pragma unroll
    for (int j=0;j<TN;j++) acc[i][j]=0.f;

  for (int k0=0;k0<K;k0+=BK){
#pragma unroll
    for (int r=0;r<BM;r+=THREADS/(BK/4)){
      float4 v = *(const float4*)(A + (size_t)(bm + a_row + r)*K + (k0 + a_k));
      As[a_k+0][a_row+r]=v.x;
      As[a_k+1][a_row+r]=v.y;
      As[a_k+2][a_row+r]=v.z;
      As[a_k+3][a_row+r]=v.w;
    }
    {
      int col = bn + b_c;
      const float* bp = Bm + (size_t)(k0 + b_row)*N;
      float4 v;
      if (col + 3 < N) v = *(const float4*)(bp + col);
      else {
        v.x = (col+0<N)? bp[col+0] : 0.f;
        v.y = (col+1<N)? bp[col+1] : 0.f;
        v.z = (col+2<N)? bp[col+2] : 0.f;
        v.w = (col+3<N)? bp[col+3] : 0.f;
      }
      *(float4*)&Bs[b_row][b_c] = v;
    }
    __syncthreads();
#pragma unroll
    for (int kk=0;kk<BK;kk++){
      float a[TM];
#pragma unroll
      for (int i=0;i<TM;i+=4){
        float4 v=*(const float4*)&As[kk][ty*TM+i];
        a[i]=v.x; a[i+1]=v.y; a[i+2]=v.z; a[i+3]=v.w;
      }
      float4 bv=*(const float4*)&Bs[kk][tx*TN];
      float bb4[4]={bv.x,bv.y,bv.z,bv.w};
#pragma unroll
      for (int i=0;i<TM;i++)
#pragma unroll
        for (int j=0;j<TN;j++) acc[i][j] += a[i]*bb4[j];
    }
    __syncthreads();
  }
#pragma unroll
  for (int i=0;i<TM;i++){
    int row = bm + ty*TM + i;
#pragma unroll
    for (int j=0;j<TN;j++){
      int col = bn + tx*TN + j;
      if (col < N){
        float v = acc[i][j] + bias[col];
        if (RELU) v = fmaxf(v, 0.f);
        C[(size_t)row*N + col] = v;
      }
    }
  }
}

// ---------------- primary capsules + per-capsule LayerNorm --------------------
// p[b,n,o] = LN_o( sum_i x2[b,i]*Wp[n,i,o] + bp[n,o] ) * g + beta
// One CTA handles 16 batch rows; thread t owns (n = t>>3, o = t&7).
__global__ __launch_bounds__(256)
void primary_kernel(const float* __restrict__ X2, const float* __restrict__ Wp,
                    const float* __restrict__ bp, const float* __restrict__ lng,
                    const float* __restrict__ lnb, float* __restrict__ P)
{
  __shared__ __align__(16) float xs[16][H2];
  const int t  = threadIdx.x;
  const int b0 = blockIdx.x * 16;
  for (int idx=t; idx<16*(H2/4); idx+=256){
    int bb = idx/(H2/4);
    int c4 = (idx%(H2/4))*4;
    *(float4*)&xs[bb][c4] = *(const float4*)(X2 + (size_t)(b0+bb)*H2 + c4);
  }
  __syncthreads();
  const int n = t>>3, o = t&7;
  float bias = bp[t];
  float acc[16];
#pragma unroll
  for (int bb=0;bb<16;bb++) acc[bb]=bias;
  const float* wp = Wp + (size_t)n*(H2*PD) + o;
  for (int i0=0;i0<H2;i0+=4){
    float w0 = __ldg(wp + (size_t)(i0+0)*PD);
    float w1 = __ldg(wp + (size_t)(i0+1)*PD);
    float w2 = __ldg(wp + (size_t)(i0+2)*PD);
    float w3 = __ldg(wp + (size_t)(i0+3)*PD);
#pragma unroll
    for (int bb=0;bb<16;bb++){
      float4 x = *(const float4*)&xs[bb][i0];
      acc[bb] += x.x*w0 + x.y*w1 + x.z*w2 + x.w*w3;
    }
  }
  float g = lng[t], be = lnb[t];
#pragma unroll
  for (int bb=0;bb<16;bb++){
    float x = acc[bb];
    float s = x;
    s += __shfl_xor_sync(0xffffffffu, s, 1);
    s += __shfl_xor_sync(0xffffffffu, s, 2);
    s += __shfl_xor_sync(0xffffffffu, s, 4);
    float mu = s * 0.125f;
    float d  = x - mu;
    float q  = d*d;
    q += __shfl_xor_sync(0xffffffffu, q, 1);
    q += __shfl_xor_sync(0xffffffffu, q, 2);
    q += __shfl_xor_sync(0xffffffffu, q, 4);
    float var = q * 0.125f;
    P[(size_t)(b0+bb)*H2 + t] = d * rsqrtf(var + 1e-5f) * g + be;
  }
}

// ---------------- preds GEMM: preds[b,n,jo] = p[b,n,:] . Wr[n,jo,:] -> fp16 ---
// One CTA = (64 batch rows, one n). Wr slice kept transposed in SMEM, p tile
// in registers (8 rows per 32-lane group), so inner loop is 8 LDS : 128 FMA.
__global__ __launch_bounds__(256)
void preds_kernel(const float* __restrict__ P, const float* __restrict__ Wr,
                  __half* __restrict__ preds)
{
  extern __shared__ __align__(16) float sm[];
  float* wrs = sm;            // [8][JO]  (i-major, conflict-free on jo)
  float* ps  = sm + 8*JO;     // [64][8]
  const int n  = blockIdx.y;
  const int b0 = blockIdx.x * 64;
  const int t  = threadIdx.x;
  const float* wsrc = Wr + (size_t)n*(JO*PD);
  for (int idx=t; idx<JO*PD; idx+=256){
    int jo = idx>>3, i = idx&7;
    wrs[i*JO + jo] = wsrc[idx];
  }
  for (int idx=t; idx<64*8; idx+=256){
    int bb = idx>>3, i = idx&7;
    ps[idx] = P[(size_t)(b0+bb)*H2 + n*8 + i];
  }
  __syncthreads();
  const int ty   = t>>5;   // 8 groups, each owns 8 batch rows
  const int lane = t&31;
  float pr[8][8];
#pragma unroll
  for (int q=0;q<8;q++)
#pragma unroll
    for (int i=0;i<8;i++) pr[q][i] = ps[(ty*8+q)*8 + i];
  __half* out = preds + (size_t)b0*PREDROW + (size_t)n*JO;
  for (int jo=lane*2; jo<JO; jo+=64){
    float w0[8], w1[8];
#pragma unroll
    for (int i=0;i<8;i++){
      float2 w = *(const float2*)&wrs[i*JO + jo];
      w0[i]=w.x; w1[i]=w.y;
    }
#pragma unroll
    for (int q=0;q<8;q++){
      float s0=0.f, s1=0.f;
#pragma unroll
      for (int i=0;i<8;i++){ s0 += pr[q][i]*w0[i]; s1 += pr[q][i]*w1[i]; }
      *(__half2*)(out + (size_t)(ty*8+q)*PREDROW + jo) = __floats2half2_rn(s0, s1);
    }
  }
}

// ---------------- dynamic routing (3 iters) fully in SMEM, one CTA per b -----
#define SMEM_ROUTING (PREDROW*2 + (NP*NL + NP*NL + JO + 2*NP)*4)   // 134656 B

__global__ void routing_kernel(const __half* __restrict__ preds,
                               float* __restrict__ V)
{
  extern __shared__ __align__(16) unsigned char smraw[];
  __half* ps = (__half*)smraw;                      // [NP][JO] fp16
  float* bl  = (float*)(smraw + (size_t)PREDROW*2); // [NP][NL] logits
  float* cs  = bl + NP*NL;                          // [NP][NL] coupling
  float* vs  = cs + NP*NL;                          // [JO]     s / v
  float* nmx = vs + JO;                             // [NP]
  float* nnv = nmx + NP;                            // [NP]
  const int b = blockIdx.x;
  const int t = threadIdx.x;

  {
    const uint4* src = (const uint4*)(preds + (size_t)b*PREDROW);
    uint4* dst = (uint4*)ps;
    for (int i=t; i<PREDROW/8; i+=256) dst[i] = src[i];
  }
  for (int i=t; i<NP*NL; i+=256) bl[i]=0.f;
  __syncthreads();

  const __half2* p2 = (const __half2*)ps;

  // iteration 0: softmax(0) is exactly uniform -> s = mean_n(preds)/ (NL weight)
  for (int jo2=t; jo2<JO/2; jo2+=256){
    float ax=0.f, ay=0.f;
#pragma unroll
    for (int n=0;n<NP;n++){
      float2 f = __half22float2(p2[n*(JO/2)+jo2]);
      ax += f.x; ay += f.y;
    }
    vs[jo2*2]   = ax*(1.0f/NL);
    vs[jo2*2+1] = ay*(1.0f/NL);
  }
  __syncthreads();

  for (int iter=0; iter<3; iter++){
    if (iter > 0){
      // softmax over labels, per capsule n
      if (t<NP){
        float m=-1e30f;
        for (int j=0;j<NL;j++) m = fmaxf(m, bl[t*NL+j]);
        float ssum=0.f;
        for (int j=0;j<NL;j++) ssum += __expf(bl[t*NL+j]-m);
        nmx[t]=m; nnv[t]=1.f/ssum;
      }
      __syncthreads();
      for (int nj=t; nj<NP*NL; nj+=256){
        int n = nj/NL;
        cs[nj] = __expf(bl[nj]-nmx[n])*nnv[n];
      }
      __syncthreads();
      // s[j,o] = sum_n c[n,j] * preds[n,j,o]
      for (int jo2=t; jo2<JO/2; jo2+=256){
        int j = jo2>>3;
        float ax=0.f, ay=0.f;
#pragma unroll
        for (int n=0;n<NP;n++){
          float c = cs[n*NL+j];
          float2 f = __half22float2(p2[n*(JO/2)+jo2]);
          ax += c*f.x; ay += c*f.y;
        }
        vs[jo2*2]=ax; vs[jo2*2+1]=ay;
      }
      __syncthreads();
    }
    // squash per label j (in place)
    if (t<NL){
      float sq=0.f;
#pragma unroll
      for (int o=0;o<CD;o++){ float x=vs[t*CD+o]; sq+=x*x; }
      float scale = sq/(1.f+sq)*rsqrtf(sq+1e-8f);
#pragma unroll
      for (int o=0;o<CD;o++) vs[t*CD+o]*=scale;
    }
    __syncthreads();
    if (iter<2){
      // agreement -> logits update
      for (int nj=t; nj<NP*NL; nj+=256){
        int n=nj/NL, j=nj%NL;
        float a=0.f;
#pragma unroll
        for (int o2=0;o2<CD/2;o2++){
          float2 f = __half22float2(p2[n*(JO/2) + j*(CD/2) + o2]);
          a += f.x*vs[j*CD+o2*2] + f.y*vs[j*CD+o2*2+1];
        }
        bl[nj] += a;
      }
      __syncthreads();
    }
  }
  for (int jo=t; jo<JO; jo+=256) V[(size_t)b*JO + jo] = vs[jo];
}

// ---------------- launch ------------------------------------------------------
extern "C" void kernel_launch(void* const* d_in, const int* in_sizes, int n_in,
                              void* d_out, int out_size)
{
  (void)in_sizes; (void)n_in; (void)out_size;
  const float* features = (const float*)d_in[0];
  const float* W1  = (const float*)d_in[1];
  const float* b1  = (const float*)d_in[2];
  const float* W2  = (const float*)d_in[3];
  const float* b2  = (const float*)d_in[4];
  const float* Wp  = (const float*)d_in[5];
  const float* bp  = (const float*)d_in[6];
  const float* lng = (const float*)d_in[7];
  const float* lnb = (const float*)d_in[8];
  const float* Wr  = (const float*)d_in[9];
  const float* Wc  = (const float*)d_in[10];
  const float* bc  = (const float*)d_in[11];
  float* out = (float*)d_out;

  float *X1,*X2,*P,*V; __half* PR;
  cudaGetSymbolAddress((void**)&X1, g_X1);
  cudaGetSymbolAddress((void**)&X2, g_X2);
  cudaGetSymbolAddress((void**)&P,  g_P);
  cudaGetSymbolAddress((void**)&PR, g_preds);
  cudaGetSymbolAddress((void**)&V,  g_V);

  // 1) X1 = relu(features @ W1 + b1)          [4096 x 512],  K = 10000
  gemm_kernel<128,64,16,8,true><<<dim3(H1/64, BATCH/128), 256>>>(
      features, W1, b1, X1, BATCH, H1, IN_DIM);
  // 2) X2 = relu(X1 @ W2 + b2)                [4096 x 256]
  gemm_kernel<128,64,16,8,true><<<dim3(H2/64, BATCH/128), 256>>>(
      X1, W2, b2, X2, BATCH, H2, H1);
  // 3) primary capsules + LayerNorm           [4096 x 32 x 8]
  primary_kernel<<<BATCH/16, 256>>>(X2, Wp, bp, lng, lnb, P);
  // 4) preds (fp16)                           [4096 x 32 x 1600]
  cudaFuncSetAttribute(preds_kernel, cudaFuncAttributeMaxDynamicSharedMemorySize,
                       (8*JO + 64*8)*4);
  preds_kernel<<<dim3(BATCH/64, NP), 256, (8*JO + 64*8)*4>>>(P, Wr, PR);
  // 5) dynamic routing -> V                   [4096 x 1600]
  cudaFuncSetAttribute(routing_kernel, cudaFuncAttributeMaxDynamicSharedMemorySize,
                       SMEM_ROUTING);
  routing_kernel<<<BATCH, 256, SMEM_ROUTING>>>(PR, V);
  // 6) logits = V @ Wc + bc                   [4096 x 100]
  gemm_kernel<64,64,16,4,false><<<dim3((NL+63)/64, BATCH/64), 256>>>(
      V, Wc, bc, out, BATCH, NL, JO);
}

// round 3
// speedup vs baseline: 1.5954x; 1.5954x over previous
#include <cuda_runtime.h>
#include <cuda_fp16.h>
#include <cuda_bf16.h>
#include <cstdint>
#include <cstddef>

#define BATCH 4096
#define IN_DIM 10000
#define H1 512
#define H2 256
#define NP 32
#define PD 8
#define NL 100
#define CD 16
#define JO (NL*CD)       // 1600
#define PREDROW (NP*JO)  // 51200
#define KPAD1 10240

// ---------------- helpers ----------------------------------------------------
__device__ __forceinline__ uint32_t smem_u32(const void* p) {
  uint32_t a;
  asm("{ .reg .u64 t; cvta.to.shared.u64 t, %1; cvt.u32.u64 %0, t; }" : "=r"(a) : "l"(p));
  return a;
}
__device__ __forceinline__ void cp_async16(uint32_t smem, const void* g) {
  asm volatile("cp.async.cg.shared.global [%0], [%1], 16;" :: "r"(smem), "l"(g));
}
#define CP_COMMIT() asm volatile("cp.async.commit_group;" ::: "memory")
#define CP_WAIT(N)  asm volatile("cp.async.wait_group %0;" :: "n"(N) : "memory")

__device__ __forceinline__ void ldm_x4(uint32_t* r, uint32_t addr) {
  asm volatile("ldmatrix.sync.aligned.m8n8.x4.shared.b16 {%0,%1,%2,%3}, [%4];"
               : "=r"(r[0]), "=r"(r[1]), "=r"(r[2]), "=r"(r[3]) : "r"(addr));
}
__device__ __forceinline__ void mma_bf16(float* d, const uint32_t* a, const uint32_t* b) {
  asm volatile("mma.sync.aligned.m16n8k16.row.col.f32.bf16.bf16.f32 "
               "{%0,%1,%2,%3}, {%4,%5,%6,%7}, {%8,%9}, {%0,%1,%2,%3};"
               : "+f"(d[0]), "+f"(d[1]), "+f"(d[2]), "+f"(d[3])
               : "r"(a[0]), "r"(a[1]), "r"(a[2]), "r"(a[3]), "r"(b[0]), "r"(b[1]));
}
__device__ __forceinline__ uint32_t pack_bf16(float a, float b) {
  __nv_bfloat16 ha = __float2bfloat16(a), hb = __float2bfloat16(b);
  return (uint32_t)__bfloat16_as_ushort(ha) | ((uint32_t)__bfloat16_as_ushort(hb) << 16);
}

// ---------------- scratch ----------------------------------------------------
__device__ __nv_bfloat16 g_Ahi[(size_t)BATCH*KPAD1];
__device__ __nv_bfloat16 g_Alo[(size_t)BATCH*KPAD1];
__device__ __nv_bfloat16 g_B1hi[(size_t)H1*KPAD1];
__device__ __nv_bfloat16 g_B1lo[(size_t)H1*KPAD1];
__device__ __nv_bfloat16 g_B2hi[(size_t)H2*H1];
__device__ __nv_bfloat16 g_B2lo[(size_t)H2*H1];
__device__ __nv_bfloat16 g_X1hi[(size_t)BATCH*H1];
__device__ __nv_bfloat16 g_X1lo[(size_t)BATCH*H1];
__device__ float  g_X2[(size_t)BATCH*H2];
__device__ float  g_P [(size_t)BATCH*H2];
__device__ __half g_preds[(size_t)BATCH*PREDROW];
__device__ float  g_V [(size_t)BATCH*JO];

// ---------------- conversion: features -> A_hi/A_lo (bf16 split, K padded) ---
__global__ __launch_bounds__(256)
void convA_kernel(const float* __restrict__ F, __nv_bfloat16* __restrict__ Ahi,
                  __nv_bfloat16* __restrict__ Alo)
{
  size_t total = (size_t)BATCH*(KPAD1/4);
  for (size_t i = (size_t)blockIdx.x*blockDim.x + threadIdx.x; i < total;
       i += (size_t)gridDim.x*blockDim.x) {
    size_t row = i / (KPAD1/4);
    int k4 = (int)(i % (KPAD1/4)) * 4;
    float4 v = make_float4(0.f,0.f,0.f,0.f);
    if (k4 < IN_DIM) v = *(const float4*)(F + row*IN_DIM + k4);
    float h0 = __bfloat162float(__float2bfloat16(v.x));
    float h1 = __bfloat162float(__float2bfloat16(v.y));
    float h2 = __bfloat162float(__float2bfloat16(v.z));
    float h3 = __bfloat162float(__float2bfloat16(v.w));
    size_t o = row*KPAD1 + k4;
    *(uint32_t*)(Ahi+o)   = pack_bf16(h0, h1);
    *(uint32_t*)(Ahi+o+2) = pack_bf16(h2, h3);
    *(uint32_t*)(Alo+o)   = pack_bf16(v.x-h0, v.y-h1);
    *(uint32_t*)(Alo+o+2) = pack_bf16(v.z-h2, v.w-h3);
  }
}

// ---------------- conversion: W[K,N] -> B_hi/B_lo[N,KP] (transpose + split) --
__global__ __launch_bounds__(256)
void convW_kernel(const float* __restrict__ W, __nv_bfloat16* __restrict__ Bhi,
                  __nv_bfloat16* __restrict__ Blo, int K, int N, int KP)
{
  __shared__ float tile[32][33];
  int kb = blockIdx.x*32, nb = blockIdx.y*32;
  int tx = threadIdx.x, ty = threadIdx.y;   // block (32,8)
#pragma unroll
  for (int i=0;i<32;i+=8){
    int k = kb+ty+i;
    tile[ty+i][tx] = (k < K) ? W[(size_t)k*N + nb+tx] : 0.f;
  }
  __syncthreads();
#pragma unroll
  for (int i=0;i<32;i+=8){
    int n = nb+ty+i, k = kb+tx;
    float v = tile[tx][ty+i];
    float h = __bfloat162float(__float2bfloat16(v));
    Bhi[(size_t)n*KP + k] = __float2bfloat16(h);
    Blo[(size_t)n*KP + k] = __float2bfloat16(v - h);
  }
}

// ---------------- split-bf16 mma.sync GEMM -----------------------------------
// C[M,N] = relu(A[M,K] @ B[K,N] + bias) with A,B pre-split into bf16 hi/lo.
// 3 mma passes: ah*bh + ah*bl + al*bh. BM=128, BN=128, BK=32, 3 stages.
// EPI=0: write fp32. EPI=1: write bf16 hi/lo pair (for feeding next GEMM).
#define G_BM 128
#define G_BN 128
#define G_BK 32
#define G_STAGES 3
#define G_TILEB 8192            // one [128][32] bf16 tile, 64B rows
#define G_STAGEB (4*G_TILEB)    // Ahi, Alo, Bhi, Blo
#define G_SMEM (G_STAGES*G_STAGEB)  // 98304

template<int EPI>
__global__ __launch_bounds__(256, 1)
void mma_gemm_kernel(const __nv_bfloat16* __restrict__ Ahi,
                     const __nv_bfloat16* __restrict__ Alo,
                     const __nv_bfloat16* __restrict__ Bhi,
                     const __nv_bfloat16* __restrict__ Blo,
                     const float* __restrict__ bias,
                     float* __restrict__ outF,
                     __nv_bfloat16* __restrict__ outHi,
                     __nv_bfloat16* __restrict__ outLo,
                     int Kdim, int KT, int Ntot)
{
  extern __shared__ __align__(128) unsigned char smraw[];
  const uint32_t sb = smem_u32(smraw);
  const int t = threadIdx.x;
  const int m0 = blockIdx.y * G_BM;
  const int n0 = blockIdx.x * G_BN;

  // ---- stage loader: 2048 16B chunks; per tile 512 chunks = 2 halves of 256
  auto load_stage = [&](int s, int kt){
    const uint32_t stb = sb + s*G_STAGEB;
    const int k0 = kt*G_BK;
    const __nv_bfloat16* gb[4] = {Ahi, Alo, Bhi, Blo};
#pragma unroll
    for (int tile = 0; tile < 4; tile++){
      const int row0 = (tile < 2) ? m0 : n0;
      const __nv_bfloat16* g = gb[tile];
#pragma unroll
      for (int half = 0; half < 2; half++){
        int rem = half*256 + t;
        int r = rem >> 2, c16 = rem & 3;
        uint32_t dst = stb + tile*G_TILEB + r*64 + (((c16 ^ ((r>>1)&3))) << 4);
        cp_async16(dst, g + (size_t)(row0 + r)*Kdim + k0 + c16*8);
      }
    }
  };

  const int wid = t >> 5, lane = t & 31;
  const int wm = wid & 1, wn = wid >> 1;     // warp tile: 64m x 32n
  int ra[4], rb[2];
#pragma unroll
  for (int i=0;i<4;i++) ra[i] = wm*64 + i*16 + (lane&7) + ((lane>>3)&1)*8;
#pragma unroll
  for (int h=0;h<2;h++)  rb[h] = wn*32 + h*16 + (lane&7) + ((lane>>4)&1)*8;
  const int ca = (lane>>4);        // extra k16-chunk for A lanes 16-31
  const int cb = ((lane>>3)&1);    // for B lanes 8-15 / 24-31

  float acc[4][4][4];
#pragma unroll
  for (int i=0;i<4;i++)
#pragma unroll
    for (int j=0;j<4;j++)
#pragma unroll
      for (int q=0;q<4;q++) acc[i][j][q]=0.f;

  load_stage(0, 0); CP_COMMIT();
  load_stage(1, 1); CP_COMMIT();

  for (int kt = 0; kt < KT; kt++){
    CP_WAIT(1);
    __syncthreads();
    // prefetch into the slot just freed (kt-1's slot == (kt+2)%3)
    if (kt + G_STAGES - 1 < KT) load_stage((kt + G_STAGES - 1) % G_STAGES, kt + G_STAGES - 1);
    CP_COMMIT();

    const uint32_t stb = sb + (kt % G_STAGES)*G_STAGEB;
#pragma unroll
    for (int kk = 0; kk < 2; kk++){
      uint32_t AH[4][4], AL[4][4], BH[4][2], BL[4][2];
#pragma unroll
      for (int i=0;i<4;i++){
        uint32_t off = ra[i]*64 + ((((kk*2 + ca) ^ ((ra[i]>>1)&3))) << 4);
        ldm_x4(AH[i], stb + 0*G_TILEB + off);
        ldm_x4(AL[i], stb + 1*G_TILEB + off);
      }
#pragma unroll
      for (int h=0;h<2;h++){
        uint32_t off = rb[h]*64 + ((((kk*2 + cb) ^ ((rb[h]>>1)&3))) << 4);
        uint32_t r4[4];
        ldm_x4(r4, stb + 2*G_TILEB + off);
        BH[h*2][0]=r4[0]; BH[h*2][1]=r4[1]; BH[h*2+1][0]=r4[2]; BH[h*2+1][1]=r4[3];
        ldm_x4(r4, stb + 3*G_TILEB + off);
        BL[h*2][0]=r4[0]; BL[h*2][1]=r4[1]; BL[h*2+1][0]=r4[2]; BL[h*2+1][1]=r4[3];
      }
#pragma unroll
      for (int i=0;i<4;i++)
#pragma unroll
        for (int j=0;j<4;j++){
          mma_bf16(acc[i][j], AH[i], BH[j]);
          mma_bf16(acc[i][j], AH[i], BL[j]);
          mma_bf16(acc[i][j], AL[i], BH[j]);
        }
    }
    __syncthreads();
  }

  // ---- epilogue: bias + relu
  const int g = lane >> 2, tq = lane & 3;
#pragma unroll
  for (int i=0;i<4;i++){
#pragma unroll
    for (int j=0;j<4;j++){
      int row = m0 + wm*64 + i*16 + g;
      int col = n0 + wn*32 + j*8 + tq*2;
      float b0 = bias[col], b1 = bias[col+1];
      float v0 = fmaxf(acc[i][j][0]+b0, 0.f);
      float v1 = fmaxf(acc[i][j][1]+b1, 0.f);
      float v2 = fmaxf(acc[i][j][2]+b0, 0.f);
      float v3 = fmaxf(acc[i][j][3]+b1, 0.f);
      if (EPI == 0){
        *(float2*)(outF + (size_t)row*Ntot + col)     = make_float2(v0, v1);
        *(float2*)(outF + (size_t)(row+8)*Ntot + col) = make_float2(v2, v3);
      } else {
        float h0 = __bfloat162float(__float2bfloat16(v0));
        float h1 = __bfloat162float(__float2bfloat16(v1));
        float h2 = __bfloat162float(__float2bfloat16(v2));
        float h3 = __bfloat162float(__float2bfloat16(v3));
        *(uint32_t*)(outHi + (size_t)row*Ntot + col)     = pack_bf16(h0, h1);
        *(uint32_t*)(outHi + (size_t)(row+8)*Ntot + col) = pack_bf16(h2, h3);
        *(uint32_t*)(outLo + (size_t)row*Ntot + col)     = pack_bf16(v0-h0, v1-h1);
        *(uint32_t*)(outLo + (size_t)(row+8)*Ntot + col) = pack_bf16(v2-h2, v3-h3);
      }
    }
  }
}

// ---------------- generic tiled fp32 GEMM (logits stage only) ----------------
template<int BM,int BN,int BK,int TM,bool RELU>
__global__ __launch_bounds__((BM/TM)*(BN/4))
void gemm_kernel(const float* __restrict__ A, const float* __restrict__ Bm,
                 const float* __restrict__ bias, float* __restrict__ C,
                 int M, int N, int K)
{
  constexpr int TN = 4;
  constexpr int THREADS = (BM/TM)*(BN/TN);
  __shared__ __align__(16) float As[BK][BM];
  __shared__ __align__(16) float Bs[BK][BN];
  const int t  = threadIdx.x;
  const int bm = blockIdx.y * BM;
  const int bn = blockIdx.x * BN;
  const int tx = t % (BN/TN);
  const int ty = t / (BN/TN);
  const int a_row = t / (BK/4);
  const int a_k   = (t % (BK/4)) * 4;
  const int b_row = t / (BN/4);
  const int b_c   = (t % (BN/4)) * 4;

  float acc[TM][TN];
#pragma unroll
  for (int i=0;i<TM;i++)
#pragma unroll
    for (int j=0;j<TN;j++) acc[i][j]=0.f;

  for (int k0=0;k0<K;k0+=BK){
#pragma unroll
    for (int r=0;r<BM;r+=THREADS/(BK/4)){
      float4 v = *(const float4*)(A + (size_t)(bm + a_row + r)*K + (k0 + a_k));
      As[a_k+0][a_row+r]=v.x; As[a_k+1][a_row+r]=v.y;
      As[a_k+2][a_row+r]=v.z; As[a_k+3][a_row+r]=v.w;
    }
    {
      int col = bn + b_c;
      const float* bp = Bm + (size_t)(k0 + b_row)*N;
      float4 v;
      if (col + 3 < N) v = *(const float4*)(bp + col);
      else {
        v.x = (col+0<N)? bp[col+0] : 0.f;
        v.y = (col+1<N)? bp[col+1] : 0.f;
        v.z = (col+2<N)? bp[col+2] : 0.f;
        v.w = (col+3<N)? bp[col+3] : 0.f;
      }
      *(float4*)&Bs[b_row][b_c] = v;
    }
    __syncthreads();
#pragma unroll
    for (int kk=0;kk<BK;kk++){
      float a[TM];
#pragma unroll
      for (int i=0;i<TM;i+=4){
        float4 v=*(const float4*)&As[kk][ty*TM+i];
        a[i]=v.x; a[i+1]=v.y; a[i+2]=v.z; a[i+3]=v.w;
      }
      float4 bv=*(const float4*)&Bs[kk][tx*TN];
      float bb4[4]={bv.x,bv.y,bv.z,bv.w};
#pragma unroll
      for (int i=0;i<TM;i++)
#pragma unroll
        for (int j=0;j<TN;j++) acc[i][j] += a[i]*bb4[j];
    }
    __syncthreads();
  }
#pragma unroll
  for (int i=0;i<TM;i++){
    int row = bm + ty*TM + i;
#pragma unroll
    for (int j=0;j<TN;j++){
      int col = bn + tx*TN + j;
      if (col < N){
        float v = acc[i][j] + bias[col];
        if (RELU) v = fmaxf(v, 0.f);
        C[(size_t)row*N + col] = v;
      }
    }
  }
}

// ---------------- primary capsules + per-capsule LayerNorm -------------------
__global__ __launch_bounds__(256)
void primary_kernel(const float* __restrict__ X2, const float* __restrict__ Wp,
                    const float* __restrict__ bp, const float* __restrict__ lng,
                    const float* __restrict__ lnb, float* __restrict__ P)
{
  __shared__ __align__(16) float xs[16][H2];
  const int t  = threadIdx.x;
  const int b0 = blockIdx.x * 16;
  for (int idx=t; idx<16*(H2/4); idx+=256){
    int bb = idx/(H2/4);
    int c4 = (idx%(H2/4))*4;
    *(float4*)&xs[bb][c4] = *(const float4*)(X2 + (size_t)(b0+bb)*H2 + c4);
  }
  __syncthreads();
  const int n = t>>3, o = t&7;
  float bias = bp[t];
  float acc[16];
#pragma unroll
  for (int bb=0;bb<16;bb++) acc[bb]=bias;
  const float* wp = Wp + (size_t)n*(H2*PD) + o;
  for (int i0=0;i0<H2;i0+=4){
    float w0 = __ldg(wp + (size_t)(i0+0)*PD);
    float w1 = __ldg(wp + (size_t)(i0+1)*PD);
    float w2 = __ldg(wp + (size_t)(i0+2)*PD);
    float w3 = __ldg(wp + (size_t)(i0+3)*PD);
#pragma unroll
    for (int bb=0;bb<16;bb++){
      float4 x = *(const float4*)&xs[bb][i0];
      acc[bb] += x.x*w0 + x.y*w1 + x.z*w2 + x.w*w3;
    }
  }
  float g = lng[t], be = lnb[t];
#pragma unroll
  for (int bb=0;bb<16;bb++){
    float x = acc[bb];
    float s = x;
    s += __shfl_xor_sync(0xffffffffu, s, 1);
    s += __shfl_xor_sync(0xffffffffu, s, 2);
    s += __shfl_xor_sync(0xffffffffu, s, 4);
    float mu = s * 0.125f;
    float d  = x - mu;
    float q  = d*d;
    q += __shfl_xor_sync(0xffffffffu, q, 1);
    q += __shfl_xor_sync(0xffffffffu, q, 2);
    q += __shfl_xor_sync(0xffffffffu, q, 4);
    float var = q * 0.125f;
    P[(size_t)(b0+bb)*H2 + t] = d * rsqrtf(var + 1e-5f) * g + be;
  }
}

// ---------------- preds GEMM -> fp16 -----------------------------------------
__global__ __launch_bounds__(256)
void preds_kernel(const float* __restrict__ P, const float* __restrict__ Wr,
                  __half* __restrict__ preds)
{
  extern __shared__ __align__(16) float sm[];
  float* wrs = sm;            // [8][JO]
  float* ps  = sm + 8*JO;     // [64][8]
  const int n  = blockIdx.y;
  const int b0 = blockIdx.x * 64;
  const int t  = threadIdx.x;
  const float* wsrc = Wr + (size_t)n*(JO*PD);
  for (int idx=t; idx<JO*PD; idx+=256){
    int jo = idx>>3, i = idx&7;
    wrs[i*JO + jo] = wsrc[idx];
  }
  for (int idx=t; idx<64*8; idx+=256){
    int bb = idx>>3, i = idx&7;
    ps[idx] = P[(size_t)(b0+bb)*H2 + n*8 + i];
  }
  __syncthreads();
  const int ty   = t>>5;
  const int lane = t&31;
  float pr[8][8];
#pragma unroll
  for (int q=0;q<8;q++)
#pragma unroll
    for (int i=0;i<8;i++) pr[q][i] = ps[(ty*8+q)*8 + i];
  __half* out = preds + (size_t)b0*PREDROW + (size_t)n*JO;
  for (int jo=lane*2; jo<JO; jo+=64){
    float w0[8], w1[8];
#pragma unroll
    for (int i=0;i<8;i++){
      float2 w = *(const float2*)&wrs[i*JO + jo];
      w0[i]=w.x; w1[i]=w.y;
    }
#pragma unroll
    for (int q=0;q<8;q++){
      float s0=0.f, s1=0.f;
#pragma unroll
      for (int i=0;i<8;i++){ s0 += pr[q][i]*w0[i]; s1 += pr[q][i]*w1[i]; }
      *(__half2*)(out + (size_t)(ty*8+q)*PREDROW + jo) = __floats2half2_rn(s0, s1);
    }
  }
}

// ---------------- dynamic routing (3 iters) in SMEM --------------------------
#define SMEM_ROUTING (PREDROW*2 + (NP*NL + NP*NL + JO + 2*NP)*4)

__global__ void routing_kernel(const __half* __restrict__ preds,
                               float* __restrict__ V)
{
  extern __shared__ __align__(16) unsigned char smraw[];
  __half* ps = (__half*)smraw;
  float* bl  = (float*)(smraw + (size_t)PREDROW*2);
  float* cs  = bl + NP*NL;
  float* vs  = cs + NP*NL;
  float* nmx = vs + JO;
  float* nnv = nmx + NP;
  const int b = blockIdx.x;
  const int t = threadIdx.x;

  {
    const uint4* src = (const uint4*)(preds + (size_t)b*PREDROW);
    uint4* dst = (uint4*)ps;
    for (int i=t; i<PREDROW/8; i+=256) dst[i] = src[i];
  }
  for (int i=t; i<NP*NL; i+=256) bl[i]=0.f;
  __syncthreads();

  const __half2* p2 = (const __half2*)ps;

  for (int jo2=t; jo2<JO/2; jo2+=256){
    float ax=0.f, ay=0.f;
#pragma unroll
    for (int n=0;n<NP;n++){
      float2 f = __half22float2(p2[n*(JO/2)+jo2]);
      ax += f.x; ay += f.y;
    }
    vs[jo2*2]   = ax*(1.0f/NL);
    vs[jo2*2+1] = ay*(1.0f/NL);
  }
  __syncthreads();

  for (int iter=0; iter<3; iter++){
    if (iter > 0){
      if (t<NP){
        float m=-1e30f;
        for (int j=0;j<NL;j++) m = fmaxf(m, bl[t*NL+j]);
        float ssum=0.f;
        for (int j=0;j<NL;j++) ssum += __expf(bl[t*NL+j]-m);
        nmx[t]=m; nnv[t]=1.f/ssum;
      }
      __syncthreads();
      for (int nj=t; nj<NP*NL; nj+=256){
        int n = nj/NL;
        cs[nj] = __expf(bl[nj]-nmx[n])*nnv[n];
      }
      __syncthreads();
      for (int jo2=t; jo2<JO/2; jo2+=256){
        int j = jo2>>3;
        float ax=0.f, ay=0.f;
#pragma unroll
        for (int n=0;n<NP;n++){
          float c = cs[n*NL+j];
          float2 f = __half22float2(p2[n*(JO/2)+jo2]);
          ax += c*f.x; ay += c*f.y;
        }
        vs[jo2*2]=ax; vs[jo2*2+1]=ay;
      }
      __syncthreads();
    }
    if (t<NL){
      float sq=0.f;
#pragma unroll
      for (int o=0;o<CD;o++){ float x=vs[t*CD+o]; sq+=x*x; }
      float scale = sq/(1.f+sq)*rsqrtf(sq+1e-8f);
#pragma unroll
      for (int o=0;o<CD;o++) vs[t*CD+o]*=scale;
    }
    __syncthreads();
    if (iter<2){
      for (int nj=t; nj<NP*NL; nj+=256){
        int n=nj/NL, j=nj%NL;
        float a=0.f;
#pragma unroll
        for (int o2=0;o2<CD/2;o2++){
          float2 f = __half22float2(p2[n*(JO/2) + j*(CD/2) + o2]);
          a += f.x*vs[j*CD+o2*2] + f.y*vs[j*CD+o2*2+1];
        }
        bl[nj] += a;
      }
      __syncthreads();
    }
  }
  for (int jo=t; jo<JO; jo+=256) V[(size_t)b*JO + jo] = vs[jo];
}

// ---------------- launch -----------------------------------------------------
extern "C" void kernel_launch(void* const* d_in, const int* in_sizes, int n_in,
                              void* d_out, int out_size)
{
  (void)in_sizes; (void)n_in; (void)out_size;
  const float* features = (const float*)d_in[0];
  const float* W1  = (const float*)d_in[1];
  const float* b1  = (const float*)d_in[2];
  const float* W2  = (const float*)d_in[3];
  const float* b2  = (const float*)d_in[4];
  const float* Wp  = (const float*)d_in[5];
  const float* bp  = (const float*)d_in[6];
  const float* lng = (const float*)d_in[7];
  const float* lnb = (const float*)d_in[8];
  const float* Wr  = (const float*)d_in[9];
  const float* Wc  = (const float*)d_in[10];
  const float* bc  = (const float*)d_in[11];
  float* out = (float*)d_out;

  __nv_bfloat16 *Ahi,*Alo,*B1hi,*B1lo,*B2hi,*B2lo,*X1hi,*X1lo;
  float *X2,*P,*V; __half* PR;
  cudaGetSymbolAddress((void**)&Ahi,  g_Ahi);
  cudaGetSymbolAddress((void**)&Alo,  g_Alo);
  cudaGetSymbolAddress((void**)&B1hi, g_B1hi);
  cudaGetSymbolAddress((void**)&B1lo, g_B1lo);
  cudaGetSymbolAddress((void**)&B2hi, g_B2hi);
  cudaGetSymbolAddress((void**)&B2lo, g_B2lo);
  cudaGetSymbolAddress((void**)&X1hi, g_X1hi);
  cudaGetSymbolAddress((void**)&X1lo, g_X1lo);
  cudaGetSymbolAddress((void**)&X2, g_X2);
  cudaGetSymbolAddress((void**)&P,  g_P);
  cudaGetSymbolAddress((void**)&PR, g_preds);
  cudaGetSymbolAddress((void**)&V,  g_V);

  // 1a) conversions (features, W1, W2 -> split bf16; weights transposed)
  convA_kernel<<<2048, 256>>>(features, Ahi, Alo);
  convW_kernel<<<dim3(KPAD1/32, H1/32), dim3(32,8)>>>(W1, B1hi, B1lo, IN_DIM, H1, KPAD1);
  convW_kernel<<<dim3(H1/32, H2/32),    dim3(32,8)>>>(W2, B2hi, B2lo, H1, H2, H1);
  // 1b) GEMM1: X1 = relu(features@W1+b1), emitted as bf16 hi/lo
  cudaFuncSetAttribute(mma_gemm_kernel<1>, cudaFuncAttributeMaxDynamicSharedMemorySize, G_SMEM);
  mma_gemm_kernel<1><<<dim3(H1/G_BN, BATCH/G_BM), 256, G_SMEM>>>(
      Ahi, Alo, B1hi, B1lo, b1, nullptr, X1hi, X1lo, KPAD1, KPAD1/G_BK, H1);
  // 2) GEMM2: X2 = relu(X1@W2+b2), fp32
  cudaFuncSetAttribute(mma_gemm_kernel<0>, cudaFuncAttributeMaxDynamicSharedMemorySize, G_SMEM);
  mma_gemm_kernel<0><<<dim3(H2/G_BN, BATCH/G_BM), 256, G_SMEM>>>(
      X1hi, X1lo, B2hi, B2lo, b2, X2, nullptr, nullptr, H1, H1/G_BK, H2);
  // 3) primary capsules + LayerNorm
  primary_kernel<<<BATCH/16, 256>>>(X2, Wp, bp, lng, lnb, P);
  // 4) preds (fp16)
  cudaFuncSetAttribute(preds_kernel, cudaFuncAttributeMaxDynamicSharedMemorySize,
                       (8*JO + 64*8)*4);
  preds_kernel<<<dim3(BATCH/64, NP), 256, (8*JO + 64*8)*4>>>(P, Wr, PR);
  // 5) dynamic routing -> V
  cudaFuncSetAttribute(routing_kernel, cudaFuncAttributeMaxDynamicSharedMemorySize,
                       SMEM_ROUTING);
  routing_kernel<<<BATCH, 256, SMEM_ROUTING>>>(PR, V);
  // 6) logits = V @ Wc + bc
  gemm_kernel<64,64,16,4,false><<<dim3((NL+63)/64, BATCH/64), 256>>>(
      V, Wc, bc, out, BATCH, NL, JO);
}

// round 4
// speedup vs baseline: 1.6076x; 1.0076x over previous
#include <cuda_runtime.h>
#include <cuda_fp16.h>
#include <cuda_bf16.h>
#include <cstdint>
#include <cstddef>

#define BATCH 4096
#define IN_DIM 10000
#define H1 512
#define H2 256
#define NP 32
#define PD 8
#define NL 100
#define CD 16
#define JO (NL*CD)       // 1600
#define PREDROW (NP*JO)  // 51200
#define KPAD1 10240
#define KSLICE 5120
#define NLPAD 128

// ---------------- helpers ----------------------------------------------------
__device__ __forceinline__ uint32_t smem_u32(const void* p) {
  uint32_t a;
  asm("{ .reg .u64 t; cvta.to.shared.u64 t, %1; cvt.u32.u64 %0, t; }" : "=r"(a) : "l"(p));
  return a;
}
__device__ __forceinline__ void cp_async16(uint32_t smem, const void* g) {
  asm volatile("cp.async.cg.shared.global [%0], [%1], 16;" :: "r"(smem), "l"(g));
}
#define CP_COMMIT() asm volatile("cp.async.commit_group;" ::: "memory")
#define CP_WAIT(N)  asm volatile("cp.async.wait_group %0;" :: "n"(N) : "memory")

__device__ __forceinline__ void ldm_x4(uint32_t* r, uint32_t addr) {
  asm volatile("ldmatrix.sync.aligned.m8n8.x4.shared.b16 {%0,%1,%2,%3}, [%4];"
               : "=r"(r[0]), "=r"(r[1]), "=r"(r[2]), "=r"(r[3]) : "r"(addr));
}
__device__ __forceinline__ void mma_bf16(float* d, const uint32_t* a, const uint32_t* b) {
  asm volatile("mma.sync.aligned.m16n8k16.row.col.f32.bf16.bf16.f32 "
               "{%0,%1,%2,%3}, {%4,%5,%6,%7}, {%8,%9}, {%0,%1,%2,%3};"
               : "+f"(d[0]), "+f"(d[1]), "+f"(d[2]), "+f"(d[3])
               : "r"(a[0]), "r"(a[1]), "r"(a[2]), "r"(a[3]), "r"(b[0]), "r"(b[1]));
}
__device__ __forceinline__ void mma_fp16(float* d, uint32_t a0, uint32_t a1,
                                         uint32_t a2, uint32_t a3,
                                         uint32_t b0, uint32_t b1) {
  asm volatile("mma.sync.aligned.m16n8k16.row.col.f32.f16.f16.f32 "
               "{%0,%1,%2,%3}, {%4,%5,%6,%7}, {%8,%9}, {%0,%1,%2,%3};"
               : "+f"(d[0]), "+f"(d[1]), "+f"(d[2]), "+f"(d[3])
               : "r"(a0), "r"(a1), "r"(a2), "r"(a3), "r"(b0), "r"(b1));
}
__device__ __forceinline__ uint32_t pack_bf16(float a, float b) {
  __nv_bfloat16 ha = __float2bfloat16(a), hb = __float2bfloat16(b);
  return (uint32_t)__bfloat16_as_ushort(ha) | ((uint32_t)__bfloat16_as_ushort(hb) << 16);
}

// ---------------- scratch ----------------------------------------------------
__device__ __nv_bfloat16 g_Ahi[(size_t)BATCH*KPAD1];
__device__ __nv_bfloat16 g_Alo[(size_t)BATCH*KPAD1];
__device__ __nv_bfloat16 g_B1hi[(size_t)H1*KPAD1];
__device__ __nv_bfloat16 g_B1lo[(size_t)H1*KPAD1];
__device__ __nv_bfloat16 g_B2hi[(size_t)H2*H1];
__device__ __nv_bfloat16 g_B2lo[(size_t)H2*H1];
__device__ __nv_bfloat16 g_Wchi[(size_t)NLPAD*JO];
__device__ __nv_bfloat16 g_Wclo[(size_t)NLPAD*JO];
__device__ float  g_bcPad[NLPAD];
__device__ float  g_Cpart[(size_t)2*BATCH*H1];
__device__ __nv_bfloat16 g_X1hi[(size_t)BATCH*H1];
__device__ __nv_bfloat16 g_X1lo[(size_t)BATCH*H1];
__device__ float  g_X2[(size_t)BATCH*H2];
__device__ float  g_P [(size_t)BATCH*H2];
__device__ __half g_preds[(size_t)BATCH*PREDROW];
__device__ __nv_bfloat16 g_Vhi[(size_t)BATCH*JO];
__device__ __nv_bfloat16 g_Vlo[(size_t)BATCH*JO];

// ---------------- conversions ------------------------------------------------
__global__ __launch_bounds__(256)
void convA_kernel(const float* __restrict__ F, __nv_bfloat16* __restrict__ Ahi,
                  __nv_bfloat16* __restrict__ Alo)
{
  size_t total = (size_t)BATCH*(KPAD1/4);
  for (size_t i = (size_t)blockIdx.x*blockDim.x + threadIdx.x; i < total;
       i += (size_t)gridDim.x*blockDim.x) {
    size_t row = i / (KPAD1/4);
    int k4 = (int)(i % (KPAD1/4)) * 4;
    float4 v = make_float4(0.f,0.f,0.f,0.f);
    if (k4 < IN_DIM) v = *(const float4*)(F + row*IN_DIM + k4);
    float h0 = __bfloat162float(__float2bfloat16(v.x));
    float h1 = __bfloat162float(__float2bfloat16(v.y));
    float h2 = __bfloat162float(__float2bfloat16(v.z));
    float h3 = __bfloat162float(__float2bfloat16(v.w));
    size_t o = row*KPAD1 + k4;
    *(uint32_t*)(Ahi+o)   = pack_bf16(h0, h1);
    *(uint32_t*)(Ahi+o+2) = pack_bf16(h2, h3);
    *(uint32_t*)(Alo+o)   = pack_bf16(v.x-h0, v.y-h1);
    *(uint32_t*)(Alo+o+2) = pack_bf16(v.z-h2, v.w-h3);
  }
}

// W[K,N] -> Bhi/Blo[Npad rows][KP] transposed + split; guards on k and n.
__global__ __launch_bounds__(256)
void convW_kernel(const float* __restrict__ W, __nv_bfloat16* __restrict__ Bhi,
                  __nv_bfloat16* __restrict__ Blo, int K, int N, int KP)
{
  __shared__ float tile[32][33];
  int kb = blockIdx.x*32, nb = blockIdx.y*32;
  int tx = threadIdx.x, ty = threadIdx.y;   // block (32,8)
#pragma unroll
  for (int i=0;i<32;i+=8){
    int k = kb+ty+i;
    int col = nb+tx;
    tile[ty+i][tx] = (k < K && col < N) ? W[(size_t)k*N + col] : 0.f;
  }
  __syncthreads();
#pragma unroll
  for (int i=0;i<32;i+=8){
    int n = nb+ty+i, k = kb+tx;
    float v = tile[tx][ty+i];
    float h = __bfloat162float(__float2bfloat16(v));
    Bhi[(size_t)n*KP + k] = __float2bfloat16(h);
    Blo[(size_t)n*KP + k] = __float2bfloat16(v - h);
  }
}

__global__ void bcpad_kernel(const float* __restrict__ bc, float* __restrict__ bcPad)
{
  int i = threadIdx.x;
  if (i < NLPAD) bcPad[i] = (i < NL) ? bc[i] : 0.f;
}

// ---------------- GEMM1: 4-warp 64x64 warp tiles, K-split 2 -----------------
#define T_BM 128
#define T_BN 128
#define T_BK 32
#define T_TILEB 8192
#define T_STAGEB (4*T_TILEB)          // 32 KB
#define T_SMEM (3*T_STAGEB)           // 96 KB

__global__ __launch_bounds__(128)
void gemm1_kernel(const __nv_bfloat16* __restrict__ Ahi,
                  const __nv_bfloat16* __restrict__ Alo,
                  const __nv_bfloat16* __restrict__ Bhi,
                  const __nv_bfloat16* __restrict__ Blo,
                  float* __restrict__ Cpart)
{
  extern __shared__ __align__(128) unsigned char smraw[];
  const uint32_t sb = smem_u32(smraw);
  const int t = threadIdx.x;
  const int m0 = blockIdx.y * T_BM;
  const int n0 = blockIdx.x * T_BN;
  const int kz = blockIdx.z;
  const size_t kofs = (size_t)kz * KSLICE;
  const int KT = KSLICE / T_BK;                 // 160

  const __nv_bfloat16* gb0 = Ahi; const __nv_bfloat16* gb1 = Alo;
  const __nv_bfloat16* gb2 = Bhi; const __nv_bfloat16* gb3 = Blo;

  auto load_stage = [&](int s, int kt){
    const uint32_t stb = sb + s*T_STAGEB;
    const size_t k0 = kofs + (size_t)kt*T_BK;
    for (int c = t; c < 2048; c += 128){
      int tile = c >> 9, rem = c & 511;
      int r = rem >> 2, c16 = rem & 3;
      int row0 = (tile < 2) ? m0 : n0;
      const __nv_bfloat16* g = (tile==0)?gb0:(tile==1)?gb1:(tile==2)?gb2:gb3;
      uint32_t dst = stb + tile*T_TILEB + r*64 + (((c16 ^ ((r>>1)&3))) << 4);
      cp_async16(dst, g + (size_t)(row0 + r)*KPAD1 + k0 + c16*8);
    }
  };

  const int wid = t>>5, lane = t&31;
  const int wm = wid & 1, wn = wid >> 1;
  int ra[4], rb[4];
#pragma unroll
  for (int i=0;i<4;i++) ra[i] = wm*64 + i*16 + (lane&7) + ((lane>>3)&1)*8;
#pragma unroll
  for (int h=0;h<4;h++) rb[h] = wn*64 + h*16 + (lane&7) + ((lane>>4)&1)*8;
  const int ca = lane>>4;
  const int cb = (lane>>3)&1;

  float acc[4][8][4];
#pragma unroll
  for (int i=0;i<4;i++)
#pragma unroll
    for (int j=0;j<8;j++)
#pragma unroll
      for (int q=0;q<4;q++) acc[i][j][q]=0.f;

  load_stage(0, 0); CP_COMMIT();
  load_stage(1, 1); CP_COMMIT();

  for (int kt = 0; kt < KT; kt++){
    CP_WAIT(1);
    __syncthreads();
    if (kt + 2 < KT) load_stage((kt + 2) % 3, kt + 2);
    CP_COMMIT();

    const uint32_t stb = sb + (kt % 3)*T_STAGEB;
#pragma unroll
    for (int kk = 0; kk < 2; kk++){
      uint32_t AH[4][4], AL[4][4], BH[8][2], BL[8][2];
#pragma unroll
      for (int i=0;i<4;i++){
        uint32_t off = ra[i]*64 + ((((kk*2 + ca) ^ ((ra[i]>>1)&3))) << 4);
        ldm_x4(AH[i], stb + 0*T_TILEB + off);
        ldm_x4(AL[i], stb + 1*T_TILEB + off);
      }
#pragma unroll
      for (int h=0;h<4;h++){
        uint32_t off = rb[h]*64 + ((((kk*2 + cb) ^ ((rb[h]>>1)&3))) << 4);
        uint32_t r4[4];
        ldm_x4(r4, stb + 2*T_TILEB + off);
        BH[h*2][0]=r4[0]; BH[h*2][1]=r4[1]; BH[h*2+1][0]=r4[2]; BH[h*2+1][1]=r4[3];
        ldm_x4(r4, stb + 3*T_TILEB + off);
        BL[h*2][0]=r4[0]; BL[h*2][1]=r4[1]; BL[h*2+1][0]=r4[2]; BL[h*2+1][1]=r4[3];
      }
#pragma unroll
      for (int i=0;i<4;i++)
#pragma unroll
        for (int j=0;j<8;j++){
          mma_bf16(acc[i][j], AH[i], BH[j]);
          mma_bf16(acc[i][j], AH[i], BL[j]);
          mma_bf16(acc[i][j], AL[i], BH[j]);
        }
    }
    __syncthreads();
  }

  const int g = lane >> 2, tq = lane & 3;
#pragma unroll
  for (int i=0;i<4;i++){
#pragma unroll
    for (int j=0;j<8;j++){
      int row = m0 + wm*64 + i*16 + g;
      int col = n0 + wn*64 + j*8 + tq*2;
      float* dst = Cpart + ((size_t)kz*BATCH + row)*H1 + col;
      *(float2*)dst              = make_float2(acc[i][j][0], acc[i][j][1]);
      *(float2*)(dst + 8*H1)     = make_float2(acc[i][j][2], acc[i][j][3]);
    }
  }
}

// ---------------- reduce partials + bias + relu -> X1 (bf16 split) ----------
__global__ __launch_bounds__(256)
void reduce_relu_kernel(const float* __restrict__ C, const float* __restrict__ b1,
                        __nv_bfloat16* __restrict__ X1hi, __nv_bfloat16* __restrict__ X1lo)
{
  size_t total = (size_t)BATCH*H1/4;
  for (size_t i = (size_t)blockIdx.x*blockDim.x + threadIdx.x; i < total;
       i += (size_t)gridDim.x*blockDim.x) {
    float4 a = *(const float4*)(C + i*4);
    float4 b = *(const float4*)(C + (size_t)BATCH*H1 + i*4);
    int col = (int)((i*4) % H1);
    float4 bb = *(const float4*)(b1 + col);
    float v0 = fmaxf(a.x+b.x+bb.x, 0.f);
    float v1 = fmaxf(a.y+b.y+bb.y, 0.f);
    float v2 = fmaxf(a.z+b.z+bb.z, 0.f);
    float v3 = fmaxf(a.w+b.w+bb.w, 0.f);
    float h0 = __bfloat162float(__float2bfloat16(v0));
    float h1 = __bfloat162float(__float2bfloat16(v1));
    float h2 = __bfloat162float(__float2bfloat16(v2));
    float h3 = __bfloat162float(__float2bfloat16(v3));
    *(uint32_t*)(X1hi + i*4)     = pack_bf16(h0, h1);
    *(uint32_t*)(X1hi + i*4 + 2) = pack_bf16(h2, h3);
    *(uint32_t*)(X1lo + i*4)     = pack_bf16(v0-h0, v1-h1);
    *(uint32_t*)(X1lo + i*4 + 2) = pack_bf16(v2-h2, v3-h3);
  }
}

// ---------------- generic split-bf16 mma GEMM (GEMM2, logits) ----------------
// 8 warps, 64x32 warp tiles; C = relu?no: C = A@B + bias, fp32 out.
// NV: valid/store-stride N (cols >= NV are padding, not written).
#define G_BM 128
#define G_BN 128
#define G_BK 32
#define G_STAGES 3
#define G_TILEB 8192
#define G_STAGEB (4*G_TILEB)
#define G_SMEM (G_STAGES*G_STAGEB)

__global__ __launch_bounds__(256, 1)
void mma_gemm_kernel(const __nv_bfloat16* __restrict__ Ahi,
                     const __nv_bfloat16* __restrict__ Alo,
                     const __nv_bfloat16* __restrict__ Bhi,
                     const __nv_bfloat16* __restrict__ Blo,
                     const float* __restrict__ bias,
                     float* __restrict__ outF,
                     int Kdim, int KT, int NV)
{
  extern __shared__ __align__(128) unsigned char smraw[];
  const uint32_t sb = smem_u32(smraw);
  const int t = threadIdx.x;
  const int m0 = blockIdx.y * G_BM;
  const int n0 = blockIdx.x * G_BN;

  auto load_stage = [&](int s, int kt){
    const uint32_t stb = sb + s*G_STAGEB;
    const int k0 = kt*G_BK;
    const __nv_bfloat16* gb[4] = {Ahi, Alo, Bhi, Blo};
#pragma unroll
    for (int tile = 0; tile < 4; tile++){
      const int row0 = (tile < 2) ? m0 : n0;
      const __nv_bfloat16* g = gb[tile];
#pragma unroll
      for (int half = 0; half < 2; half++){
        int rem = half*256 + t;
        int r = rem >> 2, c16 = rem & 3;
        uint32_t dst = stb + tile*G_TILEB + r*64 + (((c16 ^ ((r>>1)&3))) << 4);
        cp_async16(dst, g + (size_t)(row0 + r)*Kdim + k0 + c16*8);
      }
    }
  };

  const int wid = t >> 5, lane = t & 31;
  const int wm = wid & 1, wn = wid >> 1;
  int ra[4], rb[2];
#pragma unroll
  for (int i=0;i<4;i++) ra[i] = wm*64 + i*16 + (lane&7) + ((lane>>3)&1)*8;
#pragma unroll
  for (int h=0;h<2;h++)  rb[h] = wn*32 + h*16 + (lane&7) + ((lane>>4)&1)*8;
  const int ca = (lane>>4);
  const int cb = ((lane>>3)&1);

  float acc[4][4][4];
#pragma unroll
  for (int i=0;i<4;i++)
#pragma unroll
    for (int j=0;j<4;j++)
#pragma unroll
      for (int q=0;q<4;q++) acc[i][j][q]=0.f;

  load_stage(0, 0); CP_COMMIT();
  load_stage(1, 1); CP_COMMIT();

  for (int kt = 0; kt < KT; kt++){
    CP_WAIT(1);
    __syncthreads();
    if (kt + G_STAGES - 1 < KT) load_stage((kt + G_STAGES - 1) % G_STAGES, kt + G_STAGES - 1);
    CP_COMMIT();

    const uint32_t stb = sb + (kt % G_STAGES)*G_STAGEB;
#pragma unroll
    for (int kk = 0; kk < 2; kk++){
      uint32_t AH[4][4], AL[4][4], BH[4][2], BL[4][2];
#pragma unroll
      for (int i=0;i<4;i++){
        uint32_t off = ra[i]*64 + ((((kk*2 + ca) ^ ((ra[i]>>1)&3))) << 4);
        ldm_x4(AH[i], stb + 0*G_TILEB + off);
        ldm_x4(AL[i], stb + 1*G_TILEB + off);
      }
#pragma unroll
      for (int h=0;h<2;h++){
        uint32_t off = rb[h]*64 + ((((kk*2 + cb) ^ ((rb[h]>>1)&3))) << 4);
        uint32_t r4[4];
        ldm_x4(r4, stb + 2*G_TILEB + off);
        BH[h*2][0]=r4[0]; BH[h*2][1]=r4[1]; BH[h*2+1][0]=r4[2]; BH[h*2+1][1]=r4[3];
        ldm_x4(r4, stb + 3*G_TILEB + off);
        BL[h*2][0]=r4[0]; BL[h*2][1]=r4[1]; BL[h*2+1][0]=r4[2]; BL[h*2+1][1]=r4[3];
      }
#pragma unroll
      for (int i=0;i<4;i++)
#pragma unroll
        for (int j=0;j<4;j++){
          mma_bf16(acc[i][j], AH[i], BH[j]);
          mma_bf16(acc[i][j], AH[i], BL[j]);
          mma_bf16(acc[i][j], AL[i], BH[j]);
        }
    }
    __syncthreads();
  }

  const int g = lane >> 2, tq = lane & 3;
#pragma unroll
  for (int i=0;i<4;i++){
#pragma unroll
    for (int j=0;j<4;j++){
      int row = m0 + wm*64 + i*16 + g;
      int col = n0 + wn*32 + j*8 + tq*2;
      if (col < NV){
        float b0 = bias[col], b1 = bias[col+1];
        *(float2*)(outF + (size_t)row*NV + col)     = make_float2(acc[i][j][0]+b0, acc[i][j][1]+b1);
        *(float2*)(outF + (size_t)(row+8)*NV + col) = make_float2(acc[i][j][2]+b0, acc[i][j][3]+b1);
      }
    }
  }
}

// GEMM2 needs relu — separate tiny variant flag via NV sign? Use dedicated kernel.
__global__ __launch_bounds__(256, 1)
void mma_gemm_relu_kernel(const __nv_bfloat16* __restrict__ Ahi,
                          const __nv_bfloat16* __restrict__ Alo,
                          const __nv_bfloat16* __restrict__ Bhi,
                          const __nv_bfloat16* __restrict__ Blo,
                          const float* __restrict__ bias,
                          float* __restrict__ outF,
                          int Kdim, int KT, int NV)
{
  extern __shared__ __align__(128) unsigned char smraw[];
  const uint32_t sb = smem_u32(smraw);
  const int t = threadIdx.x;
  const int m0 = blockIdx.y * G_BM;
  const int n0 = blockIdx.x * G_BN;

  auto load_stage = [&](int s, int kt){
    const uint32_t stb = sb + s*G_STAGEB;
    const int k0 = kt*G_BK;
    const __nv_bfloat16* gb[4] = {Ahi, Alo, Bhi, Blo};
#pragma unroll
    for (int tile = 0; tile < 4; tile++){
      const int row0 = (tile < 2) ? m0 : n0;
      const __nv_bfloat16* g = gb[tile];
#pragma unroll
      for (int half = 0; half < 2; half++){
        int rem = half*256 + t;
        int r = rem >> 2, c16 = rem & 3;
        uint32_t dst = stb + tile*G_TILEB + r*64 + (((c16 ^ ((r>>1)&3))) << 4);
        cp_async16(dst, g + (size_t)(row0 + r)*Kdim + k0 + c16*8);
      }
    }
  };

  const int wid = t >> 5, lane = t & 31;
  const int wm = wid & 1, wn = wid >> 1;
  int ra[4], rb[2];
#pragma unroll
  for (int i=0;i<4;i++) ra[i] = wm*64 + i*16 + (lane&7) + ((lane>>3)&1)*8;
#pragma unroll
  for (int h=0;h<2;h++)  rb[h] = wn*32 + h*16 + (lane&7) + ((lane>>4)&1)*8;
  const int ca = (lane>>4);
  const int cb = ((lane>>3)&1);

  float acc[4][4][4];
#pragma unroll
  for (int i=0;i<4;i++)
#pragma unroll
    for (int j=0;j<4;j++)
#pragma unroll
      for (int q=0;q<4;q++) acc[i][j][q]=0.f;

  load_stage(0, 0); CP_COMMIT();
  load_stage(1, 1); CP_COMMIT();

  for (int kt = 0; kt < KT; kt++){
    CP_WAIT(1);
    __syncthreads();
    if (kt + G_STAGES - 1 < KT) load_stage((kt + G_STAGES - 1) % G_STAGES, kt + G_STAGES - 1);
    CP_COMMIT();

    const uint32_t stb = sb + (kt % G_STAGES)*G_STAGEB;
#pragma unroll
    for (int kk = 0; kk < 2; kk++){
      uint32_t AH[4][4], AL[4][4], BH[4][2], BL[4][2];
#pragma unroll
      for (int i=0;i<4;i++){
        uint32_t off = ra[i]*64 + ((((kk*2 + ca) ^ ((ra[i]>>1)&3))) << 4);
        ldm_x4(AH[i], stb + 0*G_TILEB + off);
        ldm_x4(AL[i], stb + 1*G_TILEB + off);
      }
#pragma unroll
      for (int h=0;h<2;h++){
        uint32_t off = rb[h]*64 + ((((kk*2 + cb) ^ ((rb[h]>>1)&3))) << 4);
        uint32_t r4[4];
        ldm_x4(r4, stb + 2*G_TILEB + off);
        BH[h*2][0]=r4[0]; BH[h*2][1]=r4[1]; BH[h*2+1][0]=r4[2]; BH[h*2+1][1]=r4[3];
        ldm_x4(r4, stb + 3*G_TILEB + off);
        BL[h*2][0]=r4[0]; BL[h*2][1]=r4[1]; BL[h*2+1][0]=r4[2]; BL[h*2+1][1]=r4[3];
      }
#pragma unroll
      for (int i=0;i<4;i++)
#pragma unroll
        for (int j=0;j<4;j++){
          mma_bf16(acc[i][j], AH[i], BH[j]);
          mma_bf16(acc[i][j], AH[i], BL[j]);
          mma_bf16(acc[i][j], AL[i], BH[j]);
        }
    }
    __syncthreads();
  }

  const int g = lane >> 2, tq = lane & 3;
#pragma unroll
  for (int i=0;i<4;i++){
#pragma unroll
    for (int j=0;j<4;j++){
      int row = m0 + wm*64 + i*16 + g;
      int col = n0 + wn*32 + j*8 + tq*2;
      if (col < NV){
        float b0 = bias[col], b1 = bias[col+1];
        float v0 = fmaxf(acc[i][j][0]+b0, 0.f);
        float v1 = fmaxf(acc[i][j][1]+b1, 0.f);
        float v2 = fmaxf(acc[i][j][2]+b0, 0.f);
        float v3 = fmaxf(acc[i][j][3]+b1, 0.f);
        *(float2*)(outF + (size_t)row*NV + col)     = make_float2(v0, v1);
        *(float2*)(outF + (size_t)(row+8)*NV + col) = make_float2(v2, v3);
      }
    }
  }
}

// ---------------- primary capsules + per-capsule LayerNorm -------------------
__global__ __launch_bounds__(256)
void primary_kernel(const float* __restrict__ X2, const float* __restrict__ Wp,
                    const float* __restrict__ bp, const float* __restrict__ lng,
                    const float* __restrict__ lnb, float* __restrict__ P)
{
  __shared__ __align__(16) float xs[16][H2];
  const int t  = threadIdx.x;
  const int b0 = blockIdx.x * 16;
  for (int idx=t; idx<16*(H2/4); idx+=256){
    int bb = idx/(H2/4);
    int c4 = (idx%(H2/4))*4;
    *(float4*)&xs[bb][c4] = *(const float4*)(X2 + (size_t)(b0+bb)*H2 + c4);
  }
  __syncthreads();
  const int n = t>>3, o = t&7;
  float bias = bp[t];
  float acc[16];
#pragma unroll
  for (int bb=0;bb<16;bb++) acc[bb]=bias;
  const float* wp = Wp + (size_t)n*(H2*PD) + o;
  for (int i0=0;i0<H2;i0+=4){
    float w0 = __ldg(wp + (size_t)(i0+0)*PD);
    float w1 = __ldg(wp + (size_t)(i0+1)*PD);
    float w2 = __ldg(wp + (size_t)(i0+2)*PD);
    float w3 = __ldg(wp + (size_t)(i0+3)*PD);
#pragma unroll
    for (int bb=0;bb<16;bb++){
      float4 x = *(const float4*)&xs[bb][i0];
      acc[bb] += x.x*w0 + x.y*w1 + x.z*w2 + x.w*w3;
    }
  }
  float g = lng[t], be = lnb[t];
#pragma unroll
  for (int bb=0;bb<16;bb++){
    float x = acc[bb];
    float s = x;
    s += __shfl_xor_sync(0xffffffffu, s, 1);
    s += __shfl_xor_sync(0xffffffffu, s, 2);
    s += __shfl_xor_sync(0xffffffffu, s, 4);
    float mu = s * 0.125f;
    float d  = x - mu;
    float q  = d*d;
    q += __shfl_xor_sync(0xffffffffu, q, 1);
    q += __shfl_xor_sync(0xffffffffu, q, 2);
    q += __shfl_xor_sync(0xffffffffu, q, 4);
    float var = q * 0.125f;
    P[(size_t)(b0+bb)*H2 + t] = d * rsqrtf(var + 1e-5f) * g + be;
  }
}

// ---------------- preds via fp16 mma: A=[p_hi|p_lo], B=[w|w] -----------------
#define PCHUNK 160
#define PCSTRIDE 168   // padded row stride (halves); 336 B, 16B-aligned
#define PREDS_SMEM (JO*PD*2 + 128*16*2 + 128*PCSTRIDE*2)  // 25600+4096+43008 = 72704

__global__ __launch_bounds__(256)
void preds_mma_kernel(const float* __restrict__ P, const float* __restrict__ Wr,
                      __half* __restrict__ preds)
{
  extern __shared__ __align__(16) unsigned char smraw[];
  __half* wsh  = (__half*)smraw;                         // [JO][8] fp16
  __half* ash  = wsh + JO*PD;                            // [128][16]
  __half* cbuf = ash + 128*16;                           // [128][PCSTRIDE]
  const int n  = blockIdx.y;
  const int b0 = blockIdx.x * 128;
  const int t  = threadIdx.x;
  const int wid = t>>5, lane = t&31;

  const float* wsrc = Wr + (size_t)n*(JO*PD);
  for (int idx=t; idx<JO*PD; idx+=256) wsh[idx] = __float2half(wsrc[idx]);
  for (int idx=t; idx<128*8; idx+=256){
    int r = idx>>3, i = idx&7;
    float v = P[(size_t)(b0+r)*H2 + n*8 + i];
    __half h = __float2half(v);
    ash[r*16 + i]     = h;
    ash[r*16 + 8 + i] = __float2half(v - __half2float(h));
  }
  __syncthreads();

  const int g = lane>>2, tq = lane&3;
  const int ar0 = wid*16 + g;
  uint32_t a0 = *(const uint32_t*)&ash[ar0*16 + tq*2];
  uint32_t a1 = *(const uint32_t*)&ash[(ar0+8)*16 + tq*2];
  uint32_t a2 = *(const uint32_t*)&ash[ar0*16 + 8 + tq*2];
  uint32_t a3 = *(const uint32_t*)&ash[(ar0+8)*16 + 8 + tq*2];

  for (int chunk = 0; chunk < JO/PCHUNK; chunk++){
#pragma unroll 4
    for (int jt = 0; jt < PCHUNK/8; jt++){
      int jo0 = chunk*PCHUNK + jt*8;
      uint32_t b0v = *(const uint32_t*)&wsh[(jo0+g)*8 + tq*2];
      float c[4] = {0.f,0.f,0.f,0.f};
      mma_fp16(c, a0, a1, a2, a3, b0v, b0v);
      __half2 lo = __floats2half2_rn(c[0], c[1]);
      __half2 hi = __floats2half2_rn(c[2], c[3]);
      *(__half2*)&cbuf[(wid*16+g)*PCSTRIDE + jt*8 + tq*2]   = lo;
      *(__half2*)&cbuf[(wid*16+g+8)*PCSTRIDE + jt*8 + tq*2] = hi;
    }
    __syncthreads();
    for (int idx = t; idx < 128*(PCHUNK/8); idx += 256){
      int r = idx / (PCHUNK/8), q = idx % (PCHUNK/8);
      uint4 v = *(const uint4*)&cbuf[r*PCSTRIDE + q*8];
      *(uint4*)(preds + (size_t)(b0+r)*PREDROW + (size_t)n*JO + chunk*PCHUNK + q*8) = v;
    }
    __syncthreads();
  }
}

// ---------------- dynamic routing (3 iters) in SMEM, 512 threads -------------
#define SMEM_ROUTING (PREDROW*2 + (NP*NL + NP*NL + JO + 2*NP)*4)
#define RT_THREADS 512

__global__ void routing_kernel(const __half* __restrict__ preds,
                               __nv_bfloat16* __restrict__ Vhi,
                               __nv_bfloat16* __restrict__ Vlo)
{
  extern __shared__ __align__(16) unsigned char smraw[];
  __half* ps = (__half*)smraw;
  float* bl  = (float*)(smraw + (size_t)PREDROW*2);
  float* cs  = bl + NP*NL;
  float* vs  = cs + NP*NL;
  float* nmx = vs + JO;
  float* nnv = nmx + NP;
  const int b = blockIdx.x;
  const int t = threadIdx.x;

  {
    const uint4* src = (const uint4*)(preds + (size_t)b*PREDROW);
    uint4* dst = (uint4*)ps;
    for (int i=t; i<PREDROW/8; i+=RT_THREADS) dst[i] = src[i];
  }
  for (int i=t; i<NP*NL; i+=RT_THREADS) bl[i]=0.f;
  __syncthreads();

  const __half2* p2 = (const __half2*)ps;

  for (int jo2=t; jo2<JO/2; jo2+=RT_THREADS){
    float ax=0.f, ay=0.f;
#pragma unroll
    for (int n=0;n<NP;n++){
      float2 f = __half22float2(p2[n*(JO/2)+jo2]);
      ax += f.x; ay += f.y;
    }
    vs[jo2*2]   = ax*(1.0f/NL);
    vs[jo2*2+1] = ay*(1.0f/NL);
  }
  __syncthreads();

  for (int iter=0; iter<3; iter++){
    if (iter > 0){
      if (t<NP){
        float m=-1e30f;
        for (int j=0;j<NL;j++) m = fmaxf(m, bl[t*NL+j]);
        float ssum=0.f;
        for (int j=0;j<NL;j++) ssum += __expf(bl[t*NL+j]-m);
        nmx[t]=m; nnv[t]=1.f/ssum;
      }
      __syncthreads();
      for (int nj=t; nj<NP*NL; nj+=RT_THREADS){
        int n = nj/NL;
        cs[nj] = __expf(bl[nj]-nmx[n])*nnv[n];
      }
      __syncthreads();
      for (int jo2=t; jo2<JO/2; jo2+=RT_THREADS){
        int j = jo2>>3;
        float ax=0.f, ay=0.f;
#pragma unroll
        for (int n=0;n<NP;n++){
          float c = cs[n*NL+j];
          float2 f = __half22float2(p2[n*(JO/2)+jo2]);
          ax += c*f.x; ay += c*f.y;
        }
        vs[jo2*2]=ax; vs[jo2*2+1]=ay;
      }
      __syncthreads();
    }
    if (t<NL){
      float sq=0.f;
#pragma unroll
      for (int o=0;o<CD;o++){ float x=vs[t*CD+o]; sq+=x*x; }
      float scale = sq/(1.f+sq)*rsqrtf(sq+1e-8f);
#pragma unroll
      for (int o=0;o<CD;o++) vs[t*CD+o]*=scale;
    }
    __syncthreads();
    if (iter<2){
      for (int nj=t; nj<NP*NL; nj+=RT_THREADS){
        int n=nj/NL, j=nj%NL;
        float a=0.f;
#pragma unroll
        for (int o2=0;o2<CD/2;o2++){
          float2 f = __half22float2(p2[n*(JO/2) + j*(CD/2) + o2]);
          a += f.x*vs[j*CD+o2*2] + f.y*vs[j*CD+o2*2+1];
        }
        bl[nj] += a;
      }
      __syncthreads();
    }
  }
  for (int jo=t; jo<JO; jo+=RT_THREADS){
    float v = vs[jo];
    float h = __bfloat162float(__float2bfloat16(v));
    Vhi[(size_t)b*JO + jo] = __float2bfloat16(h);
    Vlo[(size_t)b*JO + jo] = __float2bfloat16(v - h);
  }
}

// ---------------- launch -----------------------------------------------------
extern "C" void kernel_launch(void* const* d_in, const int* in_sizes, int n_in,
                              void* d_out, int out_size)
{
  (void)in_sizes; (void)n_in; (void)out_size;
  const float* features = (const float*)d_in[0];
  const float* W1  = (const float*)d_in[1];
  const float* b1  = (const float*)d_in[2];
  const float* W2  = (const float*)d_in[3];
  const float* b2  = (const float*)d_in[4];
  const float* Wp  = (const float*)d_in[5];
  const float* bp  = (const float*)d_in[6];
  const float* lng = (const float*)d_in[7];
  const float* lnb = (const float*)d_in[8];
  const float* Wr  = (const float*)d_in[9];
  const float* Wc  = (const float*)d_in[10];
  const float* bc  = (const float*)d_in[11];
  float* out = (float*)d_out;

  __nv_bfloat16 *Ahi,*Alo,*B1hi,*B1lo,*B2hi,*B2lo,*Wchi,*Wclo,*X1hi,*X1lo,*Vhi,*Vlo;
  float *X2,*P,*Cp,*bcPad; __half* PR;
  cudaGetSymbolAddress((void**)&Ahi,  g_Ahi);
  cudaGetSymbolAddress((void**)&Alo,  g_Alo);
  cudaGetSymbolAddress((void**)&B1hi, g_B1hi);
  cudaGetSymbolAddress((void**)&B1lo, g_B1lo);
  cudaGetSymbolAddress((void**)&B2hi, g_B2hi);
  cudaGetSymbolAddress((void**)&B2lo, g_B2lo);
  cudaGetSymbolAddress((void**)&Wchi, g_Wchi);
  cudaGetSymbolAddress((void**)&Wclo, g_Wclo);
  cudaGetSymbolAddress((void**)&bcPad,g_bcPad);
  cudaGetSymbolAddress((void**)&Cp,   g_Cpart);
  cudaGetSymbolAddress((void**)&X1hi, g_X1hi);
  cudaGetSymbolAddress((void**)&X1lo, g_X1lo);
  cudaGetSymbolAddress((void**)&X2, g_X2);
  cudaGetSymbolAddress((void**)&P,  g_P);
  cudaGetSymbolAddress((void**)&PR, g_preds);
  cudaGetSymbolAddress((void**)&Vhi, g_Vhi);
  cudaGetSymbolAddress((void**)&Vlo, g_Vlo);

  // conversions
  convA_kernel<<<2048, 256>>>(features, Ahi, Alo);
  convW_kernel<<<dim3(KPAD1/32, H1/32), dim3(32,8)>>>(W1, B1hi, B1lo, IN_DIM, H1, KPAD1);
  convW_kernel<<<dim3(H1/32, H2/32),    dim3(32,8)>>>(W2, B2hi, B2lo, H1, H2, H1);
  convW_kernel<<<dim3(JO/32, NLPAD/32), dim3(32,8)>>>(Wc, Wchi, Wclo, JO, NL, JO);
  bcpad_kernel<<<1, NLPAD>>>(bc, bcPad);

  // GEMM1 (K-split 2) + reduce
  cudaFuncSetAttribute(gemm1_kernel, cudaFuncAttributeMaxDynamicSharedMemorySize, T_SMEM);
  gemm1_kernel<<<dim3(H1/T_BN, BATCH/T_BM, 2), 128, T_SMEM>>>(Ahi, Alo, B1hi, B1lo, Cp);
  reduce_relu_kernel<<<1024, 256>>>(Cp, b1, X1hi, X1lo);

  // GEMM2 (relu)
  cudaFuncSetAttribute(mma_gemm_relu_kernel, cudaFuncAttributeMaxDynamicSharedMemorySize, G_SMEM);
  mma_gemm_relu_kernel<<<dim3(H2/G_BN, BATCH/G_BM), 256, G_SMEM>>>(
      X1hi, X1lo, B2hi, B2lo, b2, X2, H1, H1/G_BK, H2);

  // primary capsules + LN
  primary_kernel<<<BATCH/16, 256>>>(X2, Wp, bp, lng, lnb, P);

  // preds (fp16 mma)
  cudaFuncSetAttribute(preds_mma_kernel, cudaFuncAttributeMaxDynamicSharedMemorySize, PREDS_SMEM);
  preds_mma_kernel<<<dim3(BATCH/128, NP), 256, PREDS_SMEM>>>(P, Wr, PR);

  // routing -> V (bf16 split)
  cudaFuncSetAttribute(routing_kernel, cudaFuncAttributeMaxDynamicSharedMemorySize, SMEM_ROUTING);
  routing_kernel<<<BATCH, RT_THREADS, SMEM_ROUTING>>>(PR, Vhi, Vlo);

  // logits = V @ Wc + bc (padded N=128, valid 100)
  cudaFuncSetAttribute(mma_gemm_kernel, cudaFuncAttributeMaxDynamicSharedMemorySize, G_SMEM);
  mma_gemm_kernel<<<dim3(1, BATCH/G_BM), 256, G_SMEM>>>(
      Vhi, Vlo, Wchi, Wclo, bcPad, out, JO, JO/G_BK, NL);
}

// round 5
// speedup vs baseline: 1.7995x; 1.1194x over previous
#include <cuda_runtime.h>
#include <cuda_fp16.h>
#include <cstdint>
#include <cstddef>

#define BATCH 4096
#define IN_DIM 10000
#define H1 512
#define H2 256
#define NP 32
#define PD 8
#define NL 100
#define CD 16
#define JO (NL*CD)       // 1600
#define PREDROW (NP*JO)  // 51200
#define KPAD1 10240
#define NLPAD 128

// ---------------- helpers ----------------------------------------------------
__device__ __forceinline__ uint32_t smem_u32(const void* p) {
  uint32_t a;
  asm("{ .reg .u64 t; cvta.to.shared.u64 t, %1; cvt.u32.u64 %0, t; }" : "=r"(a) : "l"(p));
  return a;
}
__device__ __forceinline__ void cp_async16(uint32_t smem, const void* g) {
  asm volatile("cp.async.cg.shared.global [%0], [%1], 16;" :: "r"(smem), "l"(g));
}
#define CP_COMMIT() asm volatile("cp.async.commit_group;" ::: "memory")
#define CP_WAIT(N)  asm volatile("cp.async.wait_group %0;" :: "n"(N) : "memory")

__device__ __forceinline__ void ldm_x4(uint32_t* r, uint32_t addr) {
  asm volatile("ldmatrix.sync.aligned.m8n8.x4.shared.b16 {%0,%1,%2,%3}, [%4];"
               : "=r"(r[0]), "=r"(r[1]), "=r"(r[2]), "=r"(r[3]) : "r"(addr));
}
__device__ __forceinline__ void mma_fp16(float* d, uint32_t a0, uint32_t a1,
                                         uint32_t a2, uint32_t a3,
                                         uint32_t b0, uint32_t b1) {
  asm volatile("mma.sync.aligned.m16n8k16.row.col.f32.f16.f16.f32 "
               "{%0,%1,%2,%3}, {%4,%5,%6,%7}, {%8,%9}, {%0,%1,%2,%3};"
               : "+f"(d[0]), "+f"(d[1]), "+f"(d[2]), "+f"(d[3])
               : "r"(a0), "r"(a1), "r"(a2), "r"(a3), "r"(b0), "r"(b1));
}

// ---------------- scratch ----------------------------------------------------
// A operands are "K-packed split fp16": row length 2*K halves; logical k-octet o
// occupies halves [16o..16o+7] = hi, [16o+8..16o+15] = lo.
__device__ __half g_A1p[(size_t)BATCH*2*KPAD1];   // features packed (160 MB)
__device__ __half g_B1h[(size_t)H1*KPAD1];        // W1^T fp16
__device__ __half g_B2h[(size_t)H2*H1];           // W2^T fp16
__device__ __half g_Wch[(size_t)NLPAD*JO];        // Wc^T fp16, zero-padded rows
__device__ float  g_Cpart[(size_t)2*BATCH*H1];    // GEMM1 k-split partials
__device__ __half g_X1p[(size_t)BATCH*2*H1];      // X1 packed
__device__ float  g_X2[(size_t)BATCH*H2];
__device__ float  g_P [(size_t)BATCH*H2];
__device__ __half g_preds[(size_t)BATCH*PREDROW];
__device__ __half g_Vp[(size_t)BATCH*2*JO];       // V packed

// ---------------- conversions ------------------------------------------------
// features -> packed split fp16 (zero-pad K to KPAD1; IN_DIM % 8 == 0)
__global__ __launch_bounds__(256)
void convA_f16_kernel(const float* __restrict__ F, __half* __restrict__ Ap)
{
  int total = BATCH*(KPAD1/8);
  for (int i = blockIdx.x*blockDim.x + threadIdx.x; i < total;
       i += gridDim.x*blockDim.x) {
    int row = i / (KPAD1/8), o = i % (KPAD1/8);
    uint32_t u[8];
    if (o*8 < IN_DIM){
      const float* src = F + (size_t)row*IN_DIM + o*8;
#pragma unroll
      for (int k=0;k<8;k+=2){
        float v0 = src[k], v1 = src[k+1];
        __half h0 = __float2half(v0), h1 = __float2half(v1);
        u[k>>1]     = (uint32_t)__half_as_ushort(h0) | ((uint32_t)__half_as_ushort(h1)<<16);
        __half l0 = __float2half(v0 - __half2float(h0));
        __half l1 = __float2half(v1 - __half2float(h1));
        u[4+(k>>1)] = (uint32_t)__half_as_ushort(l0) | ((uint32_t)__half_as_ushort(l1)<<16);
      }
    } else {
#pragma unroll
      for (int k=0;k<8;k++) u[k]=0;
    }
    __half* dst = Ap + (size_t)row*(2*KPAD1) + o*16;
    *(uint4*)dst       = *(uint4*)u;
    *(uint4*)(dst + 8) = *(uint4*)(u+4);
  }
}

// W[K,N] -> B[Npad rows][KP] transposed fp16 (zero-pad both dims)
__global__ __launch_bounds__(256)
void convW_f16_kernel(const float* __restrict__ W, __half* __restrict__ B,
                      int K, int N, int KP)
{
  __shared__ float tile[32][33];
  int kb = blockIdx.x*32, nb = blockIdx.y*32;
  int tx = threadIdx.x, ty = threadIdx.y;   // block (32,8)
#pragma unroll
  for (int i=0;i<32;i+=8){
    int k = kb+ty+i, col = nb+tx;
    tile[ty+i][tx] = (k < K && col < N) ? W[(size_t)k*N + col] : 0.f;
  }
  __syncthreads();
#pragma unroll
  for (int i=0;i<32;i+=8){
    int n = nb+ty+i, k = kb+tx;
    B[(size_t)n*KP + k] = __float2half(tile[tx][ty+i]);
  }
}

// ---------------- fp16 K-packed GEMM ----------------------------------------
// C[M,N] = A[M,K] @ B[K,N] (+bias)(+relu), A packed split fp16, B fp16.
// 8 warps (2m x 4n), warp tile 64m x 32n, BM=BN=128, BK=32 logical k, 3 stages.
// MODE 0: fp32 partial, no bias, k-split via blockIdx.z.
// MODE 1: fp32, bias + relu.
// MODE 2: fp32, bias, column guard col < Ntot (Ntot is both stride and valid N).
#define F_BM 128
#define F_BN 128
#define F_BK 32
#define F_ATILE (128*128)                 // bytes
#define F_BTILE (128*64)
#define F_STAGEB (F_ATILE + F_BTILE)      // 24576
#define F_SMEM (3*F_STAGEB)               // 73728

template<int MODE>
__global__ __launch_bounds__(256, 2)
void fp16_gemm_kernel(const __half* __restrict__ Ap,
                      const __half* __restrict__ Bh,
                      const float* __restrict__ bias,
                      float* __restrict__ outF,
                      int Klog, int KT, int Ntot, int Mtot)
{
  extern __shared__ __align__(128) unsigned char smraw[];
  const uint32_t sb = smem_u32(smraw);
  const int t = threadIdx.x;
  const int m0 = blockIdx.y * F_BM;
  const int n0 = blockIdx.x * F_BN;
  const int kz = blockIdx.z;
  const int c0 = kz * KT;
  const int strideA = 2*Klog;

  auto load_stage = [&](int s, int c){
    const uint32_t stb = sb + s*F_STAGEB;
    const int cc = c0 + c;
#pragma unroll
    for (int it = 0; it < 6; it++){
      int idx = t + it*256;
      if (idx < 1024){
        int r = idx>>3, u = idx&7;
        uint32_t dst = stb + r*128 + ((u ^ (r&7))<<4);
        cp_async16(dst, Ap + (size_t)(m0+r)*strideA + cc*64 + u*8);
      } else {
        int j = idx - 1024;
        int r = j>>2, u = j&3;
        uint32_t dst = stb + F_ATILE + r*64 + ((u ^ ((r>>1)&3))<<4);
        cp_async16(dst, Bh + (size_t)(n0+r)*Klog + cc*32 + u*8);
      }
    }
  };

  const int wid = t>>5, lane = t&31;
  const int wm = wid & 1, wn = wid >> 1;
  // A ldmatrix rows/units
  int ra[4];
#pragma unroll
  for (int i=0;i<4;i++) ra[i] = wm*64 + i*16 + (lane&7) + ((lane>>3)&1)*8;
  const int ua = lane>>4;                 // 0: hi unit, 1: lo unit
  // B ldmatrix rows/units: per ldm h covers n-octets 2h,2h+1 and kk pair
  int rb[2];
#pragma unroll
  for (int h=0;h<2;h++) rb[h] = wn*32 + h*16 + (lane&7) + ((lane>>3)&1)*8;
  const int ub = lane>>4;                 // 0: kk even, 1: kk odd

  float acc[4][4][4];
#pragma unroll
  for (int i=0;i<4;i++)
#pragma unroll
    for (int j=0;j<4;j++)
#pragma unroll
      for (int q=0;q<4;q++) acc[i][j][q]=0.f;

  load_stage(0, 0); CP_COMMIT();
  load_stage(1, 1); CP_COMMIT();

  for (int kt = 0; kt < KT; kt++){
    CP_WAIT(1);
    __syncthreads();
    if (kt + 2 < KT) load_stage((kt + 2) % 3, kt + 2);
    CP_COMMIT();

    const uint32_t stA = sb + (kt % 3)*F_STAGEB;
    const uint32_t stB = stA + F_ATILE;
#pragma unroll
    for (int p = 0; p < 2; p++){          // kk pairs
      uint32_t Br[2][4];
#pragma unroll
      for (int h=0;h<2;h++){
        int u = 2*p + ub;                 // b-chunk unit
        ldm_x4(Br[h], stB + rb[h]*64 + ((u ^ ((rb[h]>>1)&3))<<4));
      }
#pragma unroll
      for (int e = 0; e < 2; e++){        // kk = 2p+e
        int kk = 2*p + e;
        uint32_t Ar[4][4];
#pragma unroll
        for (int i=0;i<4;i++){
          int u = 2*kk + ua;              // a-chunk unit (hi/lo)
          ldm_x4(Ar[i], stA + ra[i]*128 + ((u ^ (ra[i]&7))<<4));
        }
#pragma unroll
        for (int i=0;i<4;i++)
#pragma unroll
          for (int j=0;j<4;j++){
            uint32_t b = Br[j>>1][(j&1) + 2*e];
            mma_fp16(acc[i][j], Ar[i][0], Ar[i][1], Ar[i][2], Ar[i][3], b, b);
          }
      }
    }
    __syncthreads();
  }

  // epilogue
  const int g = lane >> 2, tq = lane & 3;
#pragma unroll
  for (int i=0;i<4;i++){
#pragma unroll
    for (int j=0;j<4;j++){
      int row = m0 + wm*64 + i*16 + g;
      int col = n0 + wn*32 + j*8 + tq*2;
      if (MODE == 0){
        float* dst = outF + ((size_t)kz*Mtot + row)*Ntot + col;
        *(float2*)dst           = make_float2(acc[i][j][0], acc[i][j][1]);
        *(float2*)(dst + (size_t)8*Ntot) = make_float2(acc[i][j][2], acc[i][j][3]);
      } else if (MODE == 1){
        float b0 = bias[col], b1 = bias[col+1];
        float* dst = outF + (size_t)row*Ntot + col;
        *(float2*)dst           = make_float2(fmaxf(acc[i][j][0]+b0,0.f), fmaxf(acc[i][j][1]+b1,0.f));
        *(float2*)(dst + (size_t)8*Ntot) = make_float2(fmaxf(acc[i][j][2]+b0,0.f), fmaxf(acc[i][j][3]+b1,0.f));
      } else {
        if (col + 1 < Ntot){
          float b0 = bias[col], b1 = bias[col+1];
          float* dst = outF + (size_t)row*Ntot + col;
          *(float2*)dst           = make_float2(acc[i][j][0]+b0, acc[i][j][1]+b1);
          *(float2*)(dst + (size_t)8*Ntot) = make_float2(acc[i][j][2]+b0, acc[i][j][3]+b1);
        }
      }
    }
  }
}

// ---------------- reduce partials + bias + relu -> X1 packed fp16 -----------
__global__ __launch_bounds__(256)
void reduce_relu_kernel(const float* __restrict__ C, const float* __restrict__ b1,
                        __half* __restrict__ X1p)
{
  int total = BATCH*(H1/8);
  for (int i = blockIdx.x*blockDim.x + threadIdx.x; i < total;
       i += gridDim.x*blockDim.x) {
    int b = i / (H1/8), o = i % (H1/8);
    const float* c0 = C + (size_t)b*H1 + o*8;
    const float* c1 = c0 + (size_t)BATCH*H1;
    const float* bb = b1 + o*8;
    uint32_t u[8];
#pragma unroll
    for (int k=0;k<8;k+=2){
      float v0 = fmaxf(c0[k]   + c1[k]   + bb[k],   0.f);
      float v1 = fmaxf(c0[k+1] + c1[k+1] + bb[k+1], 0.f);
      __half h0 = __float2half(v0), h1 = __float2half(v1);
      u[k>>1]     = (uint32_t)__half_as_ushort(h0) | ((uint32_t)__half_as_ushort(h1)<<16);
      __half l0 = __float2half(v0 - __half2float(h0));
      __half l1 = __float2half(v1 - __half2float(h1));
      u[4+(k>>1)] = (uint32_t)__half_as_ushort(l0) | ((uint32_t)__half_as_ushort(l1)<<16);
    }
    __half* dst = X1p + (size_t)b*(2*H1) + o*16;
    *(uint4*)dst       = *(uint4*)u;
    *(uint4*)(dst + 8) = *(uint4*)(u+4);
  }
}

// ---------------- primary capsules + per-capsule LayerNorm -------------------
__global__ __launch_bounds__(256)
void primary_kernel(const float* __restrict__ X2, const float* __restrict__ Wp,
                    const float* __restrict__ bp, const float* __restrict__ lng,
                    const float* __restrict__ lnb, float* __restrict__ P)
{
  __shared__ __align__(16) float xs[16][H2];
  const int t  = threadIdx.x;
  const int b0 = blockIdx.x * 16;
  for (int idx=t; idx<16*(H2/4); idx+=256){
    int bb = idx/(H2/4);
    int c4 = (idx%(H2/4))*4;
    *(float4*)&xs[bb][c4] = *(const float4*)(X2 + (size_t)(b0+bb)*H2 + c4);
  }
  __syncthreads();
  const int n = t>>3, o = t&7;
  float bias = bp[t];
  float acc[16];
#pragma unroll
  for (int bb=0;bb<16;bb++) acc[bb]=bias;
  const float* wp = Wp + (size_t)n*(H2*PD) + o;
  for (int i0=0;i0<H2;i0+=4){
    float w0 = __ldg(wp + (size_t)(i0+0)*PD);
    float w1 = __ldg(wp + (size_t)(i0+1)*PD);
    float w2 = __ldg(wp + (size_t)(i0+2)*PD);
    float w3 = __ldg(wp + (size_t)(i0+3)*PD);
#pragma unroll
    for (int bb=0;bb<16;bb++){
      float4 x = *(const float4*)&xs[bb][i0];
      acc[bb] += x.x*w0 + x.y*w1 + x.z*w2 + x.w*w3;
    }
  }
  float g = lng[t], be = lnb[t];
#pragma unroll
  for (int bb=0;bb<16;bb++){
    float x = acc[bb];
    float s = x;
    s += __shfl_xor_sync(0xffffffffu, s, 1);
    s += __shfl_xor_sync(0xffffffffu, s, 2);
    s += __shfl_xor_sync(0xffffffffu, s, 4);
    float mu = s * 0.125f;
    float d  = x - mu;
    float q  = d*d;
    q += __shfl_xor_sync(0xffffffffu, q, 1);
    q += __shfl_xor_sync(0xffffffffu, q, 2);
    q += __shfl_xor_sync(0xffffffffu, q, 4);
    float var = q * 0.125f;
    P[(size_t)(b0+bb)*H2 + t] = d * rsqrtf(var + 1e-5f) * g + be;
  }
}

// ---------------- preds via fp16 mma: A=[p_hi|p_lo], B=[w|w] -----------------
#define PCHUNK 160
#define PCSTRIDE 168
#define PREDS_SMEM (JO*PD*2 + 128*16*2 + 128*PCSTRIDE*2)

__global__ __launch_bounds__(256)
void preds_mma_kernel(const float* __restrict__ P, const float* __restrict__ Wr,
                      __half* __restrict__ preds)
{
  extern __shared__ __align__(16) unsigned char smraw[];
  __half* wsh  = (__half*)smraw;                         // [JO][8] fp16
  __half* ash  = wsh + JO*PD;                            // [128][16]
  __half* cbuf = ash + 128*16;                           // [128][PCSTRIDE]
  const int n  = blockIdx.y;
  const int b0 = blockIdx.x * 128;
  const int t  = threadIdx.x;
  const int wid = t>>5, lane = t&31;

  const float* wsrc = Wr + (size_t)n*(JO*PD);
  for (int idx=t; idx<JO*PD; idx+=256) wsh[idx] = __float2half(wsrc[idx]);
  for (int idx=t; idx<128*8; idx+=256){
    int r = idx>>3, i = idx&7;
    float v = P[(size_t)(b0+r)*H2 + n*8 + i];
    __half h = __float2half(v);
    ash[r*16 + i]     = h;
    ash[r*16 + 8 + i] = __float2half(v - __half2float(h));
  }
  __syncthreads();

  const int g = lane>>2, tq = lane&3;
  const int ar0 = wid*16 + g;
  uint32_t a0 = *(const uint32_t*)&ash[ar0*16 + tq*2];
  uint32_t a1 = *(const uint32_t*)&ash[(ar0+8)*16 + tq*2];
  uint32_t a2 = *(const uint32_t*)&ash[ar0*16 + 8 + tq*2];
  uint32_t a3 = *(const uint32_t*)&ash[(ar0+8)*16 + 8 + tq*2];

  for (int chunk = 0; chunk < JO/PCHUNK; chunk++){
#pragma unroll 4
    for (int jt = 0; jt < PCHUNK/8; jt++){
      int jo0 = chunk*PCHUNK + jt*8;
      uint32_t b0v = *(const uint32_t*)&wsh[(jo0+g)*8 + tq*2];
      float c[4] = {0.f,0.f,0.f,0.f};
      mma_fp16(c, a0, a1, a2, a3, b0v, b0v);
      __half2 lo = __floats2half2_rn(c[0], c[1]);
      __half2 hi = __floats2half2_rn(c[2], c[3]);
      *(__half2*)&cbuf[(wid*16+g)*PCSTRIDE + jt*8 + tq*2]   = lo;
      *(__half2*)&cbuf[(wid*16+g+8)*PCSTRIDE + jt*8 + tq*2] = hi;
    }
    __syncthreads();
    for (int idx = t; idx < 128*(PCHUNK/8); idx += 256){
      int r = idx / (PCHUNK/8), q = idx % (PCHUNK/8);
      uint4 v = *(const uint4*)&cbuf[r*PCSTRIDE + q*8];
      *(uint4*)(preds + (size_t)(b0+r)*PREDROW + (size_t)n*JO + chunk*PCHUNK + q*8) = v;
    }
    __syncthreads();
  }
}

// ---------------- dynamic routing (3 iters) in SMEM, 512 threads -------------
#define SMEM_ROUTING (PREDROW*2 + (NP*NL + NP*NL + JO + 2*NP)*4)
#define RT_THREADS 512

__global__ void routing_kernel(const __half* __restrict__ preds,
                               __half* __restrict__ Vp)
{
  extern __shared__ __align__(16) unsigned char smraw[];
  __half* ps = (__half*)smraw;
  float* bl  = (float*)(smraw + (size_t)PREDROW*2);
  float* cs  = bl + NP*NL;
  float* vs  = cs + NP*NL;
  float* nmx = vs + JO;
  float* nnv = nmx + NP;
  const int b = blockIdx.x;
  const int t = threadIdx.x;

  {
    const uint4* src = (const uint4*)(preds + (size_t)b*PREDROW);
    uint4* dst = (uint4*)ps;
    for (int i=t; i<PREDROW/8; i+=RT_THREADS) dst[i] = src[i];
  }
  for (int i=t; i<NP*NL; i+=RT_THREADS) bl[i]=0.f;
  __syncthreads();

  const __half2* p2 = (const __half2*)ps;

  for (int jo2=t; jo2<JO/2; jo2+=RT_THREADS){
    float ax=0.f, ay=0.f;
#pragma unroll
    for (int n=0;n<NP;n++){
      float2 f = __half22float2(p2[n*(JO/2)+jo2]);
      ax += f.x; ay += f.y;
    }
    vs[jo2*2]   = ax*(1.0f/NL);
    vs[jo2*2+1] = ay*(1.0f/NL);
  }
  __syncthreads();

  for (int iter=0; iter<3; iter++){
    if (iter > 0){
      if (t<NP){
        float m=-1e30f;
        for (int j=0;j<NL;j++) m = fmaxf(m, bl[t*NL+j]);
        float ssum=0.f;
        for (int j=0;j<NL;j++) ssum += __expf(bl[t*NL+j]-m);
        nmx[t]=m; nnv[t]=1.f/ssum;
      }
      __syncthreads();
      for (int nj=t; nj<NP*NL; nj+=RT_THREADS){
        int n = nj/NL;
        cs[nj] = __expf(bl[nj]-nmx[n])*nnv[n];
      }
      __syncthreads();
      for (int jo2=t; jo2<JO/2; jo2+=RT_THREADS){
        int j = jo2>>3;
        float ax=0.f, ay=0.f;
#pragma unroll
        for (int n=0;n<NP;n++){
          float c = cs[n*NL+j];
          float2 f = __half22float2(p2[n*(JO/2)+jo2]);
          ax += c*f.x; ay += c*f.y;
        }
        vs[jo2*2]=ax; vs[jo2*2+1]=ay;
      }
      __syncthreads();
    }
    if (t<NL){
      float sq=0.f;
#pragma unroll
      for (int o=0;o<CD;o++){ float x=vs[t*CD+o]; sq+=x*x; }
      float scale = sq/(1.f+sq)*rsqrtf(sq+1e-8f);
#pragma unroll
      for (int o=0;o<CD;o++) vs[t*CD+o]*=scale;
    }
    __syncthreads();
    if (iter<2){
      for (int nj=t; nj<NP*NL; nj+=RT_THREADS){
        int n=nj/NL, j=nj%NL;
        float a=0.f;
#pragma unroll
        for (int o2=0;o2<CD/2;o2++){
          float2 f = __half22float2(p2[n*(JO/2) + j*(CD/2) + o2]);
          a += f.x*vs[j*CD+o2*2] + f.y*vs[j*CD+o2*2+1];
        }
        bl[nj] += a;
      }
      __syncthreads();
    }
  }
  // emit V as K-packed split fp16 (A operand of logits GEMM)
  for (int jo=t; jo<JO; jo+=RT_THREADS){
    float v = vs[jo];
    __half h = __float2half(v);
    int o = jo>>3, i = jo&7;
    Vp[(size_t)b*(2*JO) + o*16 + i]     = h;
    Vp[(size_t)b*(2*JO) + o*16 + 8 + i] = __float2half(v - __half2float(h));
  }
}

// ---------------- launch -----------------------------------------------------
extern "C" void kernel_launch(void* const* d_in, const int* in_sizes, int n_in,
                              void* d_out, int out_size)
{
  (void)in_sizes; (void)n_in; (void)out_size;
  const float* features = (const float*)d_in[0];
  const float* W1  = (const float*)d_in[1];
  const float* b1  = (const float*)d_in[2];
  const float* W2  = (const float*)d_in[3];
  const float* b2  = (const float*)d_in[4];
  const float* Wp  = (const float*)d_in[5];
  const float* bp  = (const float*)d_in[6];
  const float* lng = (const float*)d_in[7];
  const float* lnb = (const float*)d_in[8];
  const float* Wr  = (const float*)d_in[9];
  const float* Wc  = (const float*)d_in[10];
  const float* bc  = (const float*)d_in[11];
  float* out = (float*)d_out;

  __half *A1p,*B1h,*B2h,*Wch,*X1p,*PR,*Vp;
  float *Cp,*X2,*P;
  cudaGetSymbolAddress((void**)&A1p, g_A1p);
  cudaGetSymbolAddress((void**)&B1h, g_B1h);
  cudaGetSymbolAddress((void**)&B2h, g_B2h);
  cudaGetSymbolAddress((void**)&Wch, g_Wch);
  cudaGetSymbolAddress((void**)&Cp,  g_Cpart);
  cudaGetSymbolAddress((void**)&X1p, g_X1p);
  cudaGetSymbolAddress((void**)&X2,  g_X2);
  cudaGetSymbolAddress((void**)&P,   g_P);
  cudaGetSymbolAddress((void**)&PR,  g_preds);
  cudaGetSymbolAddress((void**)&Vp,  g_Vp);

  // conversions
  convA_f16_kernel<<<4096, 256>>>(features, A1p);
  convW_f16_kernel<<<dim3(KPAD1/32, H1/32), dim3(32,8)>>>(W1, B1h, IN_DIM, H1, KPAD1);
  convW_f16_kernel<<<dim3(H1/32, H2/32),    dim3(32,8)>>>(W2, B2h, H1, H2, H1);
  convW_f16_kernel<<<dim3(JO/32, NLPAD/32), dim3(32,8)>>>(Wc, Wch, JO, NL, JO);

  // GEMM1 (k-split 2) + reduce -> X1 packed
  cudaFuncSetAttribute(fp16_gemm_kernel<0>, cudaFuncAttributeMaxDynamicSharedMemorySize, F_SMEM);
  fp16_gemm_kernel<0><<<dim3(H1/F_BN, BATCH/F_BM, 2), 256, F_SMEM>>>(
      A1p, B1h, nullptr, Cp, KPAD1, (KPAD1/F_BK)/2, H1, BATCH);
  reduce_relu_kernel<<<1024, 256>>>(Cp, b1, X1p);

  // GEMM2: X2 = relu(X1 @ W2 + b2)
  cudaFuncSetAttribute(fp16_gemm_kernel<1>, cudaFuncAttributeMaxDynamicSharedMemorySize, F_SMEM);
  fp16_gemm_kernel<1><<<dim3(H2/F_BN, BATCH/F_BM, 1), 256, F_SMEM>>>(
      X1p, B2h, b2, X2, H1, H1/F_BK, H2, BATCH);

  // primary capsules + LN
  primary_kernel<<<BATCH/16, 256>>>(X2, Wp, bp, lng, lnb, P);

  // preds (fp16 mma)
  cudaFuncSetAttribute(preds_mma_kernel, cudaFuncAttributeMaxDynamicSharedMemorySize, PREDS_SMEM);
  preds_mma_kernel<<<dim3(BATCH/128, NP), 256, PREDS_SMEM>>>(P, Wr, PR);

  // routing -> V packed fp16
  cudaFuncSetAttribute(routing_kernel, cudaFuncAttributeMaxDynamicSharedMemorySize, SMEM_ROUTING);
  routing_kernel<<<BATCH, RT_THREADS, SMEM_ROUTING>>>(PR, Vp);

  // logits = V @ Wc + bc  (B zero-padded to 128 rows; col guard at N=100)
  cudaFuncSetAttribute(fp16_gemm_kernel<2>, cudaFuncAttributeMaxDynamicSharedMemorySize, F_SMEM);
  fp16_gemm_kernel<2><<<dim3(1, BATCH/F_BM, 1), 256, F_SMEM>>>(
      Vp, Wch, bc, out, JO, JO/F_BK, NL, BATCH);
}

// round 6
// speedup vs baseline: 1.8389x; 1.0218x over previous
#include <cuda_runtime.h>
#include <cuda_fp16.h>
#include <cstdint>
#include <cstddef>

#define BATCH 4096
#define IN_DIM 10000
#define H1 512
#define H2 256
#define NP 32
#define PD 8
#define NL 100
#define CD 16
#define JO (NL*CD)       // 1600
#define PREDROW (NP*JO)  // 51200
#define KPAD1 10240
#define NLPAD 128

// ---------------- helpers ----------------------------------------------------
__device__ __forceinline__ uint32_t smem_u32(const void* p) {
  uint32_t a;
  asm("{ .reg .u64 t; cvta.to.shared.u64 t, %1; cvt.u32.u64 %0, t; }" : "=r"(a) : "l"(p));
  return a;
}
__device__ __forceinline__ void cp_async16(uint32_t smem, const void* g) {
  asm volatile("cp.async.cg.shared.global [%0], [%1], 16;" :: "r"(smem), "l"(g));
}
#define CP_COMMIT() asm volatile("cp.async.commit_group;" ::: "memory")
#define CP_WAIT(N)  asm volatile("cp.async.wait_group %0;" :: "n"(N) : "memory")

__device__ __forceinline__ void ldm_x4(uint32_t* r, uint32_t addr) {
  asm volatile("ldmatrix.sync.aligned.m8n8.x4.shared.b16 {%0,%1,%2,%3}, [%4];"
               : "=r"(r[0]), "=r"(r[1]), "=r"(r[2]), "=r"(r[3]) : "r"(addr));
}
__device__ __forceinline__ void mma_fp16(float* d, uint32_t a0, uint32_t a1,
                                         uint32_t a2, uint32_t a3,
                                         uint32_t b0, uint32_t b1) {
  asm volatile("mma.sync.aligned.m16n8k16.row.col.f32.f16.f16.f32 "
               "{%0,%1,%2,%3}, {%4,%5,%6,%7}, {%8,%9}, {%0,%1,%2,%3};"
               : "+f"(d[0]), "+f"(d[1]), "+f"(d[2]), "+f"(d[3])
               : "r"(a0), "r"(a1), "r"(a2), "r"(a3), "r"(b0), "r"(b1));
}

// ---------------- scratch ----------------------------------------------------
// A operands are "K-packed split fp16": row length 2*K halves; logical k-octet o
// occupies halves [16o..16o+7] = hi, [16o+8..16o+15] = lo.
__device__ __half g_A1p[(size_t)BATCH*2*KPAD1];   // features packed
__device__ __half g_B1h[(size_t)H1*KPAD1];        // W1^T fp16
__device__ __half g_B2h[(size_t)H2*H1];           // W2^T fp16
__device__ __half g_Wch[(size_t)NLPAD*JO];        // Wc^T fp16, zero-padded rows
__device__ float  g_Cpart[(size_t)2*BATCH*H1];    // GEMM1 k-split partials
__device__ __half g_X1p[(size_t)BATCH*2*H1];      // X1 packed
__device__ float  g_X2[(size_t)BATCH*H2];
__device__ float  g_P [(size_t)BATCH*H2];
__device__ __half g_preds[(size_t)BATCH*PREDROW];
__device__ __half g_Vp[(size_t)BATCH*2*JO];       // V packed

// ---------------- conversions ------------------------------------------------
__global__ __launch_bounds__(256)
void convA_f16_kernel(const float* __restrict__ F, __half* __restrict__ Ap)
{
  int total = BATCH*(KPAD1/8);
  for (int i = blockIdx.x*blockDim.x + threadIdx.x; i < total;
       i += gridDim.x*blockDim.x) {
    int row = i / (KPAD1/8), o = i % (KPAD1/8);
    uint32_t u[8];
    if (o*8 < IN_DIM){
      const float* src = F + (size_t)row*IN_DIM + o*8;
#pragma unroll
      for (int k=0;k<8;k+=2){
        float v0 = src[k], v1 = src[k+1];
        __half h0 = __float2half(v0), h1 = __float2half(v1);
        u[k>>1]     = (uint32_t)__half_as_ushort(h0) | ((uint32_t)__half_as_ushort(h1)<<16);
        __half l0 = __float2half(v0 - __half2float(h0));
        __half l1 = __float2half(v1 - __half2float(h1));
        u[4+(k>>1)] = (uint32_t)__half_as_ushort(l0) | ((uint32_t)__half_as_ushort(l1)<<16);
      }
    } else {
#pragma unroll
      for (int k=0;k<8;k++) u[k]=0;
    }
    __half* dst = Ap + (size_t)row*(2*KPAD1) + o*16;
    *(uint4*)dst       = *(uint4*)u;
    *(uint4*)(dst + 8) = *(uint4*)(u+4);
  }
}

__global__ __launch_bounds__(256)
void convW_f16_kernel(const float* __restrict__ W, __half* __restrict__ B,
                      int K, int N, int KP)
{
  __shared__ float tile[32][33];
  int kb = blockIdx.x*32, nb = blockIdx.y*32;
  int tx = threadIdx.x, ty = threadIdx.y;   // block (32,8)
#pragma unroll
  for (int i=0;i<32;i+=8){
    int k = kb+ty+i, col = nb+tx;
    tile[ty+i][tx] = (k < K && col < N) ? W[(size_t)k*N + col] : 0.f;
  }
  __syncthreads();
#pragma unroll
  for (int i=0;i<32;i+=8){
    int n = nb+ty+i, k = kb+tx;
    B[(size_t)n*KP + k] = __float2half(tile[tx][ty+i]);
  }
}

// ---------------- fp16 K-packed GEMM ----------------------------------------
#define F_BM 128
#define F_BN 128
#define F_BK 32
#define F_ATILE (128*128)
#define F_BTILE (128*64)
#define F_STAGEB (F_ATILE + F_BTILE)      // 24576
#define F_SMEM (3*F_STAGEB)               // 73728

template<int MODE>
__global__ __launch_bounds__(256, 2)
void fp16_gemm_kernel(const __half* __restrict__ Ap,
                      const __half* __restrict__ Bh,
                      const float* __restrict__ bias,
                      float* __restrict__ outF,
                      int Klog, int KT, int Ntot, int Mtot)
{
  extern __shared__ __align__(128) unsigned char smraw[];
  const uint32_t sb = smem_u32(smraw);
  const int t = threadIdx.x;
  const int m0 = blockIdx.y * F_BM;
  const int n0 = blockIdx.x * F_BN;
  const int kz = blockIdx.z;
  const int c0 = kz * KT;
  const int strideA = 2*Klog;

  auto load_stage = [&](int s, int c){
    const uint32_t stb = sb + s*F_STAGEB;
    const int cc = c0 + c;
#pragma unroll
    for (int it = 0; it < 6; it++){
      int idx = t + it*256;
      if (idx < 1024){
        int r = idx>>3, u = idx&7;
        uint32_t dst = stb + r*128 + ((u ^ (r&7))<<4);
        cp_async16(dst, Ap + (size_t)(m0+r)*strideA + cc*64 + u*8);
      } else {
        int j = idx - 1024;
        int r = j>>2, u = j&3;
        uint32_t dst = stb + F_ATILE + r*64 + ((u ^ ((r>>1)&3))<<4);
        cp_async16(dst, Bh + (size_t)(n0+r)*Klog + cc*32 + u*8);
      }
    }
  };

  const int wid = t>>5, lane = t&31;
  const int wm = wid & 1, wn = wid >> 1;
  int ra[4];
#pragma unroll
  for (int i=0;i<4;i++) ra[i] = wm*64 + i*16 + (lane&7) + ((lane>>3)&1)*8;
  const int ua = lane>>4;
  int rb[2];
#pragma unroll
  for (int h=0;h<2;h++) rb[h] = wn*32 + h*16 + (lane&7) + ((lane>>3)&1)*8;
  const int ub = lane>>4;

  float acc[4][4][4];
#pragma unroll
  for (int i=0;i<4;i++)
#pragma unroll
    for (int j=0;j<4;j++)
#pragma unroll
      for (int q=0;q<4;q++) acc[i][j][q]=0.f;

  load_stage(0, 0); CP_COMMIT();
  load_stage(1, 1); CP_COMMIT();

  for (int kt = 0; kt < KT; kt++){
    CP_WAIT(1);
    __syncthreads();
    if (kt + 2 < KT) load_stage((kt + 2) % 3, kt + 2);
    CP_COMMIT();

    const uint32_t stA = sb + (kt % 3)*F_STAGEB;
    const uint32_t stB = stA + F_ATILE;
#pragma unroll
    for (int p = 0; p < 2; p++){
      uint32_t Br[2][4];
#pragma unroll
      for (int h=0;h<2;h++){
        int u = 2*p + ub;
        ldm_x4(Br[h], stB + rb[h]*64 + ((u ^ ((rb[h]>>1)&3))<<4));
      }
#pragma unroll
      for (int e = 0; e < 2; e++){
        int kk = 2*p + e;
        uint32_t Ar[4][4];
#pragma unroll
        for (int i=0;i<4;i++){
          int u = 2*kk + ua;
          ldm_x4(Ar[i], stA + ra[i]*128 + ((u ^ (ra[i]&7))<<4));
        }
#pragma unroll
        for (int i=0;i<4;i++)
#pragma unroll
          for (int j=0;j<4;j++){
            uint32_t b = Br[j>>1][(j&1) + 2*e];
            mma_fp16(acc[i][j], Ar[i][0], Ar[i][1], Ar[i][2], Ar[i][3], b, b);
          }
      }
    }
    __syncthreads();
  }

  const int g = lane >> 2, tq = lane & 3;
#pragma unroll
  for (int i=0;i<4;i++){
#pragma unroll
    for (int j=0;j<4;j++){
      int row = m0 + wm*64 + i*16 + g;
      int col = n0 + wn*32 + j*8 + tq*2;
      if (MODE == 0){
        float* dst = outF + ((size_t)kz*Mtot + row)*Ntot + col;
        *(float2*)dst           = make_float2(acc[i][j][0], acc[i][j][1]);
        *(float2*)(dst + (size_t)8*Ntot) = make_float2(acc[i][j][2], acc[i][j][3]);
      } else if (MODE == 1){
        float b0 = bias[col], b1 = bias[col+1];
        float* dst = outF + (size_t)row*Ntot + col;
        *(float2*)dst           = make_float2(fmaxf(acc[i][j][0]+b0,0.f), fmaxf(acc[i][j][1]+b1,0.f));
        *(float2*)(dst + (size_t)8*Ntot) = make_float2(fmaxf(acc[i][j][2]+b0,0.f), fmaxf(acc[i][j][3]+b1,0.f));
      } else {
        if (col + 1 < Ntot){
          float b0 = bias[col], b1 = bias[col+1];
          float* dst = outF + (size_t)row*Ntot + col;
          *(float2*)dst           = make_float2(acc[i][j][0]+b0, acc[i][j][1]+b1);
          *(float2*)(dst + (size_t)8*Ntot) = make_float2(acc[i][j][2]+b0, acc[i][j][3]+b1);
        }
      }
    }
  }
}

// ---------------- reduce partials + bias + relu -> X1 packed fp16 -----------
__global__ __launch_bounds__(256)
void reduce_relu_kernel(const float* __restrict__ C, const float* __restrict__ b1,
                        __half* __restrict__ X1p)
{
  int total = BATCH*(H1/8);
  for (int i = blockIdx.x*blockDim.x + threadIdx.x; i < total;
       i += gridDim.x*blockDim.x) {
    int b = i / (H1/8), o = i % (H1/8);
    const float* c0 = C + (size_t)b*H1 + o*8;
    const float* c1 = c0 + (size_t)BATCH*H1;
    const float* bb = b1 + o*8;
    uint32_t u[8];
#pragma unroll
    for (int k=0;k<8;k+=2){
      float v0 = fmaxf(c0[k]   + c1[k]   + bb[k],   0.f);
      float v1 = fmaxf(c0[k+1] + c1[k+1] + bb[k+1], 0.f);
      __half h0 = __float2half(v0), h1 = __float2half(v1);
      u[k>>1]     = (uint32_t)__half_as_ushort(h0) | ((uint32_t)__half_as_ushort(h1)<<16);
      __half l0 = __float2half(v0 - __half2float(h0));
      __half l1 = __float2half(v1 - __half2float(h1));
      u[4+(k>>1)] = (uint32_t)__half_as_ushort(l0) | ((uint32_t)__half_as_ushort(l1)<<16);
    }
    __half* dst = X1p + (size_t)b*(2*H1) + o*16;
    *(uint4*)dst       = *(uint4*)u;
    *(uint4*)(dst + 8) = *(uint4*)(u+4);
  }
}

// ---------------- primary capsules + per-capsule LayerNorm -------------------
__global__ __launch_bounds__(256)
void primary_kernel(const float* __restrict__ X2, const float* __restrict__ Wp,
                    const float* __restrict__ bp, const float* __restrict__ lng,
                    const float* __restrict__ lnb, float* __restrict__ P)
{
  __shared__ __align__(16) float xs[16][H2];
  const int t  = threadIdx.x;
  const int b0 = blockIdx.x * 16;
  for (int idx=t; idx<16*(H2/4); idx+=256){
    int bb = idx/(H2/4);
    int c4 = (idx%(H2/4))*4;
    *(float4*)&xs[bb][c4] = *(const float4*)(X2 + (size_t)(b0+bb)*H2 + c4);
  }
  __syncthreads();
  const int n = t>>3, o = t&7;
  float bias = bp[t];
  float acc[16];
#pragma unroll
  for (int bb=0;bb<16;bb++) acc[bb]=bias;
  const float* wp = Wp + (size_t)n*(H2*PD) + o;
  for (int i0=0;i0<H2;i0+=4){
    float w0 = __ldg(wp + (size_t)(i0+0)*PD);
    float w1 = __ldg(wp + (size_t)(i0+1)*PD);
    float w2 = __ldg(wp + (size_t)(i0+2)*PD);
    float w3 = __ldg(wp + (size_t)(i0+3)*PD);
#pragma unroll
    for (int bb=0;bb<16;bb++){
      float4 x = *(const float4*)&xs[bb][i0];
      acc[bb] += x.x*w0 + x.y*w1 + x.z*w2 + x.w*w3;
    }
  }
  float g = lng[t], be = lnb[t];
#pragma unroll
  for (int bb=0;bb<16;bb++){
    float x = acc[bb];
    float s = x;
    s += __shfl_xor_sync(0xffffffffu, s, 1);
    s += __shfl_xor_sync(0xffffffffu, s, 2);
    s += __shfl_xor_sync(0xffffffffu, s, 4);
    float mu = s * 0.125f;
    float d  = x - mu;
    float q  = d*d;
    q += __shfl_xor_sync(0xffffffffu, q, 1);
    q += __shfl_xor_sync(0xffffffffu, q, 2);
    q += __shfl_xor_sync(0xffffffffu, q, 4);
    float var = q * 0.125f;
    P[(size_t)(b0+bb)*H2 + t] = d * rsqrtf(var + 1e-5f) * g + be;
  }
}

// ---------------- preds via fp16 mma, direct __half2 stores ------------------
#define PREDS_SMEM (JO*PD*2 + 128*16*2)   // 25600 + 4096 = 29696

__global__ __launch_bounds__(256)
void preds_mma_kernel(const float* __restrict__ P, const float* __restrict__ Wr,
                      __half* __restrict__ preds)
{
  extern __shared__ __align__(16) unsigned char smraw[];
  __half* wsh  = (__half*)smraw;                         // [JO][8] fp16
  __half* ash  = wsh + JO*PD;                            // [128][16]
  const int n  = blockIdx.y;
  const int b0 = blockIdx.x * 128;
  const int t  = threadIdx.x;
  const int wid = t>>5, lane = t&31;

  const float* wsrc = Wr + (size_t)n*(JO*PD);
  for (int idx=t; idx<JO*PD; idx+=256) wsh[idx] = __float2half(wsrc[idx]);
  for (int idx=t; idx<128*8; idx+=256){
    int r = idx>>3, i = idx&7;
    float v = P[(size_t)(b0+r)*H2 + n*8 + i];
    __half h = __float2half(v);
    ash[r*16 + i]     = h;
    ash[r*16 + 8 + i] = __float2half(v - __half2float(h));
  }
  __syncthreads();

  const int g = lane>>2, tq = lane&3;
  const int ar0 = wid*16 + g;
  uint32_t a0 = *(const uint32_t*)&ash[ar0*16 + tq*2];
  uint32_t a1 = *(const uint32_t*)&ash[(ar0+8)*16 + tq*2];
  uint32_t a2 = *(const uint32_t*)&ash[ar0*16 + 8 + tq*2];
  uint32_t a3 = *(const uint32_t*)&ash[(ar0+8)*16 + 8 + tq*2];

  __half* out0 = preds + (size_t)(b0 + wid*16 + g)*PREDROW + (size_t)n*JO + tq*2;
  __half* out1 = out0 + (size_t)8*PREDROW;

#pragma unroll 4
  for (int jt = 0; jt < JO/8; jt++){
    uint32_t b0v = *(const uint32_t*)&wsh[(jt*8+g)*8 + tq*2];
    float c[4] = {0.f,0.f,0.f,0.f};
    mma_fp16(c, a0, a1, a2, a3, b0v, b0v);
    *(__half2*)(out0 + jt*8) = __floats2half2_rn(c[0], c[1]);
    *(__half2*)(out1 + jt*8) = __floats2half2_rn(c[2], c[3]);
  }
}

// ---------------- dynamic routing: register-resident preds, 800 threads ------
#define RT_T 800

__global__ __launch_bounds__(RT_T, 1)
void routing_kernel(const __half* __restrict__ preds, __half* __restrict__ Vp)
{
  __shared__ float bl[NP*NL];      // 12.8 KB
  __shared__ float cs[NP*NL];      // 12.8 KB
  __shared__ float pmax[NP*4];
  __shared__ float psum[NP*4];
  const int b = blockIdx.x;
  const int t = threadIdx.x;       // 0..799
  const int j = t >> 3;            // label 0..99
  const int g8 = t & 7;            // position within 8-thread label group

  // each thread owns jo-pair (2t, 2t+1) for all 32 capsules
  __half2 p2[NP];
  const __half2* src = (const __half2*)(preds + (size_t)b*PREDROW);
#pragma unroll
  for (int n=0;n<NP;n++) p2[n] = src[(size_t)n*(JO/2) + t];

  float2 v;
  {
    float ax=0.f, ay=0.f;
#pragma unroll
    for (int n=0;n<NP;n++){ float2 f = __half22float2(p2[n]); ax += f.x; ay += f.y; }
    v.x = ax*(1.0f/NL); v.y = ay*(1.0f/NL);
  }

  for (int iter=0; ; iter++){
    // squash: reduce |s|^2 over the 8 threads (16 o-values) of this label
    float sq = v.x*v.x + v.y*v.y;
    sq += __shfl_xor_sync(0xffffffffu, sq, 1);
    sq += __shfl_xor_sync(0xffffffffu, sq, 2);
    sq += __shfl_xor_sync(0xffffffffu, sq, 4);
    float scale = sq/(1.f+sq)*rsqrtf(sq+1e-8f);
    v.x *= scale; v.y *= scale;
    if (iter == 2) break;

    // agreement -> bl[n][j]
#pragma unroll
    for (int n=0;n<NP;n++){
      float2 f = __half22float2(p2[n]);
      float a = f.x*v.x + f.y*v.y;
      a += __shfl_xor_sync(0xffffffffu, a, 1);
      a += __shfl_xor_sync(0xffffffffu, a, 2);
      a += __shfl_xor_sync(0xffffffffu, a, 4);
      if ((n & 7) == g8){
        if (iter == 0) bl[n*NL + j] = a;
        else           bl[n*NL + j] += a;
      }
    }
    __syncthreads();

    // softmax over j per capsule n (2-stage: 128 threads, quarters of 25)
    if (t < NP*4){
      int n = t>>2, q = t&3;
      float m = -1e30f;
      for (int jj=q*25; jj<q*25+25; jj++) m = fmaxf(m, bl[n*NL+jj]);
      pmax[t] = m;
    }
    __syncthreads();
    if (t < NP*4){
      int n = t>>2, q = t&3;
      float m = fmaxf(fmaxf(pmax[n*4],pmax[n*4+1]),fmaxf(pmax[n*4+2],pmax[n*4+3]));
      float s = 0.f;
      for (int jj=q*25; jj<q*25+25; jj++) s += __expf(bl[n*NL+jj]-m);
      psum[t] = s;
    }
    __syncthreads();
    for (int nj=t; nj<NP*NL; nj+=RT_T){
      int n = nj/NL;
      float m = fmaxf(fmaxf(pmax[n*4],pmax[n*4+1]),fmaxf(pmax[n*4+2],pmax[n*4+3]));
      float ssum = psum[n*4]+psum[n*4+1]+psum[n*4+2]+psum[n*4+3];
      cs[nj] = __expf(bl[nj]-m)/ssum;
    }
    __syncthreads();

    // s[j,o] = sum_n c[n,j] * p[n,j,o]  (local registers + c broadcast)
    float ax=0.f, ay=0.f;
#pragma unroll
    for (int n=0;n<NP;n++){
      float c = cs[n*NL + j];
      float2 f = __half22float2(p2[n]);
      ax += c*f.x; ay += c*f.y;
    }
    v.x = ax; v.y = ay;
  }

  // emit V as K-packed split fp16 (A operand of logits GEMM)
  __half h0 = __float2half(v.x), h1 = __float2half(v.y);
  __half l0 = __float2half(v.x - __half2float(h0));
  __half l1 = __float2half(v.y - __half2float(h1));
  __half* dst = Vp + (size_t)b*(2*JO) + (t>>2)*16 + ((2*t)&7);
  *(__half2*)dst     = __halves2half2(h0, h1);
  *(__half2*)(dst+8) = __halves2half2(l0, l1);
}

// ---------------- launch -----------------------------------------------------
extern "C" void kernel_launch(void* const* d_in, const int* in_sizes, int n_in,
                              void* d_out, int out_size)
{
  (void)in_sizes; (void)n_in; (void)out_size;
  const float* features = (const float*)d_in[0];
  const float* W1  = (const float*)d_in[1];
  const float* b1  = (const float*)d_in[2];
  const float* W2  = (const float*)d_in[3];
  const float* b2  = (const float*)d_in[4];
  const float* Wp  = (const float*)d_in[5];
  const float* bp  = (const float*)d_in[6];
  const float* lng = (const float*)d_in[7];
  const float* lnb = (const float*)d_in[8];
  const float* Wr  = (const float*)d_in[9];
  const float* Wc  = (const float*)d_in[10];
  const float* bc  = (const float*)d_in[11];
  float* out = (float*)d_out;

  __half *A1p,*B1h,*B2h,*Wch,*X1p,*PR,*Vp;
  float *Cp,*X2,*P;
  cudaGetSymbolAddress((void**)&A1p, g_A1p);
  cudaGetSymbolAddress((void**)&B1h, g_B1h);
  cudaGetSymbolAddress((void**)&B2h, g_B2h);
  cudaGetSymbolAddress((void**)&Wch, g_Wch);
  cudaGetSymbolAddress((void**)&Cp,  g_Cpart);
  cudaGetSymbolAddress((void**)&X1p, g_X1p);
  cudaGetSymbolAddress((void**)&X2,  g_X2);
  cudaGetSymbolAddress((void**)&P,   g_P);
  cudaGetSymbolAddress((void**)&PR,  g_preds);
  cudaGetSymbolAddress((void**)&Vp,  g_Vp);

  // launches ordered so gemm1 is the 4th (profiled) launch
  convA_f16_kernel<<<4096, 256>>>(features, A1p);                                   // 1
  convW_f16_kernel<<<dim3(KPAD1/32, H1/32), dim3(32,8)>>>(W1, B1h, IN_DIM, H1, KPAD1); // 2
  convW_f16_kernel<<<dim3(H1/32, H2/32),    dim3(32,8)>>>(W2, B2h, H1, H2, H1);     // 3

  cudaFuncSetAttribute(fp16_gemm_kernel<0>, cudaFuncAttributeMaxDynamicSharedMemorySize, F_SMEM);
  fp16_gemm_kernel<0><<<dim3(H1/F_BN, BATCH/F_BM, 2), 256, F_SMEM>>>(               // 4
      A1p, B1h, nullptr, Cp, KPAD1, (KPAD1/F_BK)/2, H1, BATCH);

  convW_f16_kernel<<<dim3(JO/32, NLPAD/32), dim3(32,8)>>>(Wc, Wch, JO, NL, JO);     // 5
  reduce_relu_kernel<<<1024, 256>>>(Cp, b1, X1p);                                   // 6

  cudaFuncSetAttribute(fp16_gemm_kernel<1>, cudaFuncAttributeMaxDynamicSharedMemorySize, F_SMEM);
  fp16_gemm_kernel<1><<<dim3(H2/F_BN, BATCH/F_BM, 1), 256, F_SMEM>>>(               // 7
      X1p, B2h, b2, X2, H1, H1/F_BK, H2, BATCH);

  primary_kernel<<<BATCH/16, 256>>>(X2, Wp, bp, lng, lnb, P);                       // 8

  cudaFuncSetAttribute(preds_mma_kernel, cudaFuncAttributeMaxDynamicSharedMemorySize, PREDS_SMEM);
  preds_mma_kernel<<<dim3(BATCH/128, NP), 256, PREDS_SMEM>>>(P, Wr, PR);            // 9

  routing_kernel<<<BATCH, RT_T>>>(PR, Vp);                                          // 10

  cudaFuncSetAttribute(fp16_gemm_kernel<2>, cudaFuncAttributeMaxDynamicSharedMemorySize, F_SMEM);
  fp16_gemm_kernel<2><<<dim3(1, BATCH/F_BM, 1), 256, F_SMEM>>>(                     // 11
      Vp, Wch, bc, out, JO, JO/F_BK, NL, BATCH);
}

// round 7
// speedup vs baseline: 1.9552x; 1.0633x over previous
#include <cuda_runtime.h>
#include <cuda_fp16.h>
#include <cstdint>
#include <cstddef>

#define BATCH 4096
#define IN_DIM 10000
#define H1 512
#define H2 256
#define NP 32
#define PD 8
#define NL 100
#define CD 16
#define JO (NL*CD)       // 1600
#define PREDROW (NP*JO)  // 51200
#define KPAD1 10240
#define NLPAD 128
#define BCHUNK 1024      // preds/routing L2 chunk
#define LSPLIT 5         // logits k-split

// ---------------- helpers ----------------------------------------------------
__device__ __forceinline__ uint32_t smem_u32(const void* p) {
  uint32_t a;
  asm("{ .reg .u64 t; cvta.to.shared.u64 t, %1; cvt.u32.u64 %0, t; }" : "=r"(a) : "l"(p));
  return a;
}
__device__ __forceinline__ void cp_async16(uint32_t smem, const void* g) {
  asm volatile("cp.async.cg.shared.global [%0], [%1], 16;" :: "r"(smem), "l"(g));
}
#define CP_COMMIT() asm volatile("cp.async.commit_group;" ::: "memory")
#define CP_WAIT(N)  asm volatile("cp.async.wait_group %0;" :: "n"(N) : "memory")

__device__ __forceinline__ void ldm_x4(uint32_t* r, uint32_t addr) {
  asm volatile("ldmatrix.sync.aligned.m8n8.x4.shared.b16 {%0,%1,%2,%3}, [%4];"
               : "=r"(r[0]), "=r"(r[1]), "=r"(r[2]), "=r"(r[3]) : "r"(addr));
}
__device__ __forceinline__ void mma_fp16(float* d, uint32_t a0, uint32_t a1,
                                         uint32_t a2, uint32_t a3,
                                         uint32_t b0, uint32_t b1) {
  asm volatile("mma.sync.aligned.m16n8k16.row.col.f32.f16.f16.f32 "
               "{%0,%1,%2,%3}, {%4,%5,%6,%7}, {%8,%9}, {%0,%1,%2,%3};"
               : "+f"(d[0]), "+f"(d[1]), "+f"(d[2]), "+f"(d[3])
               : "r"(a0), "r"(a1), "r"(a2), "r"(a3), "r"(b0), "r"(b1));
}

// ---------------- scratch ----------------------------------------------------
__device__ __half g_A1p[(size_t)BATCH*2*KPAD1];   // features packed split fp16
__device__ __half g_B1h[(size_t)H1*KPAD1];        // W1^T fp16
__device__ __half g_B2h[(size_t)H2*H1];           // W2^T fp16
__device__ __half g_Wch[(size_t)NLPAD*JO];        // Wc^T fp16 (zero-padded rows)
__device__ float  g_Cpart[(size_t)LSPLIT*BATCH*NLPAD > (size_t)2*BATCH*H1
                          ? (size_t)LSPLIT*BATCH*NLPAD : (size_t)2*BATCH*H1];
__device__ __half g_X1p[(size_t)BATCH*2*H1];      // X1 packed
__device__ float  g_X2[(size_t)BATCH*H2];
__device__ float  g_P [(size_t)BATCH*H2];
__device__ __half g_preds[(size_t)BATCH*PREDROW];
__device__ __half g_Vp[(size_t)BATCH*2*JO];       // V packed

// ---------------- conversions ------------------------------------------------
__global__ __launch_bounds__(256)
void convA_f16_kernel(const float* __restrict__ F, __half* __restrict__ Ap)
{
  int total = BATCH*(KPAD1/8);
  for (int i = blockIdx.x*blockDim.x + threadIdx.x; i < total;
       i += gridDim.x*blockDim.x) {
    int row = i / (KPAD1/8), o = i % (KPAD1/8);
    uint32_t u[8];
    if (o*8 < IN_DIM){
      const float* src = F + (size_t)row*IN_DIM + o*8;
#pragma unroll
      for (int k=0;k<8;k+=2){
        float v0 = src[k], v1 = src[k+1];
        __half h0 = __float2half(v0), h1 = __float2half(v1);
        u[k>>1]     = (uint32_t)__half_as_ushort(h0) | ((uint32_t)__half_as_ushort(h1)<<16);
        __half l0 = __float2half(v0 - __half2float(h0));
        __half l1 = __float2half(v1 - __half2float(h1));
        u[4+(k>>1)] = (uint32_t)__half_as_ushort(l0) | ((uint32_t)__half_as_ushort(l1)<<16);
      }
    } else {
#pragma unroll
      for (int k=0;k<8;k++) u[k]=0;
    }
    __half* dst = Ap + (size_t)row*(2*KPAD1) + o*16;
    *(uint4*)dst       = *(uint4*)u;
    *(uint4*)(dst + 8) = *(uint4*)(u+4);
  }
}

__global__ __launch_bounds__(256)
void convW_f16_kernel(const float* __restrict__ W, __half* __restrict__ B,
                      int K, int N, int KP)
{
  __shared__ float tile[32][33];
  int kb = blockIdx.x*32, nb = blockIdx.y*32;
  int tx = threadIdx.x, ty = threadIdx.y;   // block (32,8)
#pragma unroll
  for (int i=0;i<32;i+=8){
    int k = kb+ty+i, col = nb+tx;
    tile[ty+i][tx] = (k < K && col < N) ? W[(size_t)k*N + col] : 0.f;
  }
  __syncthreads();
#pragma unroll
  for (int i=0;i<32;i+=8){
    int n = nb+ty+i, k = kb+tx;
    B[(size_t)n*KP + k] = __float2half(tile[tx][ty+i]);
  }
}

// ---------------- fp16 K-packed GEMM, 4-stage single-sync pipeline ----------
#define F_BM 128
#define F_BN 128
#define F_BK 32
#define F_ATILE (128*128)
#define F_BTILE (128*64)
#define F_STAGEB (F_ATILE + F_BTILE)      // 24576
#define F_SMEM (4*F_STAGEB)               // 98304

template<int MODE>
__global__ __launch_bounds__(256, 2)
void fp16_gemm_kernel(const __half* __restrict__ Ap,
                      const __half* __restrict__ Bh,
                      const float* __restrict__ bias,
                      float* __restrict__ outF,
                      int Klog, int KT, int Ntot, int Mtot)
{
  extern __shared__ __align__(128) unsigned char smraw[];
  const uint32_t sb = smem_u32(smraw);
  const int t = threadIdx.x;
  const int m0 = blockIdx.y * F_BM;
  const int n0 = blockIdx.x * F_BN;
  const int kz = blockIdx.z;
  const int c0 = kz * KT;
  const int strideA = 2*Klog;

  auto load_stage = [&](int s, int c){
    const uint32_t stb = sb + s*F_STAGEB;
    const int cc = c0 + c;
#pragma unroll
    for (int it = 0; it < 6; it++){
      int idx = t + it*256;
      if (idx < 1024){
        int r = idx>>3, u = idx&7;
        uint32_t dst = stb + r*128 + ((u ^ (r&7))<<4);
        cp_async16(dst, Ap + (size_t)(m0+r)*strideA + cc*64 + u*8);
      } else {
        int j = idx - 1024;
        int r = j>>2, u = j&3;
        uint32_t dst = stb + F_ATILE + r*64 + ((u ^ ((r>>1)&3))<<4);
        cp_async16(dst, Bh + (size_t)(n0+r)*Klog + cc*32 + u*8);
      }
    }
  };

  const int wid = t>>5, lane = t&31;
  const int wm = wid & 1, wn = wid >> 1;
  int ra[4];
#pragma unroll
  for (int i=0;i<4;i++) ra[i] = wm*64 + i*16 + (lane&7) + ((lane>>3)&1)*8;
  const int ua = lane>>4;
  int rb[2];
#pragma unroll
  for (int h=0;h<2;h++) rb[h] = wn*32 + h*16 + (lane&7) + ((lane>>3)&1)*8;
  const int ub = lane>>4;

  float acc[4][4][4];
#pragma unroll
  for (int i=0;i<4;i++)
#pragma unroll
    for (int j=0;j<4;j++)
#pragma unroll
      for (int q=0;q<4;q++) acc[i][j][q]=0.f;

  load_stage(0, 0);              CP_COMMIT();
  if (KT > 1) load_stage(1, 1);  CP_COMMIT();
  if (KT > 2) load_stage(2, 2);  CP_COMMIT();

  for (int kt = 0; kt < KT; kt++){
    CP_WAIT(2);
    __syncthreads();
    if (kt + 3 < KT) load_stage((kt + 3) & 3, kt + 3);
    CP_COMMIT();

    const uint32_t stA = sb + (kt & 3)*F_STAGEB;
    const uint32_t stB = stA + F_ATILE;
#pragma unroll
    for (int p = 0; p < 2; p++){
      uint32_t Br[2][4];
#pragma unroll
      for (int h=0;h<2;h++){
        int u = 2*p + ub;
        ldm_x4(Br[h], stB + rb[h]*64 + ((u ^ ((rb[h]>>1)&3))<<4));
      }
#pragma unroll
      for (int e = 0; e < 2; e++){
        int kk = 2*p + e;
        uint32_t Ar[4][4];
#pragma unroll
        for (int i=0;i<4;i++){
          int u = 2*kk + ua;
          ldm_x4(Ar[i], stA + ra[i]*128 + ((u ^ (ra[i]&7))<<4));
        }
#pragma unroll
        for (int i=0;i<4;i++)
#pragma unroll
          for (int j=0;j<4;j++){
            uint32_t b = Br[j>>1][(j&1) + 2*e];
            mma_fp16(acc[i][j], Ar[i][0], Ar[i][1], Ar[i][2], Ar[i][3], b, b);
          }
      }
    }
  }

  const int g = lane >> 2, tq = lane & 3;
#pragma unroll
  for (int i=0;i<4;i++){
#pragma unroll
    for (int j=0;j<4;j++){
      int row = m0 + wm*64 + i*16 + g;
      int col = n0 + wn*32 + j*8 + tq*2;
      if (MODE == 0){
        float* dst = outF + ((size_t)kz*Mtot + row)*Ntot + col;
        *(float2*)dst           = make_float2(acc[i][j][0], acc[i][j][1]);
        *(float2*)(dst + (size_t)8*Ntot) = make_float2(acc[i][j][2], acc[i][j][3]);
      } else if (MODE == 1){
        float b0 = bias[col], b1 = bias[col+1];
        float* dst = outF + (size_t)row*Ntot + col;
        *(float2*)dst           = make_float2(fmaxf(acc[i][j][0]+b0,0.f), fmaxf(acc[i][j][1]+b1,0.f));
        *(float2*)(dst + (size_t)8*Ntot) = make_float2(fmaxf(acc[i][j][2]+b0,0.f), fmaxf(acc[i][j][3]+b1,0.f));
      }
    }
  }
}

// ---------------- reduce partials + bias + relu -> X1 packed fp16 -----------
__global__ __launch_bounds__(256)
void reduce_relu_kernel(const float* __restrict__ C, const float* __restrict__ b1,
                        __half* __restrict__ X1p)
{
  int total = BATCH*(H1/8);
  for (int i = blockIdx.x*blockDim.x + threadIdx.x; i < total;
       i += gridDim.x*blockDim.x) {
    int b = i / (H1/8), o = i % (H1/8);
    const float* c0 = C + (size_t)b*H1 + o*8;
    const float* c1 = c0 + (size_t)BATCH*H1;
    const float* bb = b1 + o*8;
    uint32_t u[8];
#pragma unroll
    for (int k=0;k<8;k+=2){
      float v0 = fmaxf(c0[k]   + c1[k]   + bb[k],   0.f);
      float v1 = fmaxf(c0[k+1] + c1[k+1] + bb[k+1], 0.f);
      __half h0 = __float2half(v0), h1 = __float2half(v1);
      u[k>>1]     = (uint32_t)__half_as_ushort(h0) | ((uint32_t)__half_as_ushort(h1)<<16);
      __half l0 = __float2half(v0 - __half2float(h0));
      __half l1 = __float2half(v1 - __half2float(h1));
      u[4+(k>>1)] = (uint32_t)__half_as_ushort(l0) | ((uint32_t)__half_as_ushort(l1)<<16);
    }
    __half* dst = X1p + (size_t)b*(2*H1) + o*16;
    *(uint4*)dst       = *(uint4*)u;
    *(uint4*)(dst + 8) = *(uint4*)(u+4);
  }
}

// ---------------- reduce logits partials + bias -> out -----------------------
__global__ __launch_bounds__(256)
void reduce_logits_kernel(const float* __restrict__ part, const float* __restrict__ bc,
                          float* __restrict__ out)
{
  int i = blockIdx.x*blockDim.x + threadIdx.x;
  if (i < BATCH*NL){
    int b = i/NL, j = i%NL;
    float s = bc[j];
#pragma unroll
    for (int z=0; z<LSPLIT; z++) s += part[((size_t)z*BATCH + b)*NLPAD + j];
    out[i] = s;
  }
}

// ---------------- primary capsules + per-capsule LayerNorm -------------------
__global__ __launch_bounds__(256)
void primary_kernel(const float* __restrict__ X2, const float* __restrict__ Wp,
                    const float* __restrict__ bp, const float* __restrict__ lng,
                    const float* __restrict__ lnb, float* __restrict__ P)
{
  __shared__ __align__(16) float xs[16][H2];
  const int t  = threadIdx.x;
  const int b0 = blockIdx.x * 16;
  for (int idx=t; idx<16*(H2/4); idx+=256){
    int bb = idx/(H2/4);
    int c4 = (idx%(H2/4))*4;
    *(float4*)&xs[bb][c4] = *(const float4*)(X2 + (size_t)(b0+bb)*H2 + c4);
  }
  __syncthreads();
  const int n = t>>3, o = t&7;
  float bias = bp[t];
  float acc[16];
#pragma unroll
  for (int bb=0;bb<16;bb++) acc[bb]=bias;
  const float* wp = Wp + (size_t)n*(H2*PD) + o;
  for (int i0=0;i0<H2;i0+=4){
    float w0 = __ldg(wp + (size_t)(i0+0)*PD);
    float w1 = __ldg(wp + (size_t)(i0+1)*PD);
    float w2 = __ldg(wp + (size_t)(i0+2)*PD);
    float w3 = __ldg(wp + (size_t)(i0+3)*PD);
#pragma unroll
    for (int bb=0;bb<16;bb++){
      float4 x = *(const float4*)&xs[bb][i0];
      acc[bb] += x.x*w0 + x.y*w1 + x.z*w2 + x.w*w3;
    }
  }
  float g = lng[t], be = lnb[t];
#pragma unroll
  for (int bb=0;bb<16;bb++){
    float x = acc[bb];
    float s = x;
    s += __shfl_xor_sync(0xffffffffu, s, 1);
    s += __shfl_xor_sync(0xffffffffu, s, 2);
    s += __shfl_xor_sync(0xffffffffu, s, 4);
    float mu = s * 0.125f;
    float d  = x - mu;
    float q  = d*d;
    q += __shfl_xor_sync(0xffffffffu, q, 1);
    q += __shfl_xor_sync(0xffffffffu, q, 2);
    q += __shfl_xor_sync(0xffffffffu, q, 4);
    float var = q * 0.125f;
    P[(size_t)(b0+bb)*H2 + t] = d * rsqrtf(var + 1e-5f) * g + be;
  }
}

// ---------------- preds via fp16 mma, direct __half2 stores ------------------
#define PREDS_SMEM (JO*PD*2 + 128*16*2)   // 29696

__global__ __launch_bounds__(256)
void preds_mma_kernel(const float* __restrict__ P, const float* __restrict__ Wr,
                      __half* __restrict__ preds, int b_base)
{
  extern __shared__ __align__(16) unsigned char smraw[];
  __half* wsh  = (__half*)smraw;                         // [JO][8] fp16
  __half* ash  = wsh + JO*PD;                            // [128][16]
  const int n  = blockIdx.y;
  const int b0 = b_base + blockIdx.x * 128;
  const int t  = threadIdx.x;
  const int wid = t>>5, lane = t&31;

  const float* wsrc = Wr + (size_t)n*(JO*PD);
  for (int idx=t; idx<JO*PD; idx+=256) wsh[idx] = __float2half(wsrc[idx]);
  for (int idx=t; idx<128*8; idx+=256){
    int r = idx>>3, i = idx&7;
    float v = P[(size_t)(b0+r)*H2 + n*8 + i];
    __half h = __float2half(v);
    ash[r*16 + i]     = h;
    ash[r*16 + 8 + i] = __float2half(v - __half2float(h));
  }
  __syncthreads();

  const int g = lane>>2, tq = lane&3;
  const int ar0 = wid*16 + g;
  uint32_t a0 = *(const uint32_t*)&ash[ar0*16 + tq*2];
  uint32_t a1 = *(const uint32_t*)&ash[(ar0+8)*16 + tq*2];
  uint32_t a2 = *(const uint32_t*)&ash[ar0*16 + 8 + tq*2];
  uint32_t a3 = *(const uint32_t*)&ash[(ar0+8)*16 + 8 + tq*2];

  __half* out0 = preds + (size_t)(b0 + wid*16 + g)*PREDROW + (size_t)n*JO + tq*2;
  __half* out1 = out0 + (size_t)8*PREDROW;

#pragma unroll 4
  for (int jt = 0; jt < JO/8; jt++){
    uint32_t b0v = *(const uint32_t*)&wsh[(jt*8+g)*8 + tq*2];
    float c[4] = {0.f,0.f,0.f,0.f};
    mma_fp16(c, a0, a1, a2, a3, b0v, b0v);
    *(__half2*)(out0 + jt*8) = __floats2half2_rn(c[0], c[1]);
    *(__half2*)(out1 + jt*8) = __floats2half2_rn(c[2], c[3]);
  }
}

// ---------------- dynamic routing: register-resident preds, 800 threads ------
#define RT_T 800

__global__ __launch_bounds__(RT_T, 1)
void routing_kernel(const __half* __restrict__ preds, __half* __restrict__ Vp,
                    int b_base)
{
  __shared__ float bl[NP*NL];
  __shared__ float cs[NP*NL];
  __shared__ float pmax[NP*4];
  __shared__ float psum[NP*4];
  const int b = b_base + blockIdx.x;
  const int t = threadIdx.x;
  const int j = t >> 3;
  const int g8 = t & 7;

  __half2 p2[NP];
  const __half2* src = (const __half2*)(preds + (size_t)b*PREDROW);
#pragma unroll
  for (int n=0;n<NP;n++) p2[n] = src[(size_t)n*(JO/2) + t];

  float2 v;
  {
    float ax=0.f, ay=0.f;
#pragma unroll
    for (int n=0;n<NP;n++){ float2 f = __half22float2(p2[n]); ax += f.x; ay += f.y; }
    v.x = ax*(1.0f/NL); v.y = ay*(1.0f/NL);
  }

  for (int iter=0; ; iter++){
    float sq = v.x*v.x + v.y*v.y;
    sq += __shfl_xor_sync(0xffffffffu, sq, 1);
    sq += __shfl_xor_sync(0xffffffffu, sq, 2);
    sq += __shfl_xor_sync(0xffffffffu, sq, 4);
    float scale = sq/(1.f+sq)*rsqrtf(sq+1e-8f);
    v.x *= scale; v.y *= scale;
    if (iter == 2) break;

#pragma unroll
    for (int n=0;n<NP;n++){
      float2 f = __half22float2(p2[n]);
      float a = f.x*v.x + f.y*v.y;
      a += __shfl_xor_sync(0xffffffffu, a, 1);
      a += __shfl_xor_sync(0xffffffffu, a, 2);
      a += __shfl_xor_sync(0xffffffffu, a, 4);
      if ((n & 7) == g8){
        if (iter == 0) bl[n*NL + j] = a;
        else           bl[n*NL + j] += a;
      }
    }
    __syncthreads();

    if (t < NP*4){
      int n = t>>2, q = t&3;
      float m = -1e30f;
      for (int jj=q*25; jj<q*25+25; jj++) m = fmaxf(m, bl[n*NL+jj]);
      pmax[t] = m;
    }
    __syncthreads();
    if (t < NP*4){
      int n = t>>2, q = t&3;
      float m = fmaxf(fmaxf(pmax[n*4],pmax[n*4+1]),fmaxf(pmax[n*4+2],pmax[n*4+3]));
      float s = 0.f;
      for (int jj=q*25; jj<q*25+25; jj++) s += __expf(bl[n*NL+jj]-m);
      psum[t] = s;
    }
    __syncthreads();
    for (int nj=t; nj<NP*NL; nj+=RT_T){
      int n = nj/NL;
      float m = fmaxf(fmaxf(pmax[n*4],pmax[n*4+1]),fmaxf(pmax[n*4+2],pmax[n*4+3]));
      float ssum = psum[n*4]+psum[n*4+1]+psum[n*4+2]+psum[n*4+3];
      cs[nj] = __expf(bl[nj]-m)/ssum;
    }
    __syncthreads();

    float ax=0.f, ay=0.f;
#pragma unroll
    for (int n=0;n<NP;n++){
      float c = cs[n*NL + j];
      float2 f = __half22float2(p2[n]);
      ax += c*f.x; ay += c*f.y;
    }
    v.x = ax; v.y = ay;
  }

  __half h0 = __float2half(v.x), h1 = __float2half(v.y);
  __half l0 = __float2half(v.x - __half2float(h0));
  __half l1 = __float2half(v.y - __half2float(h1));
  __half* dst = Vp + (size_t)b*(2*JO) + (t>>2)*16 + ((2*t)&7);
  *(__half2*)dst     = __halves2half2(h0, h1);
  *(__half2*)(dst+8) = __halves2half2(l0, l1);
}

// ---------------- launch -----------------------------------------------------
extern "C" void kernel_launch(void* const* d_in, const int* in_sizes, int n_in,
                              void* d_out, int out_size)
{
  (void)in_sizes; (void)n_in; (void)out_size;
  const float* features = (const float*)d_in[0];
  const float* W1  = (const float*)d_in[1];
  const float* b1  = (const float*)d_in[2];
  const float* W2  = (const float*)d_in[3];
  const float* b2  = (const float*)d_in[4];
  const float* Wp  = (const float*)d_in[5];
  const float* bp  = (const float*)d_in[6];
  const float* lng = (const float*)d_in[7];
  const float* lnb = (const float*)d_in[8];
  const float* Wr  = (const float*)d_in[9];
  const float* Wc  = (const float*)d_in[10];
  const float* bc  = (const float*)d_in[11];
  float* out = (float*)d_out;

  __half *A1p,*B1h,*B2h,*Wch,*X1p,*PR,*Vp;
  float *Cp,*X2,*P;
  cudaGetSymbolAddress((void**)&A1p, g_A1p);
  cudaGetSymbolAddress((void**)&B1h, g_B1h);
  cudaGetSymbolAddress((void**)&B2h, g_B2h);
  cudaGetSymbolAddress((void**)&Wch, g_Wch);
  cudaGetSymbolAddress((void**)&Cp,  g_Cpart);
  cudaGetSymbolAddress((void**)&X1p, g_X1p);
  cudaGetSymbolAddress((void**)&X2,  g_X2);
  cudaGetSymbolAddress((void**)&P,   g_P);
  cudaGetSymbolAddress((void**)&PR,  g_preds);
  cudaGetSymbolAddress((void**)&Vp,  g_Vp);

  // launches ordered so gemm1 is the 4th (profiled) launch
  convA_f16_kernel<<<4096, 256>>>(features, A1p);                                   // 1
  convW_f16_kernel<<<dim3(KPAD1/32, H1/32), dim3(32,8)>>>(W1, B1h, IN_DIM, H1, KPAD1); // 2
  convW_f16_kernel<<<dim3(H1/32, H2/32),    dim3(32,8)>>>(W2, B2h, H1, H2, H1);     // 3

  cudaFuncSetAttribute(fp16_gemm_kernel<0>, cudaFuncAttributeMaxDynamicSharedMemorySize, F_SMEM);
  fp16_gemm_kernel<0><<<dim3(H1/F_BN, BATCH/F_BM, 2), 256, F_SMEM>>>(               // 4
      A1p, B1h, nullptr, Cp, KPAD1, (KPAD1/F_BK)/2, H1, BATCH);

  convW_f16_kernel<<<dim3(JO/32, NLPAD/32), dim3(32,8)>>>(Wc, Wch, JO, NL, JO);     // 5
  reduce_relu_kernel<<<1024, 256>>>(Cp, b1, X1p);                                   // 6

  cudaFuncSetAttribute(fp16_gemm_kernel<1>, cudaFuncAttributeMaxDynamicSharedMemorySize, F_SMEM);
  fp16_gemm_kernel<1><<<dim3(H2/F_BN, BATCH/F_BM, 1), 256, F_SMEM>>>(               // 7
      X1p, B2h, b2, X2, H1, H1/F_BK, H2, BATCH);

  primary_kernel<<<BATCH/16, 256>>>(X2, Wp, bp, lng, lnb, P);                       // 8

  // preds+routing interleaved per 1024-row chunk for L2 reuse of the preds slab
  cudaFuncSetAttribute(preds_mma_kernel, cudaFuncAttributeMaxDynamicSharedMemorySize, PREDS_SMEM);
  for (int base = 0; base < BATCH; base += BCHUNK){
    preds_mma_kernel<<<dim3(BCHUNK/128, NP), 256, PREDS_SMEM>>>(P, Wr, PR, base);
    routing_kernel<<<BCHUNK, RT_T>>>(PR, Vp, base);
  }

  // logits partials (k-split 5) + reduce
  fp16_gemm_kernel<0><<<dim3(1, BATCH/F_BM, LSPLIT), 256, F_SMEM>>>(
      Vp, Wch, nullptr, Cp, JO, (JO/F_BK)/LSPLIT, NLPAD, BATCH);
  reduce_logits_kernel<<<(BATCH*NL+255)/256, 256>>>(Cp, bc, out);
}

// round 8
// speedup vs baseline: 2.0130x; 1.0295x over previous
#include <cuda_runtime.h>
#include <cuda_fp16.h>
#include <cstdint>
#include <cstddef>

#define BATCH 4096
#define IN_DIM 10000
#define H1 512
#define H2 256
#define NP 32
#define PD 8
#define NL 100
#define CD 16
#define JO (NL*CD)       // 1600
#define PREDROW (NP*JO)  // 51200
#define KPAD1 10240
#define NLPAD 128
#define BCHUNK 1024      // preds/routing L2 chunk
#define LSPLIT 5         // logits k-split

// ---------------- helpers ----------------------------------------------------
__device__ __forceinline__ uint32_t smem_u32(const void* p) {
  uint32_t a;
  asm("{ .reg .u64 t; cvta.to.shared.u64 t, %1; cvt.u32.u64 %0, t; }" : "=r"(a) : "l"(p));
  return a;
}
__device__ __forceinline__ void cp_async16(uint32_t smem, const void* g) {
  asm volatile("cp.async.cg.shared.global [%0], [%1], 16;" :: "r"(smem), "l"(g));
}
#define CP_COMMIT() asm volatile("cp.async.commit_group;" ::: "memory")
#define CP_WAIT(N)  asm volatile("cp.async.wait_group %0;" :: "n"(N) : "memory")

__device__ __forceinline__ void ldm_x4(uint32_t* r, uint32_t addr) {
  asm volatile("ldmatrix.sync.aligned.m8n8.x4.shared.b16 {%0,%1,%2,%3}, [%4];"
               : "=r"(r[0]), "=r"(r[1]), "=r"(r[2]), "=r"(r[3]) : "r"(addr));
}
__device__ __forceinline__ void mma_fp16(float* d, uint32_t a0, uint32_t a1,
                                         uint32_t a2, uint32_t a3,
                                         uint32_t b0, uint32_t b1) {
  asm volatile("mma.sync.aligned.m16n8k16.row.col.f32.f16.f16.f32 "
               "{%0,%1,%2,%3}, {%4,%5,%6,%7}, {%8,%9}, {%0,%1,%2,%3};"
               : "+f"(d[0]), "+f"(d[1]), "+f"(d[2]), "+f"(d[3])
               : "r"(a0), "r"(a1), "r"(a2), "r"(a3), "r"(b0), "r"(b1));
}

// ---------------- scratch ----------------------------------------------------
__device__ __half g_A1p[(size_t)BATCH*2*KPAD1];   // features packed split fp16
__device__ __half g_B1h[(size_t)H1*KPAD1];        // W1^T fp16
__device__ __half g_B2h[(size_t)H2*H1];           // W2^T fp16
__device__ __half g_Wch[(size_t)NLPAD*JO];        // Wc^T fp16 (zero-padded rows)
__device__ float  g_Cpart[(size_t)LSPLIT*BATCH*NLPAD > (size_t)2*BATCH*H1
                          ? (size_t)LSPLIT*BATCH*NLPAD : (size_t)2*BATCH*H1];
__device__ __half g_X1p[(size_t)BATCH*2*H1];      // X1 packed
__device__ float  g_X2[(size_t)BATCH*H2];
__device__ float  g_P [(size_t)BATCH*H2];
__device__ __half g_preds[(size_t)BATCH*PREDROW];
__device__ __half g_Vp[(size_t)BATCH*2*JO];       // V packed

// ---------------- conversions ------------------------------------------------
__global__ __launch_bounds__(256)
void convA_f16_kernel(const float* __restrict__ F, __half* __restrict__ Ap)
{
  int total = BATCH*(KPAD1/8);
  for (int i = blockIdx.x*blockDim.x + threadIdx.x; i < total;
       i += gridDim.x*blockDim.x) {
    int row = i / (KPAD1/8), o = i % (KPAD1/8);
    uint32_t u[8];
    if (o*8 < IN_DIM){
      const float* src = F + (size_t)row*IN_DIM + o*8;
#pragma unroll
      for (int k=0;k<8;k+=2){
        float v0 = src[k], v1 = src[k+1];
        __half h0 = __float2half(v0), h1 = __float2half(v1);
        u[k>>1]     = (uint32_t)__half_as_ushort(h0) | ((uint32_t)__half_as_ushort(h1)<<16);
        __half l0 = __float2half(v0 - __half2float(h0));
        __half l1 = __float2half(v1 - __half2float(h1));
        u[4+(k>>1)] = (uint32_t)__half_as_ushort(l0) | ((uint32_t)__half_as_ushort(l1)<<16);
      }
    } else {
#pragma unroll
      for (int k=0;k<8;k++) u[k]=0;
    }
    __half* dst = Ap + (size_t)row*(2*KPAD1) + o*16;
    *(uint4*)dst       = *(uint4*)u;
    *(uint4*)(dst + 8) = *(uint4*)(u+4);
  }
}

__global__ __launch_bounds__(256)
void convW_f16_kernel(const float* __restrict__ W, __half* __restrict__ B,
                      int K, int N, int KP)
{
  __shared__ float tile[32][33];
  int kb = blockIdx.x*32, nb = blockIdx.y*32;
  int tx = threadIdx.x, ty = threadIdx.y;   // block (32,8)
#pragma unroll
  for (int i=0;i<32;i+=8){
    int k = kb+ty+i, col = nb+tx;
    tile[ty+i][tx] = (k < K && col < N) ? W[(size_t)k*N + col] : 0.f;
  }
  __syncthreads();
#pragma unroll
  for (int i=0;i<32;i+=8){
    int n = nb+ty+i, k = kb+tx;
    B[(size_t)n*KP + k] = __float2half(tile[tx][ty+i]);
  }
}

// ---------------- fp16 K-packed GEMM, 4-stage single-sync pipeline ----------
#define F_BM 128
#define F_BN 128
#define F_BK 32
#define F_ATILE (128*128)
#define F_BTILE (128*64)
#define F_STAGEB (F_ATILE + F_BTILE)      // 24576
#define F_SMEM (4*F_STAGEB)               // 98304

template<int MODE>
__global__ __launch_bounds__(256, 2)
void fp16_gemm_kernel(const __half* __restrict__ Ap,
                      const __half* __restrict__ Bh,
                      const float* __restrict__ bias,
                      float* __restrict__ outF,
                      int Klog, int KT, int Ntot, int Mtot)
{
  extern __shared__ __align__(128) unsigned char smraw[];
  const uint32_t sb = smem_u32(smraw);
  const int t = threadIdx.x;
  const int m0 = blockIdx.y * F_BM;
  const int n0 = blockIdx.x * F_BN;
  const int kz = blockIdx.z;
  const int c0 = kz * KT;
  const int strideA = 2*Klog;

  auto load_stage = [&](int s, int c){
    const uint32_t stb = sb + s*F_STAGEB;
    const int cc = c0 + c;
#pragma unroll
    for (int it = 0; it < 6; it++){
      int idx = t + it*256;
      if (idx < 1024){
        int r = idx>>3, u = idx&7;
        uint32_t dst = stb + r*128 + ((u ^ (r&7))<<4);
        cp_async16(dst, Ap + (size_t)(m0+r)*strideA + cc*64 + u*8);
      } else {
        int j = idx - 1024;
        int r = j>>2, u = j&3;
        uint32_t dst = stb + F_ATILE + r*64 + ((u ^ ((r>>1)&3))<<4);
        cp_async16(dst, Bh + (size_t)(n0+r)*Klog + cc*32 + u*8);
      }
    }
  };

  const int wid = t>>5, lane = t&31;
  const int wm = wid & 1, wn = wid >> 1;
  int ra[4];
#pragma unroll
  for (int i=0;i<4;i++) ra[i] = wm*64 + i*16 + (lane&7) + ((lane>>3)&1)*8;
  const int ua = lane>>4;
  int rb[2];
#pragma unroll
  for (int h=0;h<2;h++) rb[h] = wn*32 + h*16 + (lane&7) + ((lane>>3)&1)*8;
  const int ub = lane>>4;

  float acc[4][4][4];
#pragma unroll
  for (int i=0;i<4;i++)
#pragma unroll
    for (int j=0;j<4;j++)
#pragma unroll
      for (int q=0;q<4;q++) acc[i][j][q]=0.f;

  load_stage(0, 0);              CP_COMMIT();
  if (KT > 1) load_stage(1, 1);  CP_COMMIT();
  if (KT > 2) load_stage(2, 2);  CP_COMMIT();

  for (int kt = 0; kt < KT; kt++){
    CP_WAIT(2);
    __syncthreads();
    if (kt + 3 < KT) load_stage((kt + 3) & 3, kt + 3);
    CP_COMMIT();

    const uint32_t stA = sb + (kt & 3)*F_STAGEB;
    const uint32_t stB = stA + F_ATILE;
#pragma unroll
    for (int p = 0; p < 2; p++){
      uint32_t Br[2][4];
#pragma unroll
      for (int h=0;h<2;h++){
        int u = 2*p + ub;
        ldm_x4(Br[h], stB + rb[h]*64 + ((u ^ ((rb[h]>>1)&3))<<4));
      }
#pragma unroll
      for (int e = 0; e < 2; e++){
        int kk = 2*p + e;
        uint32_t Ar[4][4];
#pragma unroll
        for (int i=0;i<4;i++){
          int u = 2*kk + ua;
          ldm_x4(Ar[i], stA + ra[i]*128 + ((u ^ (ra[i]&7))<<4));
        }
#pragma unroll
        for (int i=0;i<4;i++)
#pragma unroll
          for (int j=0;j<4;j++){
            uint32_t b = Br[j>>1][(j&1) + 2*e];
            mma_fp16(acc[i][j], Ar[i][0], Ar[i][1], Ar[i][2], Ar[i][3], b, b);
          }
      }
    }
  }

  const int g = lane >> 2, tq = lane & 3;
#pragma unroll
  for (int i=0;i<4;i++){
#pragma unroll
    for (int j=0;j<4;j++){
      int row = m0 + wm*64 + i*16 + g;
      int col = n0 + wn*32 + j*8 + tq*2;
      if (MODE == 0){
        float* dst = outF + ((size_t)kz*Mtot + row)*Ntot + col;
        *(float2*)dst           = make_float2(acc[i][j][0], acc[i][j][1]);
        *(float2*)(dst + (size_t)8*Ntot) = make_float2(acc[i][j][2], acc[i][j][3]);
      } else if (MODE == 1){
        float b0 = bias[col], b1 = bias[col+1];
        float* dst = outF + (size_t)row*Ntot + col;
        *(float2*)dst           = make_float2(fmaxf(acc[i][j][0]+b0,0.f), fmaxf(acc[i][j][1]+b1,0.f));
        *(float2*)(dst + (size_t)8*Ntot) = make_float2(fmaxf(acc[i][j][2]+b0,0.f), fmaxf(acc[i][j][3]+b1,0.f));
      }
    }
  }
}

// ---------------- reduce partials + bias + relu -> X1 packed fp16 -----------
__global__ __launch_bounds__(256)
void reduce_relu_kernel(const float* __restrict__ C, const float* __restrict__ b1,
                        __half* __restrict__ X1p)
{
  int total = BATCH*(H1/8);
  for (int i = blockIdx.x*blockDim.x + threadIdx.x; i < total;
       i += gridDim.x*blockDim.x) {
    int b = i / (H1/8), o = i % (H1/8);
    const float* c0 = C + (size_t)b*H1 + o*8;
    const float* c1 = c0 + (size_t)BATCH*H1;
    const float* bb = b1 + o*8;
    uint32_t u[8];
#pragma unroll
    for (int k=0;k<8;k+=2){
      float v0 = fmaxf(c0[k]   + c1[k]   + bb[k],   0.f);
      float v1 = fmaxf(c0[k+1] + c1[k+1] + bb[k+1], 0.f);
      __half h0 = __float2half(v0), h1 = __float2half(v1);
      u[k>>1]     = (uint32_t)__half_as_ushort(h0) | ((uint32_t)__half_as_ushort(h1)<<16);
      __half l0 = __float2half(v0 - __half2float(h0));
      __half l1 = __float2half(v1 - __half2float(h1));
      u[4+(k>>1)] = (uint32_t)__half_as_ushort(l0) | ((uint32_t)__half_as_ushort(l1)<<16);
    }
    __half* dst = X1p + (size_t)b*(2*H1) + o*16;
    *(uint4*)dst       = *(uint4*)u;
    *(uint4*)(dst + 8) = *(uint4*)(u+4);
  }
}

// ---------------- reduce logits partials + bias -> out -----------------------
__global__ __launch_bounds__(256)
void reduce_logits_kernel(const float* __restrict__ part, const float* __restrict__ bc,
                          float* __restrict__ out)
{
  int i = blockIdx.x*blockDim.x + threadIdx.x;
  if (i < BATCH*NL){
    int b = i/NL, j = i%NL;
    float s = bc[j];
#pragma unroll
    for (int z=0; z<LSPLIT; z++) s += part[((size_t)z*BATCH + b)*NLPAD + j];
    out[i] = s;
  }
}

// ---------------- primary capsules + per-capsule LayerNorm -------------------
__global__ __launch_bounds__(256)
void primary_kernel(const float* __restrict__ X2, const float* __restrict__ Wp,
                    const float* __restrict__ bp, const float* __restrict__ lng,
                    const float* __restrict__ lnb, float* __restrict__ P)
{
  __shared__ __align__(16) float xs[16][H2];
  const int t  = threadIdx.x;
  const int b0 = blockIdx.x * 16;
  for (int idx=t; idx<16*(H2/4); idx+=256){
    int bb = idx/(H2/4);
    int c4 = (idx%(H2/4))*4;
    *(float4*)&xs[bb][c4] = *(const float4*)(X2 + (size_t)(b0+bb)*H2 + c4);
  }
  __syncthreads();
  const int n = t>>3, o = t&7;
  float bias = bp[t];
  float acc[16];
#pragma unroll
  for (int bb=0;bb<16;bb++) acc[bb]=bias;
  const float* wp = Wp + (size_t)n*(H2*PD) + o;
  for (int i0=0;i0<H2;i0+=4){
    float w0 = __ldg(wp + (size_t)(i0+0)*PD);
    float w1 = __ldg(wp + (size_t)(i0+1)*PD);
    float w2 = __ldg(wp + (size_t)(i0+2)*PD);
    float w3 = __ldg(wp + (size_t)(i0+3)*PD);
#pragma unroll
    for (int bb=0;bb<16;bb++){
      float4 x = *(const float4*)&xs[bb][i0];
      acc[bb] += x.x*w0 + x.y*w1 + x.z*w2 + x.w*w3;
    }
  }
  float g = lng[t], be = lnb[t];
#pragma unroll
  for (int bb=0;bb<16;bb++){
    float x = acc[bb];
    float s = x;
    s += __shfl_xor_sync(0xffffffffu, s, 1);
    s += __shfl_xor_sync(0xffffffffu, s, 2);
    s += __shfl_xor_sync(0xffffffffu, s, 4);
    float mu = s * 0.125f;
    float d  = x - mu;
    float q  = d*d;
    q += __shfl_xor_sync(0xffffffffu, q, 1);
    q += __shfl_xor_sync(0xffffffffu, q, 2);
    q += __shfl_xor_sync(0xffffffffu, q, 4);
    float var = q * 0.125f;
    P[(size_t)(b0+bb)*H2 + t] = d * rsqrtf(var + 1e-5f) * g + be;
  }
}

// ---------------- preds via fp16 mma; jo-permuted weights -> uint2 stores ----
// Superblock of 16 jo = 2 MMAs; SMEM weight rows permuted so thread tq's four
// outputs are jo = J + tq*4 + {0,1,2,3}  ->  one 8B store per row-half.
#define PREDS_SMEM (JO*PD*2 + 128*16*2)   // 29696

__global__ __launch_bounds__(256)
void preds_mma_kernel(const float* __restrict__ P, const float* __restrict__ Wr,
                      __half* __restrict__ preds, int b_base)
{
  extern __shared__ __align__(16) unsigned char smraw[];
  __half* wsh  = (__half*)smraw;                         // [JO][8], permuted rows
  __half* ash  = wsh + JO*PD;                            // [128][16]
  const int n  = blockIdx.y;
  const int b0 = b_base + blockIdx.x * 128;
  const int t  = threadIdx.x;
  const int wid = t>>5, lane = t&31;

  const float* wsrc = Wr + (size_t)n*(JO*PD);
  for (int i=t; i<JO*PD; i+=256){
    int d = i>>3, k = i&7;
    int jtp = d>>4, r = d&15;
    int a = r>>3, nn = r&7;
    int jo = jtp*16 + ((nn>>1)<<2) + (a<<1) + (nn&1);
    wsh[i] = __float2half(wsrc[jo*8 + k]);
  }
  for (int idx=t; idx<128*8; idx+=256){
    int r = idx>>3, i = idx&7;
    float v = P[(size_t)(b0+r)*H2 + n*8 + i];
    __half h = __float2half(v);
    ash[r*16 + i]     = h;
    ash[r*16 + 8 + i] = __float2half(v - __half2float(h));
  }
  __syncthreads();

  const int g = lane>>2, tq = lane&3;
  const int ar0 = wid*16 + g;
  uint32_t a0 = *(const uint32_t*)&ash[ar0*16 + tq*2];
  uint32_t a1 = *(const uint32_t*)&ash[(ar0+8)*16 + tq*2];
  uint32_t a2 = *(const uint32_t*)&ash[ar0*16 + 8 + tq*2];
  uint32_t a3 = *(const uint32_t*)&ash[(ar0+8)*16 + 8 + tq*2];

  __half* out0 = preds + (size_t)(b0 + wid*16 + g)*PREDROW + (size_t)n*JO + tq*4;
  __half* out1 = out0 + (size_t)8*PREDROW;

#pragma unroll 2
  for (int jtp = 0; jtp < JO/16; jtp++){
    uint32_t bv0 = *(const uint32_t*)&wsh[(jtp*16 + g)*8 + tq*2];
    uint32_t bv1 = *(const uint32_t*)&wsh[(jtp*16 + 8 + g)*8 + tq*2];
    float c[4] = {0.f,0.f,0.f,0.f};
    float d2[4] = {0.f,0.f,0.f,0.f};
    mma_fp16(c,  a0, a1, a2, a3, bv0, bv0);
    mma_fp16(d2, a0, a1, a2, a3, bv1, bv1);
    __half2 p0 = __floats2half2_rn(c[0],  c[1]);
    __half2 p1 = __floats2half2_rn(d2[0], d2[1]);
    __half2 p2 = __floats2half2_rn(c[2],  c[3]);
    __half2 p3 = __floats2half2_rn(d2[2], d2[3]);
    *(uint2*)(out0 + jtp*16) = make_uint2(*(uint32_t*)&p0, *(uint32_t*)&p1);
    *(uint2*)(out1 + jtp*16) = make_uint2(*(uint32_t*)&p2, *(uint32_t*)&p3);
  }
}

// ---------------- dynamic routing: L1-resident preds reloads, 2 CTAs/SM -----
#define RT_T 800

__global__ __launch_bounds__(RT_T, 2)
void routing_kernel(const __half* __restrict__ preds, __half* __restrict__ Vp,
                    int b_base)
{
  __shared__ float bl[NP*NL];
  __shared__ float cs[NP*NL];
  __shared__ float pmax[NP*4];
  __shared__ float psum[NP*4];
  const int b = b_base + blockIdx.x;
  const int t = threadIdx.x;
  const int j = t >> 3;
  const int g8 = t & 7;
  const __half2* src = (const __half2*)(preds + (size_t)b*PREDROW) + t;

  float2 v;
  {
    float ax=0.f, ay=0.f;
#pragma unroll
    for (int n=0;n<NP;n++){
      float2 f = __half22float2(__ldg(src + n*(JO/2)));
      ax += f.x; ay += f.y;
    }
    v.x = ax*(1.0f/NL); v.y = ay*(1.0f/NL);
  }

  for (int iter=0; ; iter++){
    float sq = v.x*v.x + v.y*v.y;
    sq += __shfl_xor_sync(0xffffffffu, sq, 1);
    sq += __shfl_xor_sync(0xffffffffu, sq, 2);
    sq += __shfl_xor_sync(0xffffffffu, sq, 4);
    float scale = sq/(1.f+sq)*rsqrtf(sq+1e-8f);
    v.x *= scale; v.y *= scale;
    if (iter == 2) break;

#pragma unroll
    for (int n=0;n<NP;n++){
      float2 f = __half22float2(__ldg(src + n*(JO/2)));
      float a = f.x*v.x + f.y*v.y;
      a += __shfl_xor_sync(0xffffffffu, a, 1);
      a += __shfl_xor_sync(0xffffffffu, a, 2);
      a += __shfl_xor_sync(0xffffffffu, a, 4);
      if ((n & 7) == g8){
        if (iter == 0) bl[n*NL + j] = a;
        else           bl[n*NL + j] += a;
      }
    }
    __syncthreads();

    if (t < NP*4){
      int n = t>>2, q = t&3;
      float m = -1e30f;
      for (int jj=q*25; jj<q*25+25; jj++) m = fmaxf(m, bl[n*NL+jj]);
      pmax[t] = m;
    }
    __syncthreads();
    if (t < NP*4){
      int n = t>>2, q = t&3;
      float m = fmaxf(fmaxf(pmax[n*4],pmax[n*4+1]),fmaxf(pmax[n*4+2],pmax[n*4+3]));
      float s = 0.f;
      for (int jj=q*25; jj<q*25+25; jj++) s += __expf(bl[n*NL+jj]-m);
      psum[t] = s;
    }
    __syncthreads();
    for (int nj=t; nj<NP*NL; nj+=RT_T){
      int n = nj/NL;
      float m = fmaxf(fmaxf(pmax[n*4],pmax[n*4+1]),fmaxf(pmax[n*4+2],pmax[n*4+3]));
      float ssum = psum[n*4]+psum[n*4+1]+psum[n*4+2]+psum[n*4+3];
      cs[nj] = __expf(bl[nj]-m)/ssum;
    }
    __syncthreads();

    float ax=0.f, ay=0.f;
#pragma unroll
    for (int n=0;n<NP;n++){
      float c = cs[n*NL + j];
      float2 f = __half22float2(__ldg(src + n*(JO/2)));
      ax += c*f.x; ay += c*f.y;
    }
    v.x = ax; v.y = ay;
    __syncthreads();
  }

  __half h0 = __float2half(v.x), h1 = __float2half(v.y);
  __half l0 = __float2half(v.x - __half2float(h0));
  __half l1 = __float2half(v.y - __half2float(h1));
  __half* dst = Vp + (size_t)b*(2*JO) + (t>>2)*16 + ((2*t)&7);
  *(__half2*)dst     = __halves2half2(h0, h1);
  *(__half2*)(dst+8) = __halves2half2(l0, l1);
}

// ---------------- launch -----------------------------------------------------
extern "C" void kernel_launch(void* const* d_in, const int* in_sizes, int n_in,
                              void* d_out, int out_size)
{
  (void)in_sizes; (void)n_in; (void)out_size;
  const float* features = (const float*)d_in[0];
  const float* W1  = (const float*)d_in[1];
  const float* b1  = (const float*)d_in[2];
  const float* W2  = (const float*)d_in[3];
  const float* b2  = (const float*)d_in[4];
  const float* Wp  = (const float*)d_in[5];
  const float* bp  = (const float*)d_in[6];
  const float* lng = (const float*)d_in[7];
  const float* lnb = (const float*)d_in[8];
  const float* Wr  = (const float*)d_in[9];
  const float* Wc  = (const float*)d_in[10];
  const float* bc  = (const float*)d_in[11];
  float* out = (float*)d_out;

  __half *A1p,*B1h,*B2h,*Wch,*X1p,*PR,*Vp;
  float *Cp,*X2,*P;
  cudaGetSymbolAddress((void**)&A1p, g_A1p);
  cudaGetSymbolAddress((void**)&B1h, g_B1h);
  cudaGetSymbolAddress((void**)&B2h, g_B2h);
  cudaGetSymbolAddress((void**)&Wch, g_Wch);
  cudaGetSymbolAddress((void**)&Cp,  g_Cpart);
  cudaGetSymbolAddress((void**)&X1p, g_X1p);
  cudaGetSymbolAddress((void**)&X2,  g_X2);
  cudaGetSymbolAddress((void**)&P,   g_P);
  cudaGetSymbolAddress((void**)&PR,  g_preds);
  cudaGetSymbolAddress((void**)&Vp,  g_Vp);

  // launches ordered so gemm1 is the 4th (profiled) launch
  convA_f16_kernel<<<4096, 256>>>(features, A1p);                                   // 1
  convW_f16_kernel<<<dim3(KPAD1/32, H1/32), dim3(32,8)>>>(W1, B1h, IN_DIM, H1, KPAD1); // 2
  convW_f16_kernel<<<dim3(H1/32, H2/32),    dim3(32,8)>>>(W2, B2h, H1, H2, H1);     // 3

  cudaFuncSetAttribute(fp16_gemm_kernel<0>, cudaFuncAttributeMaxDynamicSharedMemorySize, F_SMEM);
  fp16_gemm_kernel<0><<<dim3(H1/F_BN, BATCH/F_BM, 2), 256, F_SMEM>>>(               // 4
      A1p, B1h, nullptr, Cp, KPAD1, (KPAD1/F_BK)/2, H1, BATCH);

  convW_f16_kernel<<<dim3(JO/32, NLPAD/32), dim3(32,8)>>>(Wc, Wch, JO, NL, JO);     // 5
  reduce_relu_kernel<<<1024, 256>>>(Cp, b1, X1p);                                   // 6

  cudaFuncSetAttribute(fp16_gemm_kernel<1>, cudaFuncAttributeMaxDynamicSharedMemorySize, F_SMEM);
  fp16_gemm_kernel<1><<<dim3(H2/F_BN, BATCH/F_BM, 1), 256, F_SMEM>>>(               // 7
      X1p, B2h, b2, X2, H1, H1/F_BK, H2, BATCH);

  primary_kernel<<<BATCH/16, 256>>>(X2, Wp, bp, lng, lnb, P);                       // 8

  // preds+routing interleaved per 1024-row chunk for L2 reuse of the preds slab
  cudaFuncSetAttribute(preds_mma_kernel, cudaFuncAttributeMaxDynamicSharedMemorySize, PREDS_SMEM);
  for (int base = 0; base < BATCH; base += BCHUNK){
    preds_mma_kernel<<<dim3(BCHUNK/128, NP), 256, PREDS_SMEM>>>(P, Wr, PR, base);
    routing_kernel<<<BCHUNK, RT_T>>>(PR, Vp, base);
  }

  // logits partials (k-split 5) + reduce
  fp16_gemm_kernel<0><<<dim3(1, BATCH/F_BM, LSPLIT), 256, F_SMEM>>>(
      Vp, Wch, nullptr, Cp, JO, (JO/F_BK)/LSPLIT, NLPAD, BATCH);
  reduce_logits_kernel<<<(BATCH*NL+255)/256, 256>>>(Cp, bc, out);
}

// round 9
// speedup vs baseline: 2.2610x; 1.1232x over previous
#include <cuda_runtime.h>
#include <cuda_fp16.h>
#include <cstdint>
#include <cstddef>

#define BATCH 4096
#define IN_DIM 10000
#define H1 512
#define H2 256
#define NP 32
#define PD 8
#define NL 100
#define CD 16
#define JO (NL*CD)       // 1600
#define PREDROW (NP*JO)  // 51200
#define KPAD1 10240
#define NLPAD 128
#define BCHUNK 1024      // preds/routing L2 chunk
#define LSPLIT 5         // logits k-split

// ---------------- helpers ----------------------------------------------------
__device__ __forceinline__ uint32_t smem_u32(const void* p) {
  uint32_t a;
  asm("{ .reg .u64 t; cvta.to.shared.u64 t, %1; cvt.u32.u64 %0, t; }" : "=r"(a) : "l"(p));
  return a;
}
__device__ __forceinline__ void cp_async16(uint32_t smem, const void* g) {
  asm volatile("cp.async.cg.shared.global [%0], [%1], 16;" :: "r"(smem), "l"(g));
}
#define CP_COMMIT() asm volatile("cp.async.commit_group;" ::: "memory")
#define CP_WAIT(N)  asm volatile("cp.async.wait_group %0;" :: "n"(N) : "memory")

__device__ __forceinline__ void ldm_x4(uint32_t* r, uint32_t addr) {
  asm volatile("ldmatrix.sync.aligned.m8n8.x4.shared.b16 {%0,%1,%2,%3}, [%4];"
               : "=r"(r[0]), "=r"(r[1]), "=r"(r[2]), "=r"(r[3]) : "r"(addr));
}
__device__ __forceinline__ void mma_fp16(float* d, uint32_t a0, uint32_t a1,
                                         uint32_t a2, uint32_t a3,
                                         uint32_t b0, uint32_t b1) {
  asm volatile("mma.sync.aligned.m16n8k16.row.col.f32.f16.f16.f32 "
               "{%0,%1,%2,%3}, {%4,%5,%6,%7}, {%8,%9}, {%0,%1,%2,%3};"
               : "+f"(d[0]), "+f"(d[1]), "+f"(d[2]), "+f"(d[3])
               : "r"(a0), "r"(a1), "r"(a2), "r"(a3), "r"(b0), "r"(b1));
}

// ---------------- scratch ----------------------------------------------------
__device__ __half g_A1h[(size_t)BATCH*KPAD1];     // features plain fp16
__device__ __half g_B1h[(size_t)H1*KPAD1];        // W1^T fp16
__device__ __half g_B2h[(size_t)H2*H1];           // W2^T fp16
__device__ __half g_Wch[(size_t)NLPAD*JO];        // Wc^T fp16 (zero-padded rows)
__device__ float  g_Cpart[(size_t)LSPLIT*BATCH*NLPAD > (size_t)2*BATCH*H1
                          ? (size_t)LSPLIT*BATCH*NLPAD : (size_t)2*BATCH*H1];
__device__ __half g_X1p[(size_t)BATCH*2*H1];      // X1 K-packed split fp16
__device__ float  g_X2[(size_t)BATCH*H2];
__device__ float  g_P [(size_t)BATCH*H2];
__device__ __half g_preds[(size_t)BATCH*PREDROW];
__device__ __half g_Vp[(size_t)BATCH*2*JO];       // V K-packed split fp16

// ---------------- conversions ------------------------------------------------
// features -> plain fp16, K padded to KPAD1
__global__ __launch_bounds__(256)
void convA_plain_kernel(const float* __restrict__ F, __half* __restrict__ Ah)
{
  int total = BATCH*(KPAD1/8);
  for (int i = blockIdx.x*blockDim.x + threadIdx.x; i < total;
       i += gridDim.x*blockDim.x) {
    int row = i / (KPAD1/8), o = i % (KPAD1/8);
    uint32_t u[4];
    if (o*8 < IN_DIM){
      const float* src = F + (size_t)row*IN_DIM + o*8;
#pragma unroll
      for (int k=0;k<8;k+=2){
        __half h0 = __float2half(src[k]), h1 = __float2half(src[k+1]);
        u[k>>1] = (uint32_t)__half_as_ushort(h0) | ((uint32_t)__half_as_ushort(h1)<<16);
      }
    } else {
#pragma unroll
      for (int k=0;k<4;k++) u[k]=0;
    }
    *(uint4*)(Ah + (size_t)row*KPAD1 + o*8) = *(uint4*)u;
  }
}

__global__ __launch_bounds__(256)
void convW_f16_kernel(const float* __restrict__ W, __half* __restrict__ B,
                      int K, int N, int KP)
{
  __shared__ float tile[32][33];
  int kb = blockIdx.x*32, nb = blockIdx.y*32;
  int tx = threadIdx.x, ty = threadIdx.y;   // block (32,8)
#pragma unroll
  for (int i=0;i<32;i+=8){
    int k = kb+ty+i, col = nb+tx;
    tile[ty+i][tx] = (k < K && col < N) ? W[(size_t)k*N + col] : 0.f;
  }
  __syncthreads();
#pragma unroll
  for (int i=0;i<32;i+=8){
    int n = nb+ty+i, k = kb+tx;
    B[(size_t)n*KP + k] = __float2half(tile[tx][ty+i]);
  }
}

// ---------------- GEMM1: plain fp16 A, 4-stage pipeline ----------------------
// C_partial[kz][M][N] = A[M,K] @ B[K,N], both plain fp16, fp32 out.
#define P_ATILE (128*64)                  // 8192 B
#define P_BTILE (128*64)
#define P_STAGEB (P_ATILE + P_BTILE)      // 16384
#define P_SMEM (4*P_STAGEB)               // 65536

__global__ __launch_bounds__(256, 2)
void gemm1_plain_kernel(const __half* __restrict__ Ah,
                        const __half* __restrict__ Bh,
                        float* __restrict__ outF,
                        int Klog, int KT, int Ntot, int Mtot)
{
  extern __shared__ __align__(128) unsigned char smraw[];
  const uint32_t sb = smem_u32(smraw);
  const int t = threadIdx.x;
  const int m0 = blockIdx.y * 128;
  const int n0 = blockIdx.x * 128;
  const int kz = blockIdx.z;
  const int c0 = kz * KT;

  auto load_stage = [&](int s, int c){
    const uint32_t stb = sb + s*P_STAGEB;
    const int cc = c0 + c;
#pragma unroll
    for (int it = 0; it < 4; it++){
      int idx = t + it*256;
      if (idx < 512){
        int r = idx>>2, u = idx&3;
        uint32_t dst = stb + r*64 + ((u ^ ((r>>1)&3))<<4);
        cp_async16(dst, Ah + (size_t)(m0+r)*Klog + cc*32 + u*8);
      } else {
        int j = idx - 512;
        int r = j>>2, u = j&3;
        uint32_t dst = stb + P_ATILE + r*64 + ((u ^ ((r>>1)&3))<<4);
        cp_async16(dst, Bh + (size_t)(n0+r)*Klog + cc*32 + u*8);
      }
    }
  };

  const int wid = t>>5, lane = t&31;
  const int wm = wid & 1, wn = wid >> 1;
  int ra[4];
#pragma unroll
  for (int i=0;i<4;i++) ra[i] = wm*64 + i*16 + (lane&7) + ((lane>>3)&1)*8;
  const int ua = lane>>4;
  int rb[2];
#pragma unroll
  for (int h=0;h<2;h++) rb[h] = wn*32 + h*16 + (lane&7) + ((lane>>3)&1)*8;
  const int ub = lane>>4;

  float acc[4][4][4];
#pragma unroll
  for (int i=0;i<4;i++)
#pragma unroll
    for (int j=0;j<4;j++)
#pragma unroll
      for (int q=0;q<4;q++) acc[i][j][q]=0.f;

  load_stage(0, 0);              CP_COMMIT();
  if (KT > 1) load_stage(1, 1);  CP_COMMIT();
  if (KT > 2) load_stage(2, 2);  CP_COMMIT();

  for (int kt = 0; kt < KT; kt++){
    CP_WAIT(2);
    __syncthreads();
    if (kt + 3 < KT) load_stage((kt + 3) & 3, kt + 3);
    CP_COMMIT();

    const uint32_t stA = sb + (kt & 3)*P_STAGEB;
    const uint32_t stB = stA + P_ATILE;
#pragma unroll
    for (int p = 0; p < 2; p++){   // 16 logical k per step
      uint32_t Br[2][4];
#pragma unroll
      for (int h=0;h<2;h++){
        int u = 2*p + ub;
        ldm_x4(Br[h], stB + rb[h]*64 + ((u ^ ((rb[h]>>1)&3))<<4));
      }
      uint32_t Ar[4][4];
#pragma unroll
      for (int i=0;i<4;i++){
        int u = 2*p + ua;
        ldm_x4(Ar[i], stA + ra[i]*64 + ((u ^ ((ra[i]>>1)&3))<<4));
      }
#pragma unroll
      for (int i=0;i<4;i++)
#pragma unroll
        for (int j=0;j<4;j++)
          mma_fp16(acc[i][j], Ar[i][0], Ar[i][1], Ar[i][2], Ar[i][3],
                   Br[j>>1][(j&1)], Br[j>>1][(j&1)+2]);
    }
  }

  const int g = lane >> 2, tq = lane & 3;
#pragma unroll
  for (int i=0;i<4;i++){
#pragma unroll
    for (int j=0;j<4;j++){
      int row = m0 + wm*64 + i*16 + g;
      int col = n0 + wn*32 + j*8 + tq*2;
      float* dst = outF + ((size_t)kz*Mtot + row)*Ntot + col;
      *(float2*)dst                    = make_float2(acc[i][j][0], acc[i][j][1]);
      *(float2*)(dst + (size_t)8*Ntot) = make_float2(acc[i][j][2], acc[i][j][3]);
    }
  }
}

// ---------------- fp16 K-packed-split GEMM (GEMM2, logits) -------------------
#define F_BM 128
#define F_BN 128
#define F_BK 32
#define F_ATILE (128*128)
#define F_BTILE (128*64)
#define F_STAGEB (F_ATILE + F_BTILE)      // 24576
#define F_SMEM (4*F_STAGEB)               // 98304

template<int MODE>   // 0: fp32 partial (k-split), 1: bias+relu fp32
__global__ __launch_bounds__(256, 2)
void fp16_gemm_kernel(const __half* __restrict__ Ap,
                      const __half* __restrict__ Bh,
                      const float* __restrict__ bias,
                      float* __restrict__ outF,
                      int Klog, int KT, int Ntot, int Mtot)
{
  extern __shared__ __align__(128) unsigned char smraw[];
  const uint32_t sb = smem_u32(smraw);
  const int t = threadIdx.x;
  const int m0 = blockIdx.y * F_BM;
  const int n0 = blockIdx.x * F_BN;
  const int kz = blockIdx.z;
  const int c0 = kz * KT;
  const int strideA = 2*Klog;

  auto load_stage = [&](int s, int c){
    const uint32_t stb = sb + s*F_STAGEB;
    const int cc = c0 + c;
#pragma unroll
    for (int it = 0; it < 6; it++){
      int idx = t + it*256;
      if (idx < 1024){
        int r = idx>>3, u = idx&7;
        uint32_t dst = stb + r*128 + ((u ^ (r&7))<<4);
        cp_async16(dst, Ap + (size_t)(m0+r)*strideA + cc*64 + u*8);
      } else {
        int j = idx - 1024;
        int r = j>>2, u = j&3;
        uint32_t dst = stb + F_ATILE + r*64 + ((u ^ ((r>>1)&3))<<4);
        cp_async16(dst, Bh + (size_t)(n0+r)*Klog + cc*32 + u*8);
      }
    }
  };

  const int wid = t>>5, lane = t&31;
  const int wm = wid & 1, wn = wid >> 1;
  int ra[4];
#pragma unroll
  for (int i=0;i<4;i++) ra[i] = wm*64 + i*16 + (lane&7) + ((lane>>3)&1)*8;
  const int ua = lane>>4;
  int rb[2];
#pragma unroll
  for (int h=0;h<2;h++) rb[h] = wn*32 + h*16 + (lane&7) + ((lane>>3)&1)*8;
  const int ub = lane>>4;

  float acc[4][4][4];
#pragma unroll
  for (int i=0;i<4;i++)
#pragma unroll
    for (int j=0;j<4;j++)
#pragma unroll
      for (int q=0;q<4;q++) acc[i][j][q]=0.f;

  load_stage(0, 0);              CP_COMMIT();
  if (KT > 1) load_stage(1, 1);  CP_COMMIT();
  if (KT > 2) load_stage(2, 2);  CP_COMMIT();

  for (int kt = 0; kt < KT; kt++){
    CP_WAIT(2);
    __syncthreads();
    if (kt + 3 < KT) load_stage((kt + 3) & 3, kt + 3);
    CP_COMMIT();

    const uint32_t stA = sb + (kt & 3)*F_STAGEB;
    const uint32_t stB = stA + F_ATILE;
#pragma unroll
    for (int p = 0; p < 2; p++){
      uint32_t Br[2][4];
#pragma unroll
      for (int h=0;h<2;h++){
        int u = 2*p + ub;
        ldm_x4(Br[h], stB + rb[h]*64 + ((u ^ ((rb[h]>>1)&3))<<4));
      }
#pragma unroll
      for (int e = 0; e < 2; e++){
        int kk = 2*p + e;
        uint32_t Ar[4][4];
#pragma unroll
        for (int i=0;i<4;i++){
          int u = 2*kk + ua;
          ldm_x4(Ar[i], stA + ra[i]*128 + ((u ^ (ra[i]&7))<<4));
        }
#pragma unroll
        for (int i=0;i<4;i++)
#pragma unroll
          for (int j=0;j<4;j++){
            uint32_t b = Br[j>>1][(j&1) + 2*e];
            mma_fp16(acc[i][j], Ar[i][0], Ar[i][1], Ar[i][2], Ar[i][3], b, b);
          }
      }
    }
  }

  const int g = lane >> 2, tq = lane & 3;
#pragma unroll
  for (int i=0;i<4;i++){
#pragma unroll
    for (int j=0;j<4;j++){
      int row = m0 + wm*64 + i*16 + g;
      int col = n0 + wn*32 + j*8 + tq*2;
      if (MODE == 0){
        float* dst = outF + ((size_t)kz*Mtot + row)*Ntot + col;
        *(float2*)dst           = make_float2(acc[i][j][0], acc[i][j][1]);
        *(float2*)(dst + (size_t)8*Ntot) = make_float2(acc[i][j][2], acc[i][j][3]);
      } else if (MODE == 1){
        float b0 = bias[col], b1 = bias[col+1];
        float* dst = outF + (size_t)row*Ntot + col;
        *(float2*)dst           = make_float2(fmaxf(acc[i][j][0]+b0,0.f), fmaxf(acc[i][j][1]+b1,0.f));
        *(float2*)(dst + (size_t)8*Ntot) = make_float2(fmaxf(acc[i][j][2]+b0,0.f), fmaxf(acc[i][j][3]+b1,0.f));
      }
    }
  }
}

// ---------------- reduce partials + bias + relu -> X1 packed fp16 -----------
__global__ __launch_bounds__(256)
void reduce_relu_kernel(const float* __restrict__ C, const float* __restrict__ b1,
                        __half* __restrict__ X1p)
{
  int total = BATCH*(H1/8);
  for (int i = blockIdx.x*blockDim.x + threadIdx.x; i < total;
       i += gridDim.x*blockDim.x) {
    int b = i / (H1/8), o = i % (H1/8);
    const float* c0 = C + (size_t)b*H1 + o*8;
    const float* c1 = c0 + (size_t)BATCH*H1;
    const float* bb = b1 + o*8;
    uint32_t u[8];
#pragma unroll
    for (int k=0;k<8;k+=2){
      float v0 = fmaxf(c0[k]   + c1[k]   + bb[k],   0.f);
      float v1 = fmaxf(c0[k+1] + c1[k+1] + bb[k+1], 0.f);
      __half h0 = __float2half(v0), h1 = __float2half(v1);
      u[k>>1]     = (uint32_t)__half_as_ushort(h0) | ((uint32_t)__half_as_ushort(h1)<<16);
      __half l0 = __float2half(v0 - __half2float(h0));
      __half l1 = __float2half(v1 - __half2float(h1));
      u[4+(k>>1)] = (uint32_t)__half_as_ushort(l0) | ((uint32_t)__half_as_ushort(l1)<<16);
    }
    __half* dst = X1p + (size_t)b*(2*H1) + o*16;
    *(uint4*)dst       = *(uint4*)u;
    *(uint4*)(dst + 8) = *(uint4*)(u+4);
  }
}

// ---------------- reduce logits partials + bias -> out -----------------------
__global__ __launch_bounds__(256)
void reduce_logits_kernel(const float* __restrict__ part, const float* __restrict__ bc,
                          float* __restrict__ out)
{
  int i = blockIdx.x*blockDim.x + threadIdx.x;
  if (i < BATCH*NL){
    int b = i/NL, j = i%NL;
    float s = bc[j];
#pragma unroll
    for (int z=0; z<LSPLIT; z++) s += part[((size_t)z*BATCH + b)*NLPAD + j];
    out[i] = s;
  }
}

// ---------------- primary capsules + per-capsule LayerNorm -------------------
__global__ __launch_bounds__(256)
void primary_kernel(const float* __restrict__ X2, const float* __restrict__ Wp,
                    const float* __restrict__ bp, const float* __restrict__ lng,
                    const float* __restrict__ lnb, float* __restrict__ P)
{
  __shared__ __align__(16) float xs[16][H2];
  const int t  = threadIdx.x;
  const int b0 = blockIdx.x * 16;
  for (int idx=t; idx<16*(H2/4); idx+=256){
    int bb = idx/(H2/4);
    int c4 = (idx%(H2/4))*4;
    *(float4*)&xs[bb][c4] = *(const float4*)(X2 + (size_t)(b0+bb)*H2 + c4);
  }
  __syncthreads();
  const int n = t>>3, o = t&7;
  float bias = bp[t];
  float acc[16];
#pragma unroll
  for (int bb=0;bb<16;bb++) acc[bb]=bias;
  const float* wp = Wp + (size_t)n*(H2*PD) + o;
  for (int i0=0;i0<H2;i0+=4){
    float w0 = __ldg(wp + (size_t)(i0+0)*PD);
    float w1 = __ldg(wp + (size_t)(i0+1)*PD);
    float w2 = __ldg(wp + (size_t)(i0+2)*PD);
    float w3 = __ldg(wp + (size_t)(i0+3)*PD);
#pragma unroll
    for (int bb=0;bb<16;bb++){
      float4 x = *(const float4*)&xs[bb][i0];
      acc[bb] += x.x*w0 + x.y*w1 + x.z*w2 + x.w*w3;
    }
  }
  float g = lng[t], be = lnb[t];
#pragma unroll
  for (int bb=0;bb<16;bb++){
    float x = acc[bb];
    float s = x;
    s += __shfl_xor_sync(0xffffffffu, s, 1);
    s += __shfl_xor_sync(0xffffffffu, s, 2);
    s += __shfl_xor_sync(0xffffffffu, s, 4);
    float mu = s * 0.125f;
    float d  = x - mu;
    float q  = d*d;
    q += __shfl_xor_sync(0xffffffffu, q, 1);
    q += __shfl_xor_sync(0xffffffffu, q, 2);
    q += __shfl_xor_sync(0xffffffffu, q, 4);
    float var = q * 0.125f;
    P[(size_t)(b0+bb)*H2 + t] = d * rsqrtf(var + 1e-5f) * g + be;
  }
}

// ---------------- preds via fp16 mma; jo-permuted weights -> uint2 stores ----
#define PREDS_SMEM (JO*PD*2 + 128*16*2)   // 29696

__global__ __launch_bounds__(256)
void preds_mma_kernel(const float* __restrict__ P, const float* __restrict__ Wr,
                      __half* __restrict__ preds, int b_base)
{
  extern __shared__ __align__(16) unsigned char smraw[];
  __half* wsh  = (__half*)smraw;                         // [JO][8], permuted rows
  __half* ash  = wsh + JO*PD;                            // [128][16]
  const int n  = blockIdx.y;
  const int b0 = b_base + blockIdx.x * 128;
  const int t  = threadIdx.x;
  const int wid = t>>5, lane = t&31;

  const float* wsrc = Wr + (size_t)n*(JO*PD);
  for (int i=t; i<JO*PD; i+=256){
    int d = i>>3, k = i&7;
    int jtp = d>>4, r = d&15;
    int a = r>>3, nn = r&7;
    int jo = jtp*16 + ((nn>>1)<<2) + (a<<1) + (nn&1);
    wsh[i] = __float2half(wsrc[jo*8 + k]);
  }
  for (int idx=t; idx<128*8; idx+=256){
    int r = idx>>3, i = idx&7;
    float v = P[(size_t)(b0+r)*H2 + n*8 + i];
    __half h = __float2half(v);
    ash[r*16 + i]     = h;
    ash[r*16 + 8 + i] = __float2half(v - __half2float(h));
  }
  __syncthreads();

  const int g = lane>>2, tq = lane&3;
  const int ar0 = wid*16 + g;
  uint32_t a0 = *(const uint32_t*)&ash[ar0*16 + tq*2];
  uint32_t a1 = *(const uint32_t*)&ash[(ar0+8)*16 + tq*2];
  uint32_t a2 = *(const uint32_t*)&ash[ar0*16 + 8 + tq*2];
  uint32_t a3 = *(const uint32_t*)&ash[(ar0+8)*16 + 8 + tq*2];

  __half* out0 = preds + (size_t)(b0 + wid*16 + g)*PREDROW + (size_t)n*JO + tq*4;
  __half* out1 = out0 + (size_t)8*PREDROW;

#pragma unroll 2
  for (int jtp = 0; jtp < JO/16; jtp++){
    uint32_t bv0 = *(const uint32_t*)&wsh[(jtp*16 + g)*8 + tq*2];
    uint32_t bv1 = *(const uint32_t*)&wsh[(jtp*16 + 8 + g)*8 + tq*2];
    float c[4] = {0.f,0.f,0.f,0.f};
    float d2[4] = {0.f,0.f,0.f,0.f};
    mma_fp16(c,  a0, a1, a2, a3, bv0, bv0);
    mma_fp16(d2, a0, a1, a2, a3, bv1, bv1);
    __half2 p0 = __floats2half2_rn(c[0],  c[1]);
    __half2 p1 = __floats2half2_rn(d2[0], d2[1]);
    __half2 p2 = __floats2half2_rn(c[2],  c[3]);
    __half2 p3 = __floats2half2_rn(d2[2], d2[3]);
    *(uint2*)(out0 + jtp*16) = make_uint2(*(uint32_t*)&p0, *(uint32_t*)&p1);
    *(uint2*)(out1 + jtp*16) = make_uint2(*(uint32_t*)&p2, *(uint32_t*)&p3);
  }
}

// ---------------- dynamic routing: L1-resident preds reloads, 2 CTAs/SM -----
#define RT_T 800

__global__ __launch_bounds__(RT_T, 2)
void routing_kernel(const __half* __restrict__ preds, __half* __restrict__ Vp,
                    int b_base)
{
  __shared__ float bl[NP*NL];
  __shared__ float cs[NP*NL];
  __shared__ float pmax[NP*4];
  __shared__ float psum[NP*4];
  const int b = b_base + blockIdx.x;
  const int t = threadIdx.x;
  const int j = t >> 3;
  const int g8 = t & 7;
  const __half2* src = (const __half2*)(preds + (size_t)b*PREDROW) + t;

  float2 v;
  {
    float ax=0.f, ay=0.f;
#pragma unroll
    for (int n=0;n<NP;n++){
      float2 f = __half22float2(__ldg(src + n*(JO/2)));
      ax += f.x; ay += f.y;
    }
    v.x = ax*(1.0f/NL); v.y = ay*(1.0f/NL);
  }

  for (int iter=0; ; iter++){
    float sq = v.x*v.x + v.y*v.y;
    sq += __shfl_xor_sync(0xffffffffu, sq, 1);
    sq += __shfl_xor_sync(0xffffffffu, sq, 2);
    sq += __shfl_xor_sync(0xffffffffu, sq, 4);
    float scale = sq/(1.f+sq)*rsqrtf(sq+1e-8f);
    v.x *= scale; v.y *= scale;
    if (iter == 2) break;

#pragma unroll
    for (int n=0;n<NP;n++){
      float2 f = __half22float2(__ldg(src + n*(JO/2)));
      float a = f.x*v.x + f.y*v.y;
      a += __shfl_xor_sync(0xffffffffu, a, 1);
      a += __shfl_xor_sync(0xffffffffu, a, 2);
      a += __shfl_xor_sync(0xffffffffu, a, 4);
      if ((n & 7) == g8){
        if (iter == 0) bl[n*NL + j] = a;
        else           bl[n*NL + j] += a;
      }
    }
    __syncthreads();

    if (t < NP*4){
      int n = t>>2, q = t&3;
      float m = -1e30f;
      for (int jj=q*25; jj<q*25+25; jj++) m = fmaxf(m, bl[n*NL+jj]);
      pmax[t] = m;
    }
    __syncthreads();
    if (t < NP*4){
      int n = t>>2, q = t&3;
      float m = fmaxf(fmaxf(pmax[n*4],pmax[n*4+1]),fmaxf(pmax[n*4+2],pmax[n*4+3]));
      float s = 0.f;
      for (int jj=q*25; jj<q*25+25; jj++) s += __expf(bl[n*NL+jj]-m);
      psum[t] = s;
    }
    __syncthreads();
    for (int nj=t; nj<NP*NL; nj+=RT_T){
      int n = nj/NL;
      float m = fmaxf(fmaxf(pmax[n*4],pmax[n*4+1]),fmaxf(pmax[n*4+2],pmax[n*4+3]));
      float ssum = psum[n*4]+psum[n*4+1]+psum[n*4+2]+psum[n*4+3];
      cs[nj] = __expf(bl[nj]-m)/ssum;
    }
    __syncthreads();

    float ax=0.f, ay=0.f;
#pragma unroll
    for (int n=0;n<NP;n++){
      float c = cs[n*NL + j];
      float2 f = __half22float2(__ldg(src + n*(JO/2)));
      ax += c*f.x; ay += c*f.y;
    }
    v.x = ax; v.y = ay;
    __syncthreads();
  }

  __half h0 = __float2half(v.x), h1 = __float2half(v.y);
  __half l0 = __float2half(v.x - __half2float(h0));
  __half l1 = __float2half(v.y - __half2float(h1));
  __half* dst = Vp + (size_t)b*(2*JO) + (t>>2)*16 + ((2*t)&7);
  *(__half2*)dst     = __halves2half2(h0, h1);
  *(__half2*)(dst+8) = __halves2half2(l0, l1);
}

// ---------------- launch -----------------------------------------------------
extern "C" void kernel_launch(void* const* d_in, const int* in_sizes, int n_in,
                              void* d_out, int out_size)
{
  (void)in_sizes; (void)n_in; (void)out_size;
  const float* features = (const float*)d_in[0];
  const float* W1  = (const float*)d_in[1];
  const float* b1  = (const float*)d_in[2];
  const float* W2  = (const float*)d_in[3];
  const float* b2  = (const float*)d_in[4];
  const float* Wp  = (const float*)d_in[5];
  const float* bp  = (const float*)d_in[6];
  const float* lng = (const float*)d_in[7];
  const float* lnb = (const float*)d_in[8];
  const float* Wr  = (const float*)d_in[9];
  const float* Wc  = (const float*)d_in[10];
  const float* bc  = (const float*)d_in[11];
  float* out = (float*)d_out;

  __half *A1h,*B1h,*B2h,*Wch,*X1p,*PR,*Vp;
  float *Cp,*X2,*P;
  cudaGetSymbolAddress((void**)&A1h, g_A1h);
  cudaGetSymbolAddress((void**)&B1h, g_B1h);
  cudaGetSymbolAddress((void**)&B2h, g_B2h);
  cudaGetSymbolAddress((void**)&Wch, g_Wch);
  cudaGetSymbolAddress((void**)&Cp,  g_Cpart);
  cudaGetSymbolAddress((void**)&X1p, g_X1p);
  cudaGetSymbolAddress((void**)&X2,  g_X2);
  cudaGetSymbolAddress((void**)&P,   g_P);
  cudaGetSymbolAddress((void**)&PR,  g_preds);
  cudaGetSymbolAddress((void**)&Vp,  g_Vp);

  // launches ordered so gemm1 is the 4th (profiled) launch
  convA_plain_kernel<<<4096, 256>>>(features, A1h);                                 // 1
  convW_f16_kernel<<<dim3(KPAD1/32, H1/32), dim3(32,8)>>>(W1, B1h, IN_DIM, H1, KPAD1); // 2
  convW_f16_kernel<<<dim3(H1/32, H2/32),    dim3(32,8)>>>(W2, B2h, H1, H2, H1);     // 3

  cudaFuncSetAttribute(gemm1_plain_kernel, cudaFuncAttributeMaxDynamicSharedMemorySize, P_SMEM);
  gemm1_plain_kernel<<<dim3(H1/128, BATCH/128, 2), 256, P_SMEM>>>(                  // 4
      A1h, B1h, Cp, KPAD1, (KPAD1/F_BK)/2, H1, BATCH);

  convW_f16_kernel<<<dim3(JO/32, NLPAD/32), dim3(32,8)>>>(Wc, Wch, JO, NL, JO);     // 5
  reduce_relu_kernel<<<1024, 256>>>(Cp, b1, X1p);                                   // 6

  cudaFuncSetAttribute(fp16_gemm_kernel<1>, cudaFuncAttributeMaxDynamicSharedMemorySize, F_SMEM);
  fp16_gemm_kernel<1><<<dim3(H2/F_BN, BATCH/F_BM, 1), 256, F_SMEM>>>(               // 7
      X1p, B2h, b2, X2, H1, H1/F_BK, H2, BATCH);

  primary_kernel<<<BATCH/16, 256>>>(X2, Wp, bp, lng, lnb, P);                       // 8

  // preds+routing interleaved per 1024-row chunk for L2 reuse of the preds slab
  cudaFuncSetAttribute(preds_mma_kernel, cudaFuncAttributeMaxDynamicSharedMemorySize, PREDS_SMEM);
  for (int base = 0; base < BATCH; base += BCHUNK){
    preds_mma_kernel<<<dim3(BCHUNK/128, NP), 256, PREDS_SMEM>>>(P, Wr, PR, base);
    routing_kernel<<<BCHUNK, RT_T>>>(PR, Vp, base);
  }

  // logits partials (k-split 5) + reduce
  cudaFuncSetAttribute(fp16_gemm_kernel<0>, cudaFuncAttributeMaxDynamicSharedMemorySize, F_SMEM);
  fp16_gemm_kernel<0><<<dim3(1, BATCH/F_BM, LSPLIT), 256, F_SMEM>>>(
      Vp, Wch, nullptr, Cp, JO, (JO/F_BK)/LSPLIT, NLPAD, BATCH);
  reduce_logits_kernel<<<(BATCH*NL+255)/256, 256>>>(Cp, bc, out);
}